// round 2
// baseline (speedup 1.0000x reference)
#include <cuda_runtime.h>
#include <cstdint>
#include <cstddef>

// ---------------- problem constants ----------------
#define BB 16
#define N0 4096

// scratch (device globals; allocation-free per harness rules)
__device__ float  g_bufA[33554432];           // 128 MB  (max: 131072x256)
__device__ float  g_bufB[16777216];           // 64 MB   (max: 131072x128)
__device__ float  g_newxyz[BB * 256 * 3];
__device__ int    g_fidx[BB * 256];
__device__ int    g_gi[131072];
__device__ float  g_l1pt[BB * 256 * 128];     // l1 points, (b,s,c) layout, post-BN
__device__ float  g_l2pt[BB * 128 * 256];     // l2 points, (b,s,c) layout, post-BN
__device__ double g_sum[512];
__device__ double g_sumsq[512];
__device__ float  g_scale[512];
__device__ float  g_shift[512];

// ---------------- FPS: one block per batch ----------------
__global__ void fps_kernel(const float* __restrict__ xyz, int n, int npoint,
                           int* __restrict__ fidx, float* __restrict__ newxyz,
                           float* __restrict__ outxyz) {
    extern __shared__ float sm[];
    float* sx = sm;
    float* sy = sm + n;
    float* sz = sm + 2 * n;
    float* dist = sm + 3 * n;
    __shared__ float rv[16];
    __shared__ int   ri[16];
    __shared__ int   sfar;

    int b = blockIdx.x, tid = threadIdx.x, bt = blockDim.x;
    const float* base = xyz + (size_t)b * 3 * n;
    for (int i = tid; i < n; i += bt) {
        sx[i] = base[i];
        sy[i] = base[n + i];
        sz[i] = base[2 * n + i];
        dist[i] = 1e10f;
    }
    __syncthreads();

    int far = 0;
    for (int t = 0; t < npoint; t++) {
        float cx = sx[far], cy = sy[far], cz = sz[far];
        if (tid == 0) {
            fidx[b * npoint + t] = far;
            float* nw = &newxyz[(b * npoint + t) * 3];
            nw[0] = cx; nw[1] = cy; nw[2] = cz;
            outxyz[(size_t)b * 3 * npoint + t] = cx;
            outxyz[(size_t)b * 3 * npoint + npoint + t] = cy;
            outxyz[(size_t)b * 3 * npoint + 2 * npoint + t] = cz;
        }
        float bv = -1.0f;
        int bi = 0x7fffffff;
        for (int i = tid; i < n; i += bt) {
            float dx = __fsub_rn(sx[i], cx);
            float dy = __fsub_rn(sy[i], cy);
            float dz = __fsub_rn(sz[i], cz);
            float d = __fadd_rn(__fadd_rn(__fmul_rn(dx, dx), __fmul_rn(dy, dy)), __fmul_rn(dz, dz));
            float dd = fminf(dist[i], d);
            dist[i] = dd;
            if (dd > bv) { bv = dd; bi = i; }
        }
#pragma unroll
        for (int o = 16; o; o >>= 1) {
            float ov = __shfl_down_sync(0xffffffffu, bv, o);
            int   oi = __shfl_down_sync(0xffffffffu, bi, o);
            if (ov > bv || (ov == bv && oi < bi)) { bv = ov; bi = oi; }
        }
        if ((tid & 31) == 0) { rv[tid >> 5] = bv; ri[tid >> 5] = bi; }
        __syncthreads();
        if (tid < 32) {
            int nw = bt >> 5;
            float v = (tid < nw) ? rv[tid] : -2.0f;
            int  ii = (tid < nw) ? ri[tid] : 0x7fffffff;
#pragma unroll
            for (int o = 16; o; o >>= 1) {
                float ov = __shfl_down_sync(0xffffffffu, v, o);
                int   oi = __shfl_down_sync(0xffffffffu, ii, o);
                if (ov > v || (ov == v && oi < ii)) { v = ov; ii = oi; }
            }
            if (tid == 0) sfar = ii;
        }
        __syncthreads();
        far = sfar;
        __syncthreads();
    }
}

// ---------------- ball query: one warp per (b,s) ----------------
__global__ void ballquery_kernel(const float* __restrict__ xyz, const float* __restrict__ newxyz,
                                 int n, int S, int K, float r2, int* __restrict__ gi) {
    int gw = (blockIdx.x * blockDim.x + threadIdx.x) >> 5;
    int lane = threadIdx.x & 31;
    if (gw >= BB * S) return;
    int b = gw / S, s = gw % S;
    const float* nw = &newxyz[(b * S + s) * 3];
    float nx = nw[0], ny = nw[1], nz = nw[2];
    float nsq = __fadd_rn(__fadd_rn(__fmul_rn(nx, nx), __fmul_rn(ny, ny)), __fmul_rn(nz, nz));
    const float* px = xyz + (size_t)b * 3 * n;
    int* g = gi + (size_t)(b * S + s) * K;
    int cnt = 0, first = -1;
    for (int base = 0; base < n && cnt < K; base += 32) {
        int i = base + lane;
        float x = px[i], y = px[n + i], z = px[2 * n + i];
        float psq = __fadd_rn(__fadd_rn(__fmul_rn(x, x), __fmul_rn(y, y)), __fmul_rn(z, z));
        float dot = __fadd_rn(__fadd_rn(__fmul_rn(nx, x), __fmul_rn(ny, y)), __fmul_rn(nz, z));
        float sqr = __fsub_rn(__fadd_rn(nsq, psq), __fmul_rn(2.0f, dot));
        bool ok = !(sqr > r2);
        unsigned m = __ballot_sync(0xffffffffu, ok);
        if (first < 0 && m) first = base + __ffs(m) - 1;
        int pos = cnt + __popc(m & ((1u << lane) - 1u));
        if (ok && pos < K) g[pos] = i;
        cnt += __popc(m);
    }
    if (cnt > K) cnt = K;
    for (int p = cnt + lane; p < K; p += 32) g[p] = first;
}

// ---------------- gathers ----------------
__global__ void gather_sa1(const float* __restrict__ xyz, const float* __restrict__ pts,
                           const int* __restrict__ gi, const float* __restrict__ newxyz,
                           float* __restrict__ out) {
    int row = blockIdx.x * blockDim.x + threadIdx.x;
    if (row >= BB * 256 * 32) return;
    int s = (row >> 5) & 255, b = row >> 13;
    int idx = gi[row];
    const float* nw = &newxyz[(b * 256 + s) * 3];
    const float* px = xyz + (size_t)b * 3 * N0;
    const float* pp = pts + (size_t)b * 3 * N0;
    float* o = out + (size_t)row * 6;
    o[0] = __fsub_rn(px[idx], nw[0]);
    o[1] = __fsub_rn(px[N0 + idx], nw[1]);
    o[2] = __fsub_rn(px[2 * N0 + idx], nw[2]);
    o[3] = pp[idx];
    o[4] = pp[N0 + idx];
    o[5] = pp[2 * N0 + idx];
}

__global__ void gather_sa2(const float* __restrict__ l1xyz, const float* __restrict__ l1pt,
                           const int* __restrict__ gi, const float* __restrict__ newxyz,
                           float* __restrict__ out) {
    const int S = 128, K = 64, C = 131;
    int gw = (blockIdx.x * blockDim.x + threadIdx.x) >> 5;
    int lane = threadIdx.x & 31;
    if (gw >= BB * S * K) return;
    int s = (gw / K) % S, b = gw / (S * K);
    int idx = gi[gw];
    float* o = out + (size_t)gw * C;
    for (int c = lane; c < C; c += 32) {
        float v;
        if (c < 3)
            v = __fsub_rn(l1xyz[(size_t)b * 768 + c * 256 + idx], newxyz[(b * S + s) * 3 + c]);
        else
            v = l1pt[((size_t)b * 256 + idx) * 128 + (c - 3)];
        o[c] = v;
    }
}

__global__ void gather_sa3(const float* __restrict__ l2xyz, const float* __restrict__ l2pt,
                           float* __restrict__ out) {
    int gw = (blockIdx.x * blockDim.x + threadIdx.x) >> 5;
    int lane = threadIdx.x & 31;
    if (gw >= BB * 128) return;
    int k = gw % 128, b = gw / 128;
    float* o = out + (size_t)gw * 259;
    for (int c = lane; c < 259; c += 32) {
        float v = (c < 3) ? l2xyz[(size_t)b * 384 + c * 128 + k]
                          : l2pt[((size_t)b * 128 + k) * 256 + (c - 3)];
        o[c] = v;
    }
}

// ---------------- fused GEMM: out = A*W + bias, optional input BN+relu,
//                  per-channel stats accumulated into g_sum/g_sumsq ----------------
template <int CIN, int COUT, int BM, int TN, int KC, bool IN_BN>
__global__ void __launch_bounds__(256)
gemm_k(const float* __restrict__ A, const float* __restrict__ W,
       const float* __restrict__ bias, float* __restrict__ out) {
    constexpr int COLT = COUT / TN;
    constexpr int ROWT = 256 / COLT;
    constexpr int TM = BM / ROWT;
    constexpr int LDA = KC + 1;
    extern __shared__ float sm[];
    float* As = sm;                    // BM x LDA
    float* Ws = sm + BM * LDA;         // KC x COUT
    float* ss = Ws + KC * COUT;        // COUT
    float* sq = ss + COUT;             // COUT

    int tid = threadIdx.x;
    int ct = tid % COLT, rt = tid / COLT;
    size_t row0 = (size_t)blockIdx.x * BM;

    float acc[TM][TN];
#pragma unroll
    for (int i = 0; i < TM; i++)
#pragma unroll
        for (int j = 0; j < TN; j++) acc[i][j] = 0.f;

    for (int k0 = 0; k0 < CIN; k0 += KC) {
        int kc = (CIN - k0 < KC) ? (CIN - k0) : KC;
        __syncthreads();
        for (int e = tid; e < BM * kc; e += 256) {
            int r = e / kc, k = e - r * kc;
            float v = A[(row0 + r) * CIN + k0 + k];
            if (IN_BN) {
                int c = k0 + k;
                v = fmaxf(v * g_scale[c] + g_shift[c], 0.f);
            }
            As[r * LDA + k] = v;
        }
        for (int e = tid; e < kc * COUT; e += 256)
            Ws[e] = W[(size_t)k0 * COUT + e];
        __syncthreads();
        for (int kk = 0; kk < kc; kk++) {
            float a[TM], w[TN];
#pragma unroll
            for (int j = 0; j < TN; j++) w[j] = Ws[kk * COUT + ct * TN + j];
#pragma unroll
            for (int i = 0; i < TM; i++) a[i] = As[(rt * TM + i) * LDA + kk];
#pragma unroll
            for (int i = 0; i < TM; i++)
#pragma unroll
                for (int j = 0; j < TN; j++) acc[i][j] += a[i] * w[j];
        }
    }

    // epilogue: bias, write, per-channel partial stats
    for (int c = tid; c < COUT; c += 256) { ss[c] = 0.f; sq[c] = 0.f; }
    __syncthreads();

    float bb[TN];
#pragma unroll
    for (int j = 0; j < TN; j++) bb[j] = bias[ct * TN + j];

    float sl[TN], ql[TN];
#pragma unroll
    for (int j = 0; j < TN; j++) { sl[j] = 0.f; ql[j] = 0.f; }
#pragma unroll
    for (int i = 0; i < TM; i++) {
        size_t r = row0 + rt * TM + i;
#pragma unroll
        for (int j = 0; j < TN; j++) {
            float v = acc[i][j] + bb[j];
            out[r * COUT + ct * TN + j] = v;
            sl[j] += v;
            ql[j] += v * v;
        }
    }
#pragma unroll
    for (int j = 0; j < TN; j++) {
        atomicAdd(&ss[ct * TN + j], sl[j]);
        atomicAdd(&sq[ct * TN + j], ql[j]);
    }
    __syncthreads();
    for (int c = tid; c < COUT; c += 256) {
        atomicAdd(&g_sum[c], (double)ss[c]);
        atomicAdd(&g_sumsq[c], (double)sq[c]);
    }
}

// ---------------- BN helpers ----------------
__global__ void bn_zero_kernel() {
    int i = threadIdx.x;
    if (i < 512) { g_sum[i] = 0.0; g_sumsq[i] = 0.0; }
}

__global__ void bn_finalize_kernel(int C, double invcnt, const float* __restrict__ gamma,
                                   const float* __restrict__ beta) {
    int c = threadIdx.x;
    if (c >= C) return;
    double m = g_sum[c] * invcnt;
    double var = g_sumsq[c] * invcnt - m * m;
    float s = gamma[c] * rsqrtf((float)var + 1e-5f);
    g_scale[c] = s;
    g_shift[c] = beta[c] - (float)m * s;
}

// ---------------- maxpool over K with fused BN+relu ----------------
// relu(s*x+t) is monotone in x (increasing if s>=0, decreasing if s<0),
// so pool the raw values (max or min by sign of s) then apply BN+relu once.
__global__ void maxpool_bn_kernel(const float* __restrict__ x, int S, int K, int C,
                                  float* __restrict__ out /*(B,C,S)*/,
                                  float* __restrict__ outT /*(B*S,C) or null*/) {
    int total = BB * S * C;
    int stride = gridDim.x * blockDim.x;
    for (int i = blockIdx.x * blockDim.x + threadIdx.x; i < total; i += stride) {
        int c = i % C;
        int s = (i / C) % S;
        int b = i / (C * S);
        const float* p = x + ((size_t)(b * S + s) * K) * C + c;
        float mx = p[0], mn = p[0];
        for (int k = 1; k < K; k++) {
            float v = p[(size_t)k * C];
            mx = fmaxf(mx, v);
            mn = fminf(mn, v);
        }
        float sc = g_scale[c];
        float raw = (sc >= 0.f) ? mx : mn;
        float r = fmaxf(raw * sc + g_shift[c], 0.f);
        out[(size_t)b * C * S + (size_t)c * S + s] = r;
        if (outT) outT[(size_t)(b * S + s) * C + c] = r;
    }
}

__global__ void zero_kernel(float* p, int n) {
    int i = blockIdx.x * blockDim.x + threadIdx.x;
    if (i < n) p[i] = 0.f;
}

// ---------------- orchestration ----------------
extern "C" void kernel_launch(void* const* d_in, const int* in_sizes, int n_in,
                              void* d_out, int out_size) {
    (void)in_sizes; (void)n_in; (void)out_size;
    const float* l0_xyz = (const float*)d_in[0];
    const float* l0_pts = (const float*)d_in[1];
    float* out = (float*)d_out;

    float* o_l1xyz = out;                 // 16*3*256   = 12288
    float* o_l1pts = out + 12288;         // 16*128*256 = 524288
    float* o_l2xyz = out + 536576;        // 16*3*128   = 6144
    float* o_l2pts = out + 542720;        // 16*256*128 = 524288
    float* o_l3xyz = out + 1067008;       // 16*3*1     = 48
    float* o_x     = out + 1067056;       // 16*512     = 8192

    float *bufA, *bufB, *nxyz, *l1pt, *l2pt;
    int *fidx, *gi;
    cudaGetSymbolAddress((void**)&bufA, g_bufA);
    cudaGetSymbolAddress((void**)&bufB, g_bufB);
    cudaGetSymbolAddress((void**)&nxyz, g_newxyz);
    cudaGetSymbolAddress((void**)&l1pt, g_l1pt);
    cudaGetSymbolAddress((void**)&l2pt, g_l2pt);
    cudaGetSymbolAddress((void**)&fidx, g_fidx);
    cudaGetSymbolAddress((void**)&gi, g_gi);

    cudaFuncSetAttribute((const void*)fps_kernel, cudaFuncAttributeMaxDynamicSharedMemorySize, 65536);

    // smem byte sizes: (BM*(KC+1) + KC*COUT + 2*COUT) * 4
    constexpr int SM1 = (64 * 9 + 8 * 64 + 2 * 64) * 4;        // 4864
    constexpr int SM2 = (128 * 17 + 16 * 128 + 2 * 128) * 4;   // 17920
    constexpr int SM3 = SM2;                                   // 17920
    constexpr int SM4 = (64 * 17 + 16 * 256 + 2 * 256) * 4;    // 22784
    constexpr int SM5 = SM4;                                   // 22784
    constexpr int SM6 = (32 * 17 + 16 * 512 + 2 * 512) * 4;    // 39040

    // ================= SA1 : N=4096 -> S=256, K=32 =================
    fps_kernel<<<16, 512, 65536>>>(l0_xyz, 4096, 256, fidx, nxyz, o_l1xyz);
    ballquery_kernel<<<(16 * 256) / 8, 256>>>(l0_xyz, nxyz, 4096, 256, 32, 0.04f, gi);
    gather_sa1<<<512, 256>>>(l0_xyz, l0_pts, gi, nxyz, bufA);

    bn_zero_kernel<<<1, 512>>>();
    gemm_k<6, 64, 64, 4, 8, false><<<131072 / 64, 256, SM1>>>(
        bufA, (const float*)d_in[2], (const float*)d_in[3], bufB);
    bn_finalize_kernel<<<1, 512>>>(64, 1.0 / 131072.0, (const float*)d_in[4], (const float*)d_in[5]);

    bn_zero_kernel<<<1, 512>>>();
    gemm_k<64, 128, 128, 8, 16, true><<<131072 / 128, 256, SM2>>>(
        bufB, (const float*)d_in[6], (const float*)d_in[7], bufA);
    bn_finalize_kernel<<<1, 512>>>(128, 1.0 / 131072.0, (const float*)d_in[8], (const float*)d_in[9]);

    maxpool_bn_kernel<<<2048, 256>>>(bufA, 256, 32, 128, o_l1pts, l1pt);

    // ================= SA2 : N=256 -> S=128, K=64 =================
    fps_kernel<<<16, 256, 4096>>>(o_l1xyz, 256, 128, fidx, nxyz, o_l2xyz);
    ballquery_kernel<<<(16 * 128) / 8, 256>>>(o_l1xyz, nxyz, 256, 128, 64, 0.0625f, gi);
    gather_sa2<<<16384, 256>>>(o_l1xyz, l1pt, gi, nxyz, bufA);

    bn_zero_kernel<<<1, 512>>>();
    gemm_k<131, 128, 128, 8, 16, false><<<131072 / 128, 256, SM3>>>(
        bufA, (const float*)d_in[10], (const float*)d_in[11], bufB);
    bn_finalize_kernel<<<1, 512>>>(128, 1.0 / 131072.0, (const float*)d_in[12], (const float*)d_in[13]);

    bn_zero_kernel<<<1, 512>>>();
    gemm_k<128, 256, 64, 8, 16, true><<<131072 / 64, 256, SM4>>>(
        bufB, (const float*)d_in[14], (const float*)d_in[15], bufA);
    bn_finalize_kernel<<<1, 512>>>(256, 1.0 / 131072.0, (const float*)d_in[16], (const float*)d_in[17]);

    maxpool_bn_kernel<<<2048, 256>>>(bufA, 128, 64, 256, o_l2pts, l2pt);

    // ================= SA3 : group_all, K=128 =================
    gather_sa3<<<256, 256>>>(o_l2xyz, l2pt, bufA);

    bn_zero_kernel<<<1, 512>>>();
    gemm_k<259, 256, 64, 8, 16, false><<<2048 / 64, 256, SM5>>>(
        bufA, (const float*)d_in[18], (const float*)d_in[19], bufB);
    bn_finalize_kernel<<<1, 512>>>(256, 1.0 / 2048.0, (const float*)d_in[20], (const float*)d_in[21]);

    bn_zero_kernel<<<1, 512>>>();
    gemm_k<256, 512, 32, 8, 16, true><<<2048 / 32, 256, SM6>>>(
        bufB, (const float*)d_in[22], (const float*)d_in[23], bufA);
    bn_finalize_kernel<<<1, 512>>>(512, 1.0 / 2048.0, (const float*)d_in[24], (const float*)d_in[25]);

    maxpool_bn_kernel<<<32, 256>>>(bufA, 1, 128, 512, o_x, nullptr);
    zero_kernel<<<1, 48>>>(o_l3xyz, 48);
}

// round 4
// speedup vs baseline: 1.5278x; 1.5278x over previous
#include <cuda_runtime.h>
#include <cuda_bf16.h>
#include <cstdint>
#include <cstddef>

// ---------------- problem constants ----------------
#define BB 16
#define N0 4096

// scratch (device globals; allocation-free per harness rules)
__device__ float  g_bufA[33554432];           // 128 MB  (max: 131072x256)
__device__ float  g_bufB[16777216];           // 64 MB   (max: 131072x128)
__device__ float  g_newxyz[BB * 256 * 3];
__device__ int    g_gi[131072];
__device__ float  g_l1pt[BB * 256 * 128];     // l1 points, (b,s,c) layout, post-BN
__device__ float  g_l2pt[BB * 128 * 256];     // l2 points, (b,s,c) layout, post-BN
__device__ double g_sum[512];
__device__ double g_sumsq[512];
__device__ float  g_scale[512];
__device__ float  g_shift[512];
__device__ __nv_bfloat16 g_whi[65536];
__device__ __nv_bfloat16 g_wlo[65536];

// ---------------- FPS: one block per batch ----------------
__global__ void fps_kernel(const float* __restrict__ xyz, int n, int npoint,
                           float* __restrict__ newxyz, float* __restrict__ outxyz) {
    extern __shared__ float sm[];
    float* sx = sm;
    float* sy = sm + n;
    float* sz = sm + 2 * n;
    float* dist = sm + 3 * n;
    __shared__ float rv[16];
    __shared__ int   ri[16];
    __shared__ int   sfar;

    int b = blockIdx.x, tid = threadIdx.x, bt = blockDim.x;
    const float* base = xyz + (size_t)b * 3 * n;
    for (int i = tid; i < n; i += bt) {
        sx[i] = base[i];
        sy[i] = base[n + i];
        sz[i] = base[2 * n + i];
        dist[i] = 1e10f;
    }
    __syncthreads();

    int far = 0;
    for (int t = 0; t < npoint; t++) {
        float cx = sx[far], cy = sy[far], cz = sz[far];
        if (tid == 0) {
            float* nw = &newxyz[(b * npoint + t) * 3];
            nw[0] = cx; nw[1] = cy; nw[2] = cz;
            outxyz[(size_t)b * 3 * npoint + t] = cx;
            outxyz[(size_t)b * 3 * npoint + npoint + t] = cy;
            outxyz[(size_t)b * 3 * npoint + 2 * npoint + t] = cz;
        }
        float bv = -1.0f;
        int bi = 0x7fffffff;
        for (int i = tid; i < n; i += bt) {
            float dx = __fsub_rn(sx[i], cx);
            float dy = __fsub_rn(sy[i], cy);
            float dz = __fsub_rn(sz[i], cz);
            float d = __fadd_rn(__fadd_rn(__fmul_rn(dx, dx), __fmul_rn(dy, dy)), __fmul_rn(dz, dz));
            float dd = fminf(dist[i], d);
            dist[i] = dd;
            if (dd > bv) { bv = dd; bi = i; }
        }
#pragma unroll
        for (int o = 16; o; o >>= 1) {
            float ov = __shfl_down_sync(0xffffffffu, bv, o);
            int   oi = __shfl_down_sync(0xffffffffu, bi, o);
            if (ov > bv || (ov == bv && oi < bi)) { bv = ov; bi = oi; }
        }
        if ((tid & 31) == 0) { rv[tid >> 5] = bv; ri[tid >> 5] = bi; }
        __syncthreads();
        if (tid < 32) {
            int nw = bt >> 5;
            float v = (tid < nw) ? rv[tid] : -2.0f;
            int  ii = (tid < nw) ? ri[tid] : 0x7fffffff;
#pragma unroll
            for (int o = 16; o; o >>= 1) {
                float ov = __shfl_down_sync(0xffffffffu, v, o);
                int   oi = __shfl_down_sync(0xffffffffu, ii, o);
                if (ov > v || (ov == v && oi < ii)) { v = ov; ii = oi; }
            }
            if (tid == 0) sfar = ii;
        }
        __syncthreads();
        far = sfar;
        __syncthreads();
    }
}

// ---------------- ball query: one warp per (b,s) ----------------
__global__ void ballquery_kernel(const float* __restrict__ xyz, const float* __restrict__ newxyz,
                                 int n, int S, int K, float r2, int* __restrict__ gi) {
    int gw = (blockIdx.x * blockDim.x + threadIdx.x) >> 5;
    int lane = threadIdx.x & 31;
    if (gw >= BB * S) return;
    int b = gw / S, s = gw % S;
    const float* nw = &newxyz[(b * S + s) * 3];
    float nx = nw[0], ny = nw[1], nz = nw[2];
    float nsq = __fadd_rn(__fadd_rn(__fmul_rn(nx, nx), __fmul_rn(ny, ny)), __fmul_rn(nz, nz));
    const float* px = xyz + (size_t)b * 3 * n;
    int* g = gi + (size_t)(b * S + s) * K;
    int cnt = 0, first = -1;
    for (int base = 0; base < n && cnt < K; base += 32) {
        int i = base + lane;
        float x = px[i], y = px[n + i], z = px[2 * n + i];
        float psq = __fadd_rn(__fadd_rn(__fmul_rn(x, x), __fmul_rn(y, y)), __fmul_rn(z, z));
        float dot = __fadd_rn(__fadd_rn(__fmul_rn(nx, x), __fmul_rn(ny, y)), __fmul_rn(nz, z));
        float sqr = __fsub_rn(__fadd_rn(nsq, psq), __fmul_rn(2.0f, dot));
        bool ok = !(sqr > r2);
        unsigned m = __ballot_sync(0xffffffffu, ok);
        if (first < 0 && m) first = base + __ffs(m) - 1;
        int pos = cnt + __popc(m & ((1u << lane) - 1u));
        if (ok && pos < K) g[pos] = i;
        cnt += __popc(m);
    }
    if (cnt > K) cnt = K;
    for (int p = cnt + lane; p < K; p += 32) g[p] = first;
}

// ---------------- gathers ----------------
__global__ void gather_sa1(const float* __restrict__ xyz, const float* __restrict__ pts,
                           const int* __restrict__ gi, const float* __restrict__ newxyz,
                           float* __restrict__ out) {
    int row = blockIdx.x * blockDim.x + threadIdx.x;
    if (row >= BB * 256 * 32) return;
    int s = (row >> 5) & 255, b = row >> 13;
    int idx = gi[row];
    const float* nw = &newxyz[(b * 256 + s) * 3];
    const float* px = xyz + (size_t)b * 3 * N0;
    const float* pp = pts + (size_t)b * 3 * N0;
    float* o = out + (size_t)row * 6;
    o[0] = __fsub_rn(px[idx], nw[0]);
    o[1] = __fsub_rn(px[N0 + idx], nw[1]);
    o[2] = __fsub_rn(px[2 * N0 + idx], nw[2]);
    o[3] = pp[idx];
    o[4] = pp[N0 + idx];
    o[5] = pp[2 * N0 + idx];
}

__global__ void gather_sa2(const float* __restrict__ l1xyz, const float* __restrict__ l1pt,
                           const int* __restrict__ gi, const float* __restrict__ newxyz,
                           float* __restrict__ out) {
    const int S = 128, K = 64, C = 131;
    int gw = (blockIdx.x * blockDim.x + threadIdx.x) >> 5;
    int lane = threadIdx.x & 31;
    if (gw >= BB * S * K) return;
    int s = (gw / K) % S, b = gw / (S * K);
    int idx = gi[gw];
    float* o = out + (size_t)gw * C;
    for (int c = lane; c < C; c += 32) {
        float v;
        if (c < 3)
            v = __fsub_rn(l1xyz[(size_t)b * 768 + c * 256 + idx], newxyz[(b * S + s) * 3 + c]);
        else
            v = l1pt[((size_t)b * 256 + idx) * 128 + (c - 3)];
        o[c] = v;
    }
}

__global__ void gather_sa3(const float* __restrict__ l2xyz, const float* __restrict__ l2pt,
                           float* __restrict__ out) {
    int gw = (blockIdx.x * blockDim.x + threadIdx.x) >> 5;
    int lane = threadIdx.x & 31;
    if (gw >= BB * 128) return;
    int k = gw % 128, b = gw / 128;
    float* o = out + (size_t)gw * 259;
    for (int c = lane; c < 259; c += 32) {
        float v = (c < 3) ? l2xyz[(size_t)b * 384 + c * 128 + k]
                          : l2pt[((size_t)b * 128 + k) * 256 + (c - 3)];
        o[c] = v;
    }
}

// ---------------- W prep: fp32 [CIN][COUT] -> bf16 hi/lo transposed [COUT][KPAD] ----------------
__global__ void prep_w(const float* __restrict__ W, int CIN, int COUT, int KPAD,
                       __nv_bfloat16* __restrict__ hi, __nv_bfloat16* __restrict__ lo) {
    int i = blockIdx.x * blockDim.x + threadIdx.x;
    if (i >= COUT * KPAD) return;
    int n = i / KPAD, k = i - n * KPAD;
    float v = (k < CIN) ? W[(size_t)k * COUT + n] : 0.f;
    __nv_bfloat16 h = __float2bfloat16_rn(v);
    float r = v - __bfloat162float(h);
    hi[i] = h;
    lo[i] = __float2bfloat16_rn(r);
}

// ---------------- mma.sync helper ----------------
__device__ __forceinline__ void mma16816(float* c, const uint32_t* a, uint32_t b0, uint32_t b1) {
    asm volatile(
        "mma.sync.aligned.m16n8k16.row.col.f32.bf16.bf16.f32 "
        "{%0,%1,%2,%3}, {%4,%5,%6,%7}, {%8,%9}, {%0,%1,%2,%3};"
        : "+f"(c[0]), "+f"(c[1]), "+f"(c[2]), "+f"(c[3])
        : "r"(a[0]), "r"(a[1]), "r"(a[2]), "r"(a[3]), "r"(b0), "r"(b1));
}

// ---------------- HMMA bf16 split GEMM: out = A(fp32) * W + bias ----------------
// Block tile: 128 rows x 128 cols, K chunked by 64. 8 warps as 4(m) x 2(n):
// each warp owns 32 rows x 64 cols = 2 m-tiles(16) x 8 n-tiles(8).
// Split: D = Ahi*Whi + Ahi*Wlo + Alo*Whi (fp32 accum). BN-in + stats fused.
template <int CIN, int COUT, bool IN_BN>
__global__ void __launch_bounds__(256)
hm_gemm(const float* __restrict__ A, const __nv_bfloat16* __restrict__ Whi,
        const __nv_bfloat16* __restrict__ Wlo, const float* __restrict__ bias,
        float* __restrict__ out) {
    constexpr int KPAD = (CIN + 63) & ~63;
    constexpr int NCH = KPAD / 64;
    constexpr int LD = 72;  // 64 + 8 pad -> conflict-free fragment loads
    extern __shared__ __nv_bfloat16 sh[];
    __nv_bfloat16* Ahi = sh;                 // 128 x LD
    __nv_bfloat16* Alo = Ahi + 128 * LD;
    __nv_bfloat16* Bhi = Alo + 128 * LD;     // [n][k] layout, 128 x LD
    __nv_bfloat16* Blo = Bhi + 128 * LD;

    int tid = threadIdx.x;
    int lane = tid & 31, w = tid >> 5;
    int mw = w >> 1, nw = w & 1;
    int g = lane >> 2, tg = lane & 3;
    size_t row0 = (size_t)blockIdx.x * 128;
    int n0 = blockIdx.y * 128;

    float acc[2][8][4];
#pragma unroll
    for (int i = 0; i < 2; i++)
#pragma unroll
        for (int j = 0; j < 8; j++)
#pragma unroll
            for (int q = 0; q < 4; q++) acc[i][j][q] = 0.f;

    for (int ch = 0; ch < NCH; ch++) {
        __syncthreads();
        // fill A chunk (fp32 -> hi/lo bf16 pairs)
        for (int e = tid; e < 128 * 32; e += 256) {
            int r = e >> 5, kp = e & 31;
            int gk = ch * 64 + kp * 2;
            float v0 = 0.f, v1 = 0.f;
            if (gk < CIN)     v0 = A[(row0 + r) * CIN + gk];
            if (gk + 1 < CIN) v1 = A[(row0 + r) * CIN + gk + 1];
            if (IN_BN) {
                if (gk < CIN)     v0 = fmaxf(v0 * g_scale[gk] + g_shift[gk], 0.f);
                if (gk + 1 < CIN) v1 = fmaxf(v1 * g_scale[gk + 1] + g_shift[gk + 1], 0.f);
            }
            __nv_bfloat16 h0 = __float2bfloat16_rn(v0);
            __nv_bfloat16 h1 = __float2bfloat16_rn(v1);
            __nv_bfloat162 hp; hp.x = h0; hp.y = h1;
            __nv_bfloat162 lp;
            lp.x = __float2bfloat16_rn(v0 - __bfloat162float(h0));
            lp.y = __float2bfloat16_rn(v1 - __bfloat162float(h1));
            *reinterpret_cast<__nv_bfloat162*>(&Ahi[r * LD + kp * 2]) = hp;
            *reinterpret_cast<__nv_bfloat162*>(&Alo[r * LD + kp * 2]) = lp;
        }
        // fill B chunk from pre-split transposed W [COUT][KPAD]
        for (int e = tid; e < 128 * 32; e += 256) {
            int n = e >> 5, kp = e & 31;
            size_t gidx = (size_t)(n0 + n) * KPAD + ch * 64 + kp * 2;
            *reinterpret_cast<__nv_bfloat162*>(&Bhi[n * LD + kp * 2]) =
                *reinterpret_cast<const __nv_bfloat162*>(Whi + gidx);
            *reinterpret_cast<__nv_bfloat162*>(&Blo[n * LD + kp * 2]) =
                *reinterpret_cast<const __nv_bfloat162*>(Wlo + gidx);
        }
        __syncthreads();

#pragma unroll
        for (int ks = 0; ks < 4; ks++) {
            int k0 = ks * 16;
            uint32_t ah[2][4], al[2][4];
#pragma unroll
            for (int mt = 0; mt < 2; mt++) {
                int rm = mw * 32 + mt * 16;
                ah[mt][0] = *reinterpret_cast<uint32_t*>(&Ahi[(rm + g) * LD + k0 + tg * 2]);
                ah[mt][1] = *reinterpret_cast<uint32_t*>(&Ahi[(rm + g + 8) * LD + k0 + tg * 2]);
                ah[mt][2] = *reinterpret_cast<uint32_t*>(&Ahi[(rm + g) * LD + k0 + tg * 2 + 8]);
                ah[mt][3] = *reinterpret_cast<uint32_t*>(&Ahi[(rm + g + 8) * LD + k0 + tg * 2 + 8]);
                al[mt][0] = *reinterpret_cast<uint32_t*>(&Alo[(rm + g) * LD + k0 + tg * 2]);
                al[mt][1] = *reinterpret_cast<uint32_t*>(&Alo[(rm + g + 8) * LD + k0 + tg * 2]);
                al[mt][2] = *reinterpret_cast<uint32_t*>(&Alo[(rm + g) * LD + k0 + tg * 2 + 8]);
                al[mt][3] = *reinterpret_cast<uint32_t*>(&Alo[(rm + g + 8) * LD + k0 + tg * 2 + 8]);
            }
#pragma unroll
            for (int nt = 0; nt < 8; nt++) {
                int cn = nw * 64 + nt * 8 + g;
                uint32_t bh0 = *reinterpret_cast<uint32_t*>(&Bhi[cn * LD + k0 + tg * 2]);
                uint32_t bh1 = *reinterpret_cast<uint32_t*>(&Bhi[cn * LD + k0 + tg * 2 + 8]);
                uint32_t bl0 = *reinterpret_cast<uint32_t*>(&Blo[cn * LD + k0 + tg * 2]);
                uint32_t bl1 = *reinterpret_cast<uint32_t*>(&Blo[cn * LD + k0 + tg * 2 + 8]);
#pragma unroll
                for (int mt = 0; mt < 2; mt++) {
                    mma16816(acc[mt][nt], ah[mt], bh0, bh1);
                    mma16816(acc[mt][nt], ah[mt], bl0, bl1);
                    mma16816(acc[mt][nt], al[mt], bh0, bh1);
                }
            }
        }
    }
    __syncthreads();

    // epilogue: bias + write + per-channel stats
    float* ss = reinterpret_cast<float*>(sh);
    float* sq = ss + 128;
    for (int c = tid; c < 128; c += 256) { ss[c] = 0.f; sq[c] = 0.f; }
    __syncthreads();

#pragma unroll
    for (int mt = 0; mt < 2; mt++) {
#pragma unroll
        for (int nt = 0; nt < 8; nt++) {
            int lc = nw * 64 + nt * 8 + tg * 2;
            size_t r0 = row0 + mw * 32 + mt * 16 + g;
            float b0 = bias[n0 + lc], b1 = bias[n0 + lc + 1];
            float v00 = acc[mt][nt][0] + b0, v01 = acc[mt][nt][1] + b1;
            float v10 = acc[mt][nt][2] + b0, v11 = acc[mt][nt][3] + b1;
            *reinterpret_cast<float2*>(&out[r0 * COUT + n0 + lc]) = make_float2(v00, v01);
            *reinterpret_cast<float2*>(&out[(r0 + 8) * COUT + n0 + lc]) = make_float2(v10, v11);
            float s0 = v00 + v10, q0 = v00 * v00 + v10 * v10;
            float s1 = v01 + v11, q1 = v01 * v01 + v11 * v11;
#pragma unroll
            for (int o = 4; o < 32; o <<= 1) {
                s0 += __shfl_xor_sync(0xffffffffu, s0, o);
                q0 += __shfl_xor_sync(0xffffffffu, q0, o);
                s1 += __shfl_xor_sync(0xffffffffu, s1, o);
                q1 += __shfl_xor_sync(0xffffffffu, q1, o);
            }
            if (g == 0) {
                atomicAdd(&ss[lc], s0);
                atomicAdd(&sq[lc], q0);
                atomicAdd(&ss[lc + 1], s1);
                atomicAdd(&sq[lc + 1], q1);
            }
        }
    }
    __syncthreads();
    for (int c = tid; c < 128; c += 256) {
        atomicAdd(&g_sum[n0 + c], (double)ss[c]);
        atomicAdd(&g_sumsq[n0 + c], (double)sq[c]);
    }
}

// ---------------- SIMT GEMM (small shapes): fused input BN + stats epilogue ----------------
template <int CIN, int COUT, int BM, int TN, int KC, bool IN_BN>
__global__ void __launch_bounds__(256)
gemm_k(const float* __restrict__ A, const float* __restrict__ W,
       const float* __restrict__ bias, float* __restrict__ out) {
    constexpr int COLT = COUT / TN;
    constexpr int ROWT = 256 / COLT;
    constexpr int TM = BM / ROWT;
    constexpr int LDA = KC + 1;
    extern __shared__ float sm[];
    float* As = sm;
    float* Ws = sm + BM * LDA;
    float* ss = Ws + KC * COUT;
    float* sq = ss + COUT;

    int tid = threadIdx.x;
    int ct = tid % COLT, rt = tid / COLT;
    size_t row0 = (size_t)blockIdx.x * BM;

    float acc[TM][TN];
#pragma unroll
    for (int i = 0; i < TM; i++)
#pragma unroll
        for (int j = 0; j < TN; j++) acc[i][j] = 0.f;

    for (int k0 = 0; k0 < CIN; k0 += KC) {
        int kc = (CIN - k0 < KC) ? (CIN - k0) : KC;
        __syncthreads();
        for (int e = tid; e < BM * kc; e += 256) {
            int r = e / kc, k = e - r * kc;
            float v = A[(row0 + r) * CIN + k0 + k];
            if (IN_BN) {
                int c = k0 + k;
                v = fmaxf(v * g_scale[c] + g_shift[c], 0.f);
            }
            As[r * LDA + k] = v;
        }
        for (int e = tid; e < kc * COUT; e += 256)
            Ws[e] = W[(size_t)k0 * COUT + e];
        __syncthreads();
        for (int kk = 0; kk < kc; kk++) {
            float a[TM], ww[TN];
#pragma unroll
            for (int j = 0; j < TN; j++) ww[j] = Ws[kk * COUT + ct * TN + j];
#pragma unroll
            for (int i = 0; i < TM; i++) a[i] = As[(rt * TM + i) * LDA + kk];
#pragma unroll
            for (int i = 0; i < TM; i++)
#pragma unroll
                for (int j = 0; j < TN; j++) acc[i][j] += a[i] * ww[j];
        }
    }

    for (int c = tid; c < COUT; c += 256) { ss[c] = 0.f; sq[c] = 0.f; }
    __syncthreads();

    float bb[TN];
#pragma unroll
    for (int j = 0; j < TN; j++) bb[j] = bias[ct * TN + j];

    float sl[TN], ql[TN];
#pragma unroll
    for (int j = 0; j < TN; j++) { sl[j] = 0.f; ql[j] = 0.f; }
#pragma unroll
    for (int i = 0; i < TM; i++) {
        size_t r = row0 + rt * TM + i;
#pragma unroll
        for (int j = 0; j < TN; j++) {
            float v = acc[i][j] + bb[j];
            out[r * COUT + ct * TN + j] = v;
            sl[j] += v;
            ql[j] += v * v;
        }
    }
#pragma unroll
    for (int j = 0; j < TN; j++) {
        atomicAdd(&ss[ct * TN + j], sl[j]);
        atomicAdd(&sq[ct * TN + j], ql[j]);
    }
    __syncthreads();
    for (int c = tid; c < COUT; c += 256) {
        atomicAdd(&g_sum[c], (double)ss[c]);
        atomicAdd(&g_sumsq[c], (double)sq[c]);
    }
}

// ---------------- BN finalize (also re-zeros accumulators for next use) ----------------
__global__ void bn_finalize_kernel(int C, double invcnt, const float* __restrict__ gamma,
                                   const float* __restrict__ beta) {
    int c = threadIdx.x;
    if (c < C) {
        double m = g_sum[c] * invcnt;
        double var = g_sumsq[c] * invcnt - m * m;
        float s = gamma[c] * rsqrtf((float)var + 1e-5f);
        g_scale[c] = s;
        g_shift[c] = beta[c] - (float)m * s;
    }
    g_sum[c] = 0.0;
    g_sumsq[c] = 0.0;
}

// ---------------- maxpool over K with fused BN+relu ----------------
__global__ void maxpool_bn_kernel(const float* __restrict__ x, int S, int K, int C,
                                  float* __restrict__ out /*(B,C,S)*/,
                                  float* __restrict__ outT /*(B*S,C) or null*/) {
    int total = BB * S * C;
    int stride = gridDim.x * blockDim.x;
    for (int i = blockIdx.x * blockDim.x + threadIdx.x; i < total; i += stride) {
        int c = i % C;
        int s = (i / C) % S;
        int b = i / (C * S);
        const float* p = x + ((size_t)(b * S + s) * K) * C + c;
        float mx = p[0], mn = p[0];
        for (int k = 1; k < K; k++) {
            float v = p[(size_t)k * C];
            mx = fmaxf(mx, v);
            mn = fminf(mn, v);
        }
        float sc = g_scale[c];
        float raw = (sc >= 0.f) ? mx : mn;
        float r = fmaxf(raw * sc + g_shift[c], 0.f);
        out[(size_t)b * C * S + (size_t)c * S + s] = r;
        if (outT) outT[(size_t)(b * S + s) * C + c] = r;
    }
}

__global__ void zero_kernel(float* p, int n) {
    int i = blockIdx.x * blockDim.x + threadIdx.x;
    if (i < n) p[i] = 0.f;
}

// ---------------- orchestration ----------------
extern "C" void kernel_launch(void* const* d_in, const int* in_sizes, int n_in,
                              void* d_out, int out_size) {
    (void)in_sizes; (void)n_in; (void)out_size;
    const float* l0_xyz = (const float*)d_in[0];
    const float* l0_pts = (const float*)d_in[1];
    float* out = (float*)d_out;

    float* o_l1xyz = out;                 // 16*3*256   = 12288
    float* o_l1pts = out + 12288;         // 16*128*256 = 524288
    float* o_l2xyz = out + 536576;        // 16*3*128   = 6144
    float* o_l2pts = out + 542720;        // 16*256*128 = 524288
    float* o_l3xyz = out + 1067008;       // 16*3*1     = 48
    float* o_x     = out + 1067056;       // 16*512     = 8192

    float *bufA, *bufB, *nxyz, *l1pt, *l2pt;
    int *gi;
    __nv_bfloat16 *whi, *wlo;
    cudaGetSymbolAddress((void**)&bufA, g_bufA);
    cudaGetSymbolAddress((void**)&bufB, g_bufB);
    cudaGetSymbolAddress((void**)&nxyz, g_newxyz);
    cudaGetSymbolAddress((void**)&l1pt, g_l1pt);
    cudaGetSymbolAddress((void**)&l2pt, g_l2pt);
    cudaGetSymbolAddress((void**)&gi, g_gi);
    cudaGetSymbolAddress((void**)&whi, g_whi);
    cudaGetSymbolAddress((void**)&wlo, g_wlo);

    cudaFuncSetAttribute((const void*)fps_kernel, cudaFuncAttributeMaxDynamicSharedMemorySize, 65536);
    constexpr int HSM = 4 * 128 * 72 * 2;  // 73728 bytes
    cudaFuncSetAttribute((const void*)hm_gemm<64, 128, true>,   cudaFuncAttributeMaxDynamicSharedMemorySize, HSM);
    cudaFuncSetAttribute((const void*)hm_gemm<131, 128, false>, cudaFuncAttributeMaxDynamicSharedMemorySize, HSM);
    cudaFuncSetAttribute((const void*)hm_gemm<128, 256, true>,  cudaFuncAttributeMaxDynamicSharedMemorySize, HSM);

    // ================= SA1 : N=4096 -> S=256, K=32 =================
    fps_kernel<<<16, 512, 65536>>>(l0_xyz, 4096, 256, nxyz, o_l1xyz);
    ballquery_kernel<<<(16 * 256) / 8, 256>>>(l0_xyz, nxyz, 4096, 256, 32, 0.04f, gi);
    gather_sa1<<<512, 256>>>(l0_xyz, l0_pts, gi, nxyz, bufA);

    // 6 -> 64 (SIMT)
    gemm_k<6, 64, 64, 4, 8, false><<<131072 / 64, 256, 4864>>>(
        bufA, (const float*)d_in[2], (const float*)d_in[3], bufB);
    bn_finalize_kernel<<<1, 512>>>(64, 1.0 / 131072.0, (const float*)d_in[4], (const float*)d_in[5]);

    // 64 -> 128 (HMMA)
    prep_w<<<32, 256>>>((const float*)d_in[6], 64, 128, 64, whi, wlo);
    hm_gemm<64, 128, true><<<dim3(1024, 1), 256, HSM>>>(bufB, whi, wlo, (const float*)d_in[7], bufA);
    bn_finalize_kernel<<<1, 512>>>(128, 1.0 / 131072.0, (const float*)d_in[8], (const float*)d_in[9]);

    maxpool_bn_kernel<<<2048, 256>>>(bufA, 256, 32, 128, o_l1pts, l1pt);

    // ================= SA2 : N=256 -> S=128, K=64 =================
    fps_kernel<<<16, 256, 4096>>>(o_l1xyz, 256, 128, nxyz, o_l2xyz);
    ballquery_kernel<<<(16 * 128) / 8, 256>>>(o_l1xyz, nxyz, 256, 128, 64, 0.0625f, gi);
    gather_sa2<<<16384, 256>>>(o_l1xyz, l1pt, gi, nxyz, bufA);

    // 131 -> 128 (HMMA, KPAD=192)
    prep_w<<<96, 256>>>((const float*)d_in[10], 131, 128, 192, whi, wlo);
    hm_gemm<131, 128, false><<<dim3(1024, 1), 256, HSM>>>(bufA, whi, wlo, (const float*)d_in[11], bufB);
    bn_finalize_kernel<<<1, 512>>>(128, 1.0 / 131072.0, (const float*)d_in[12], (const float*)d_in[13]);

    // 128 -> 256 (HMMA)
    prep_w<<<128, 256>>>((const float*)d_in[14], 128, 256, 128, whi, wlo);
    hm_gemm<128, 256, true><<<dim3(1024, 2), 256, HSM>>>(bufB, whi, wlo, (const float*)d_in[15], bufA);
    bn_finalize_kernel<<<1, 512>>>(256, 1.0 / 131072.0, (const float*)d_in[16], (const float*)d_in[17]);

    maxpool_bn_kernel<<<2048, 256>>>(bufA, 128, 64, 256, o_l2pts, l2pt);

    // ================= SA3 : group_all, K=128 =================
    gather_sa3<<<256, 256>>>(o_l2xyz, l2pt, bufA);

    // 259 -> 256 (SIMT), BM=16: smem (16*17 + 16*256 + 512)*4 = 19520
    gemm_k<259, 256, 16, 4, 16, false><<<2048 / 16, 256, 19520>>>(
        bufA, (const float*)d_in[18], (const float*)d_in[19], bufB);
    bn_finalize_kernel<<<1, 512>>>(256, 1.0 / 2048.0, (const float*)d_in[20], (const float*)d_in[21]);

    // 256 -> 512 (SIMT), BM=16: smem (16*17 + 16*512 + 1024)*4 = 37952
    gemm_k<256, 512, 16, 8, 16, true><<<2048 / 16, 256, 37952>>>(
        bufB, (const float*)d_in[22], (const float*)d_in[23], bufA);
    bn_finalize_kernel<<<1, 512>>>(512, 1.0 / 2048.0, (const float*)d_in[24], (const float*)d_in[25]);

    maxpool_bn_kernel<<<32, 256>>>(bufA, 1, 128, 512, o_x, nullptr);
    zero_kernel<<<1, 48>>>(o_l3xyz, 48);
}

// round 5
// speedup vs baseline: 1.6286x; 1.0659x over previous
#include <cuda_runtime.h>
#include <cuda_bf16.h>
#include <cstdint>
#include <cstddef>

// ---------------- problem constants ----------------
#define BB 16
#define N0 4096

// scratch (device globals; allocation-free per harness rules)
__device__ float  g_bufB[16777216];           // 64 MB (max: 131072x128)
__device__ float  g_bufA[8388608];            // 32 MB (sa3 scratch)
__device__ float  g_newxyz[BB * 256 * 3];
__device__ int    g_gi[131072];
__device__ float  g_l1pt[BB * 256 * 128];     // l1 points, (b,s,c), post-BN
__device__ float  g_l2pt[BB * 128 * 256];     // l2 points, (b,s,c), post-BN
__device__ double g_sum[512];
__device__ double g_sumsq[512];
__device__ float  g_scale[512];
__device__ float  g_shift[512];
__device__ __nv_bfloat16 g_whi[65536];
__device__ __nv_bfloat16 g_wlo[65536];
__device__ float  g_pmax[1048576];            // pooled-raw max per 32-row block
__device__ float  g_pmin[1048576];            // pooled-raw min per 32-row block

// ---------------- FPS: one block per batch ----------------
__global__ void fps_kernel(const float* __restrict__ xyz, int n, int npoint,
                           float* __restrict__ newxyz, float* __restrict__ outxyz) {
    extern __shared__ float sm[];
    float* sx = sm;
    float* sy = sm + n;
    float* sz = sm + 2 * n;
    float* dist = sm + 3 * n;
    __shared__ float rv[32];
    __shared__ int   ri[32];
    __shared__ int   sfar;

    int b = blockIdx.x, tid = threadIdx.x, bt = blockDim.x;
    const float* base = xyz + (size_t)b * 3 * n;
    for (int i = tid; i < n; i += bt) {
        sx[i] = base[i];
        sy[i] = base[n + i];
        sz[i] = base[2 * n + i];
        dist[i] = 1e10f;
    }
    __syncthreads();

    int far = 0;
    for (int t = 0; t < npoint; t++) {
        float cx = sx[far], cy = sy[far], cz = sz[far];
        if (tid == 0) {
            float* nw = &newxyz[(b * npoint + t) * 3];
            nw[0] = cx; nw[1] = cy; nw[2] = cz;
            outxyz[(size_t)b * 3 * npoint + t] = cx;
            outxyz[(size_t)b * 3 * npoint + npoint + t] = cy;
            outxyz[(size_t)b * 3 * npoint + 2 * npoint + t] = cz;
        }
        float bv = -1.0f;
        int bi = 0x7fffffff;
        for (int i = tid; i < n; i += bt) {
            float dx = __fsub_rn(sx[i], cx);
            float dy = __fsub_rn(sy[i], cy);
            float dz = __fsub_rn(sz[i], cz);
            float d = __fadd_rn(__fadd_rn(__fmul_rn(dx, dx), __fmul_rn(dy, dy)), __fmul_rn(dz, dz));
            float dd = fminf(dist[i], d);
            dist[i] = dd;
            if (dd > bv) { bv = dd; bi = i; }
        }
#pragma unroll
        for (int o = 16; o; o >>= 1) {
            float ov = __shfl_down_sync(0xffffffffu, bv, o);
            int   oi = __shfl_down_sync(0xffffffffu, bi, o);
            if (ov > bv || (ov == bv && oi < bi)) { bv = ov; bi = oi; }
        }
        if ((tid & 31) == 0) { rv[tid >> 5] = bv; ri[tid >> 5] = bi; }
        __syncthreads();
        if (tid < 32) {
            int nw = bt >> 5;
            float v = (tid < nw) ? rv[tid] : -2.0f;
            int  ii = (tid < nw) ? ri[tid] : 0x7fffffff;
#pragma unroll
            for (int o = 16; o; o >>= 1) {
                float ov = __shfl_down_sync(0xffffffffu, v, o);
                int   oi = __shfl_down_sync(0xffffffffu, ii, o);
                if (ov > v || (ov == v && oi < ii)) { v = ov; ii = oi; }
            }
            if (tid == 0) sfar = ii;
        }
        __syncthreads();
        far = sfar;
        __syncthreads();
    }
}

// ---------------- ball query: one warp per (b,s) ----------------
__global__ void ballquery_kernel(const float* __restrict__ xyz, const float* __restrict__ newxyz,
                                 int n, int S, int K, float r2, int* __restrict__ gi) {
    int gw = (blockIdx.x * blockDim.x + threadIdx.x) >> 5;
    int lane = threadIdx.x & 31;
    if (gw >= BB * S) return;
    int b = gw / S, s = gw % S;
    const float* nw = &newxyz[(b * S + s) * 3];
    float nx = nw[0], ny = nw[1], nz = nw[2];
    float nsq = __fadd_rn(__fadd_rn(__fmul_rn(nx, nx), __fmul_rn(ny, ny)), __fmul_rn(nz, nz));
    const float* px = xyz + (size_t)b * 3 * n;
    int* g = gi + (size_t)(b * S + s) * K;
    int cnt = 0, first = -1;
    for (int base = 0; base < n && cnt < K; base += 32) {
        int i = base + lane;
        float x = px[i], y = px[n + i], z = px[2 * n + i];
        float psq = __fadd_rn(__fadd_rn(__fmul_rn(x, x), __fmul_rn(y, y)), __fmul_rn(z, z));
        float dot = __fadd_rn(__fadd_rn(__fmul_rn(nx, x), __fmul_rn(ny, y)), __fmul_rn(nz, z));
        float sqr = __fsub_rn(__fadd_rn(nsq, psq), __fmul_rn(2.0f, dot));
        bool ok = !(sqr > r2);
        unsigned m = __ballot_sync(0xffffffffu, ok);
        if (first < 0 && m) first = base + __ffs(m) - 1;
        int pos = cnt + __popc(m & ((1u << lane) - 1u));
        if (ok && pos < K) g[pos] = i;
        cnt += __popc(m);
    }
    if (cnt > K) cnt = K;
    for (int p = cnt + lane; p < K; p += 32) g[p] = first;
}

// ---------------- fused gather + GEMM1 (6 -> 64) + stats ----------------
__global__ void __launch_bounds__(256)
gather_gemm1(const float* __restrict__ xyz, const float* __restrict__ pts,
             const int* __restrict__ gi, const float* __restrict__ newxyz,
             const float* __restrict__ W, const float* __restrict__ bias,
             float* __restrict__ out) {
    __shared__ float Ws[6 * 64];
    __shared__ float bs[64];
    __shared__ float ss[64], sq[64];
    int tid = threadIdx.x;
    for (int e = tid; e < 384; e += 256) Ws[e] = W[e];
    if (tid < 64) { bs[tid] = bias[tid]; ss[tid] = 0.f; sq[tid] = 0.f; }
    __syncthreads();

    int row = blockIdx.x * 256 + tid;
    int b = row >> 13, s = (row >> 5) & 255;
    int idx = gi[row];
    const float* px = xyz + (size_t)b * 3 * N0;
    const float* pp = pts + (size_t)b * 3 * N0;
    const float* nw = &newxyz[(b * 256 + s) * 3];
    float in[6];
    in[0] = __fsub_rn(px[idx], nw[0]);
    in[1] = __fsub_rn(px[N0 + idx], nw[1]);
    in[2] = __fsub_rn(px[2 * N0 + idx], nw[2]);
    in[3] = pp[idx];
    in[4] = pp[N0 + idx];
    in[5] = pp[2 * N0 + idx];

    const float4* W4 = reinterpret_cast<const float4*>(Ws);
    const float4* b4 = reinterpret_cast<const float4*>(bs);
    float4 v[16];
#pragma unroll
    for (int j = 0; j < 16; j++) v[j] = b4[j];
#pragma unroll
    for (int k = 0; k < 6; k++) {
        float a = in[k];
#pragma unroll
        for (int j = 0; j < 16; j++) {
            float4 w = W4[k * 16 + j];
            v[j].x += a * w.x; v[j].y += a * w.y;
            v[j].z += a * w.z; v[j].w += a * w.w;
        }
    }
    float4* o4 = reinterpret_cast<float4*>(out + (size_t)row * 64);
#pragma unroll
    for (int j = 0; j < 16; j++) o4[j] = v[j];

    int lane = tid & 31;
#pragma unroll
    for (int j = 0; j < 16; j++) {
        float c[4] = {v[j].x, v[j].y, v[j].z, v[j].w};
#pragma unroll
        for (int q = 0; q < 4; q++) {
            float sv = c[q], qv = c[q] * c[q];
#pragma unroll
            for (int o = 16; o; o >>= 1) {
                sv += __shfl_xor_sync(0xffffffffu, sv, o);
                qv += __shfl_xor_sync(0xffffffffu, qv, o);
            }
            if (lane == 0) {
                atomicAdd(&ss[j * 4 + q], sv);
                atomicAdd(&sq[j * 4 + q], qv);
            }
        }
    }
    __syncthreads();
    if (tid < 64) {
        atomicAdd(&g_sum[tid], (double)ss[tid]);
        atomicAdd(&g_sumsq[tid], (double)sq[tid]);
    }
}

// ---------------- W prep: fp32 [CIN][COUT] -> bf16 hi/lo transposed [COUT][KPAD] ----------------
__global__ void prep_w(const float* __restrict__ W, int CIN, int COUT, int KPAD,
                       __nv_bfloat16* __restrict__ hi, __nv_bfloat16* __restrict__ lo) {
    int i = blockIdx.x * blockDim.x + threadIdx.x;
    if (i >= COUT * KPAD) return;
    int n = i / KPAD, k = i - n * KPAD;
    float v = (k < CIN) ? W[(size_t)k * COUT + n] : 0.f;
    __nv_bfloat16 h = __float2bfloat16_rn(v);
    float r = v - __bfloat162float(h);
    hi[i] = h;
    lo[i] = __float2bfloat16_rn(r);
}

// ---------------- mma.sync helper ----------------
__device__ __forceinline__ void mma16816(float* c, const uint32_t* a, uint32_t b0, uint32_t b1) {
    asm volatile(
        "mma.sync.aligned.m16n8k16.row.col.f32.bf16.bf16.f32 "
        "{%0,%1,%2,%3}, {%4,%5,%6,%7}, {%8,%9}, {%0,%1,%2,%3};"
        : "+f"(c[0]), "+f"(c[1]), "+f"(c[2]), "+f"(c[3])
        : "r"(a[0]), "r"(a[1]), "r"(a[2]), "r"(a[3]), "r"(b0), "r"(b1));
}

// ---------------- HMMA bf16 split GEMM ----------------
// Block 128x128, K chunk 64, 8 warps 4(m)x2(n). Split hi/lo (3 MMAs).
// POOL: skip activation store; write per-32-row-block raw max/min (bias incl).
// GATHER2: A elements gathered on the fly (SA2 grouping, CIN=131 layout).
template <int CIN, int COUT, bool IN_BN, bool POOL, bool GATHER2>
__global__ void __launch_bounds__(256)
hm_gemm(const float* __restrict__ A, const __nv_bfloat16* __restrict__ Whi,
        const __nv_bfloat16* __restrict__ Wlo, const float* __restrict__ bias,
        float* __restrict__ out, const int* __restrict__ gi,
        const float* __restrict__ gxyz, const float* __restrict__ gnew) {
    constexpr int KPAD = (CIN + 63) & ~63;
    constexpr int NCH = KPAD / 64;
    constexpr int LD = 72;
    extern __shared__ __nv_bfloat16 sh[];
    __nv_bfloat16* Ahi = sh;
    __nv_bfloat16* Alo = Ahi + 128 * LD;
    __nv_bfloat16* Bhi = Alo + 128 * LD;
    __nv_bfloat16* Blo = Bhi + 128 * LD;

    int tid = threadIdx.x;
    int lane = tid & 31, w = tid >> 5;
    int mw = w >> 1, nw = w & 1;
    int g = lane >> 2, tg = lane & 3;
    size_t row0 = (size_t)blockIdx.x * 128;
    int n0 = blockIdx.y * 128;

    float acc[2][8][4];
#pragma unroll
    for (int i = 0; i < 2; i++)
#pragma unroll
        for (int j = 0; j < 8; j++)
#pragma unroll
            for (int q = 0; q < 4; q++) acc[i][j][q] = 0.f;

    for (int ch = 0; ch < NCH; ch++) {
        __syncthreads();
        for (int e = tid; e < 128 * 32; e += 256) {
            int r = e >> 5, kp = e & 31;
            int gk = ch * 64 + kp * 2;
            float v0 = 0.f, v1 = 0.f;
            if (GATHER2) {
                size_t R = row0 + r;
                int bb_ = (int)(R >> 13);
                int idx = gi[R];
                size_t sidx = R >> 6;
                if (gk < CIN)
                    v0 = (gk < 3)
                        ? __fsub_rn(gxyz[bb_ * 768 + gk * 256 + idx], gnew[sidx * 3 + gk])
                        : A[((size_t)(bb_ * 256 + idx)) * 128 + (gk - 3)];
                if (gk + 1 < CIN)
                    v1 = (gk + 1 < 3)
                        ? __fsub_rn(gxyz[bb_ * 768 + (gk + 1) * 256 + idx], gnew[sidx * 3 + gk + 1])
                        : A[((size_t)(bb_ * 256 + idx)) * 128 + (gk - 2)];
            } else {
                if (gk < CIN)     v0 = A[(row0 + r) * CIN + gk];
                if (gk + 1 < CIN) v1 = A[(row0 + r) * CIN + gk + 1];
            }
            if (IN_BN) {
                if (gk < CIN)     v0 = fmaxf(v0 * g_scale[gk] + g_shift[gk], 0.f);
                if (gk + 1 < CIN) v1 = fmaxf(v1 * g_scale[gk + 1] + g_shift[gk + 1], 0.f);
            }
            __nv_bfloat16 h0 = __float2bfloat16_rn(v0);
            __nv_bfloat16 h1 = __float2bfloat16_rn(v1);
            __nv_bfloat162 hp; hp.x = h0; hp.y = h1;
            __nv_bfloat162 lp;
            lp.x = __float2bfloat16_rn(v0 - __bfloat162float(h0));
            lp.y = __float2bfloat16_rn(v1 - __bfloat162float(h1));
            *reinterpret_cast<__nv_bfloat162*>(&Ahi[r * LD + kp * 2]) = hp;
            *reinterpret_cast<__nv_bfloat162*>(&Alo[r * LD + kp * 2]) = lp;
        }
        for (int e = tid; e < 128 * 32; e += 256) {
            int n = e >> 5, kp = e & 31;
            size_t gidx = (size_t)(n0 + n) * KPAD + ch * 64 + kp * 2;
            *reinterpret_cast<__nv_bfloat162*>(&Bhi[n * LD + kp * 2]) =
                *reinterpret_cast<const __nv_bfloat162*>(Whi + gidx);
            *reinterpret_cast<__nv_bfloat162*>(&Blo[n * LD + kp * 2]) =
                *reinterpret_cast<const __nv_bfloat162*>(Wlo + gidx);
        }
        __syncthreads();

#pragma unroll
        for (int ks = 0; ks < 4; ks++) {
            int k0 = ks * 16;
            uint32_t ah[2][4], al[2][4];
#pragma unroll
            for (int mt = 0; mt < 2; mt++) {
                int rm = mw * 32 + mt * 16;
                ah[mt][0] = *reinterpret_cast<uint32_t*>(&Ahi[(rm + g) * LD + k0 + tg * 2]);
                ah[mt][1] = *reinterpret_cast<uint32_t*>(&Ahi[(rm + g + 8) * LD + k0 + tg * 2]);
                ah[mt][2] = *reinterpret_cast<uint32_t*>(&Ahi[(rm + g) * LD + k0 + tg * 2 + 8]);
                ah[mt][3] = *reinterpret_cast<uint32_t*>(&Ahi[(rm + g + 8) * LD + k0 + tg * 2 + 8]);
                al[mt][0] = *reinterpret_cast<uint32_t*>(&Alo[(rm + g) * LD + k0 + tg * 2]);
                al[mt][1] = *reinterpret_cast<uint32_t*>(&Alo[(rm + g + 8) * LD + k0 + tg * 2]);
                al[mt][2] = *reinterpret_cast<uint32_t*>(&Alo[(rm + g) * LD + k0 + tg * 2 + 8]);
                al[mt][3] = *reinterpret_cast<uint32_t*>(&Alo[(rm + g + 8) * LD + k0 + tg * 2 + 8]);
            }
#pragma unroll
            for (int nt = 0; nt < 8; nt++) {
                int cn = nw * 64 + nt * 8 + g;
                uint32_t bh0 = *reinterpret_cast<uint32_t*>(&Bhi[cn * LD + k0 + tg * 2]);
                uint32_t bh1 = *reinterpret_cast<uint32_t*>(&Bhi[cn * LD + k0 + tg * 2 + 8]);
                uint32_t bl0 = *reinterpret_cast<uint32_t*>(&Blo[cn * LD + k0 + tg * 2]);
                uint32_t bl1 = *reinterpret_cast<uint32_t*>(&Blo[cn * LD + k0 + tg * 2 + 8]);
#pragma unroll
                for (int mt = 0; mt < 2; mt++) {
                    mma16816(acc[mt][nt], ah[mt], bh0, bh1);
                    mma16816(acc[mt][nt], ah[mt], bl0, bl1);
                    mma16816(acc[mt][nt], al[mt], bh0, bh1);
                }
            }
        }
    }
    __syncthreads();

    // epilogue
    float* ss = reinterpret_cast<float*>(sh);
    float* sq = ss + 128;
    for (int c = tid; c < 128; c += 256) { ss[c] = 0.f; sq[c] = 0.f; }
    __syncthreads();

    int rb32 = (int)(row0 >> 5) + mw;
#pragma unroll
    for (int nt = 0; nt < 8; nt++) {
        int lc = nw * 64 + nt * 8 + tg * 2;
        float b0 = bias[n0 + lc], b1 = bias[n0 + lc + 1];
        float s0 = 0.f, q0 = 0.f, s1 = 0.f, q1 = 0.f;
        float mx0 = -3.4e38f, mn0 = 3.4e38f, mx1 = -3.4e38f, mn1 = 3.4e38f;
#pragma unroll
        for (int mt = 0; mt < 2; mt++) {
            float v00 = acc[mt][nt][0] + b0, v01 = acc[mt][nt][1] + b1;
            float v10 = acc[mt][nt][2] + b0, v11 = acc[mt][nt][3] + b1;
            if (!POOL) {
                size_t r0 = row0 + mw * 32 + mt * 16 + g;
                *reinterpret_cast<float2*>(&out[r0 * COUT + n0 + lc]) = make_float2(v00, v01);
                *reinterpret_cast<float2*>(&out[(r0 + 8) * COUT + n0 + lc]) = make_float2(v10, v11);
            }
            s0 += v00 + v10; q0 += v00 * v00 + v10 * v10;
            s1 += v01 + v11; q1 += v01 * v01 + v11 * v11;
            mx0 = fmaxf(mx0, fmaxf(v00, v10)); mn0 = fminf(mn0, fminf(v00, v10));
            mx1 = fmaxf(mx1, fmaxf(v01, v11)); mn1 = fminf(mn1, fminf(v01, v11));
        }
#pragma unroll
        for (int o = 4; o < 32; o <<= 1) {
            s0 += __shfl_xor_sync(0xffffffffu, s0, o);
            q0 += __shfl_xor_sync(0xffffffffu, q0, o);
            s1 += __shfl_xor_sync(0xffffffffu, s1, o);
            q1 += __shfl_xor_sync(0xffffffffu, q1, o);
            if (POOL) {
                mx0 = fmaxf(mx0, __shfl_xor_sync(0xffffffffu, mx0, o));
                mn0 = fminf(mn0, __shfl_xor_sync(0xffffffffu, mn0, o));
                mx1 = fmaxf(mx1, __shfl_xor_sync(0xffffffffu, mx1, o));
                mn1 = fminf(mn1, __shfl_xor_sync(0xffffffffu, mn1, o));
            }
        }
        if (g == 0) {
            atomicAdd(&ss[lc], s0);
            atomicAdd(&sq[lc], q0);
            atomicAdd(&ss[lc + 1], s1);
            atomicAdd(&sq[lc + 1], q1);
            if (POOL) {
                size_t pb = (size_t)rb32 * COUT + n0 + lc;
                g_pmax[pb] = mx0; g_pmin[pb] = mn0;
                g_pmax[pb + 1] = mx1; g_pmin[pb + 1] = mn1;
            }
        }
    }
    __syncthreads();
    for (int c = tid; c < 128; c += 256) {
        atomicAdd(&g_sum[n0 + c], (double)ss[c]);
        atomicAdd(&g_sumsq[n0 + c], (double)sq[c]);
    }
}

// ---------------- pooled-raw -> BN + relu -> outputs ----------------
__global__ void pool_bn_out(int S, int KG, int C, float* __restrict__ out /*(B,C,S)*/,
                            float* __restrict__ outT /*(B*S,C) or null*/) {
    int total = BB * S * C;
    int stride = gridDim.x * blockDim.x;
    for (int i = blockIdx.x * blockDim.x + threadIdx.x; i < total; i += stride) {
        int c = i % C;
        int s = (i / C) % S;
        int b = i / (C * S);
        size_t base = ((size_t)(b * S + s) * KG) * C + c;
        float mx = g_pmax[base], mn = g_pmin[base];
        for (int q = 1; q < KG; q++) {
            mx = fmaxf(mx, g_pmax[base + (size_t)q * C]);
            mn = fminf(mn, g_pmin[base + (size_t)q * C]);
        }
        float sc = g_scale[c];
        float raw = (sc >= 0.f) ? mx : mn;
        float r = fmaxf(raw * sc + g_shift[c], 0.f);
        out[(size_t)b * C * S + (size_t)c * S + s] = r;
        if (outT) outT[(size_t)(b * S + s) * C + c] = r;
    }
}

// ---------------- SIMT GEMM (small shapes): fused input BN + stats epilogue ----------------
template <int CIN, int COUT, int BM, int TN, int KC, bool IN_BN>
__global__ void __launch_bounds__(256)
gemm_k(const float* __restrict__ A, const float* __restrict__ W,
       const float* __restrict__ bias, float* __restrict__ out) {
    constexpr int COLT = COUT / TN;
    constexpr int ROWT = 256 / COLT;
    constexpr int TM = BM / ROWT;
    constexpr int LDA = KC + 1;
    extern __shared__ float sm[];
    float* As = sm;
    float* Ws = sm + BM * LDA;
    float* ss = Ws + KC * COUT;
    float* sq = ss + COUT;

    int tid = threadIdx.x;
    int ct = tid % COLT, rt = tid / COLT;
    size_t row0 = (size_t)blockIdx.x * BM;

    float acc[TM][TN];
#pragma unroll
    for (int i = 0; i < TM; i++)
#pragma unroll
        for (int j = 0; j < TN; j++) acc[i][j] = 0.f;

    for (int k0 = 0; k0 < CIN; k0 += KC) {
        int kc = (CIN - k0 < KC) ? (CIN - k0) : KC;
        __syncthreads();
        for (int e = tid; e < BM * kc; e += 256) {
            int r = e / kc, k = e - r * kc;
            float v = A[(row0 + r) * CIN + k0 + k];
            if (IN_BN) {
                int c = k0 + k;
                v = fmaxf(v * g_scale[c] + g_shift[c], 0.f);
            }
            As[r * LDA + k] = v;
        }
        for (int e = tid; e < kc * COUT; e += 256)
            Ws[e] = W[(size_t)k0 * COUT + e];
        __syncthreads();
        for (int kk = 0; kk < kc; kk++) {
            float a[TM], ww[TN];
#pragma unroll
            for (int j = 0; j < TN; j++) ww[j] = Ws[kk * COUT + ct * TN + j];
#pragma unroll
            for (int i = 0; i < TM; i++) a[i] = As[(rt * TM + i) * LDA + kk];
#pragma unroll
            for (int i = 0; i < TM; i++)
#pragma unroll
                for (int j = 0; j < TN; j++) acc[i][j] += a[i] * ww[j];
        }
    }

    for (int c = tid; c < COUT; c += 256) { ss[c] = 0.f; sq[c] = 0.f; }
    __syncthreads();

    float bb[TN];
#pragma unroll
    for (int j = 0; j < TN; j++) bb[j] = bias[ct * TN + j];

    float sl[TN], ql[TN];
#pragma unroll
    for (int j = 0; j < TN; j++) { sl[j] = 0.f; ql[j] = 0.f; }
#pragma unroll
    for (int i = 0; i < TM; i++) {
        size_t r = row0 + rt * TM + i;
#pragma unroll
        for (int j = 0; j < TN; j++) {
            float v = acc[i][j] + bb[j];
            out[r * COUT + ct * TN + j] = v;
            sl[j] += v;
            ql[j] += v * v;
        }
    }
#pragma unroll
    for (int j = 0; j < TN; j++) {
        atomicAdd(&ss[ct * TN + j], sl[j]);
        atomicAdd(&sq[ct * TN + j], ql[j]);
    }
    __syncthreads();
    for (int c = tid; c < COUT; c += 256) {
        atomicAdd(&g_sum[c], (double)ss[c]);
        atomicAdd(&g_sumsq[c], (double)sq[c]);
    }
}

// ---------------- gathers (sa3 only) ----------------
__global__ void gather_sa3(const float* __restrict__ l2xyz, const float* __restrict__ l2pt,
                           float* __restrict__ out) {
    int gw = (blockIdx.x * blockDim.x + threadIdx.x) >> 5;
    int lane = threadIdx.x & 31;
    if (gw >= BB * 128) return;
    int k = gw % 128, b = gw / 128;
    float* o = out + (size_t)gw * 259;
    for (int c = lane; c < 259; c += 32) {
        float v = (c < 3) ? l2xyz[(size_t)b * 384 + c * 128 + k]
                          : l2pt[((size_t)b * 128 + k) * 256 + (c - 3)];
        o[c] = v;
    }
}

// ---------------- BN finalize (also re-zeros accumulators for next use) ----------------
__global__ void bn_finalize_kernel(int C, double invcnt, const float* __restrict__ gamma,
                                   const float* __restrict__ beta) {
    int c = threadIdx.x;
    if (c < C) {
        double m = g_sum[c] * invcnt;
        double var = g_sumsq[c] * invcnt - m * m;
        float s = gamma[c] * rsqrtf((float)var + 1e-5f);
        g_scale[c] = s;
        g_shift[c] = beta[c] - (float)m * s;
    }
    g_sum[c] = 0.0;
    g_sumsq[c] = 0.0;
}

// ---------------- maxpool over K with fused BN+relu (sa3) ----------------
__global__ void maxpool_bn_kernel(const float* __restrict__ x, int S, int K, int C,
                                  float* __restrict__ out, float* __restrict__ outT) {
    int total = BB * S * C;
    int stride = gridDim.x * blockDim.x;
    for (int i = blockIdx.x * blockDim.x + threadIdx.x; i < total; i += stride) {
        int c = i % C;
        int s = (i / C) % S;
        int b = i / (C * S);
        const float* p = x + ((size_t)(b * S + s) * K) * C + c;
        float mx = p[0], mn = p[0];
        for (int k = 1; k < K; k++) {
            float v = p[(size_t)k * C];
            mx = fmaxf(mx, v);
            mn = fminf(mn, v);
        }
        float sc = g_scale[c];
        float raw = (sc >= 0.f) ? mx : mn;
        float r = fmaxf(raw * sc + g_shift[c], 0.f);
        out[(size_t)b * C * S + (size_t)c * S + s] = r;
        if (outT) outT[(size_t)(b * S + s) * C + c] = r;
    }
}

__global__ void zero_kernel(float* p, int n) {
    int i = blockIdx.x * blockDim.x + threadIdx.x;
    if (i < n) p[i] = 0.f;
}

// ---------------- orchestration ----------------
extern "C" void kernel_launch(void* const* d_in, const int* in_sizes, int n_in,
                              void* d_out, int out_size) {
    (void)in_sizes; (void)n_in; (void)out_size;
    const float* l0_xyz = (const float*)d_in[0];
    const float* l0_pts = (const float*)d_in[1];
    float* out = (float*)d_out;

    float* o_l1xyz = out;                 // 16*3*256   = 12288
    float* o_l1pts = out + 12288;         // 16*128*256 = 524288
    float* o_l2xyz = out + 536576;        // 16*3*128   = 6144
    float* o_l2pts = out + 542720;        // 16*256*128 = 524288
    float* o_l3xyz = out + 1067008;       // 16*3*1     = 48
    float* o_x     = out + 1067056;       // 16*512     = 8192

    float *bufA, *bufB, *nxyz, *l1pt, *l2pt;
    int *gi;
    __nv_bfloat16 *whi, *wlo;
    cudaGetSymbolAddress((void**)&bufA, g_bufA);
    cudaGetSymbolAddress((void**)&bufB, g_bufB);
    cudaGetSymbolAddress((void**)&nxyz, g_newxyz);
    cudaGetSymbolAddress((void**)&l1pt, g_l1pt);
    cudaGetSymbolAddress((void**)&l2pt, g_l2pt);
    cudaGetSymbolAddress((void**)&gi, g_gi);
    cudaGetSymbolAddress((void**)&whi, g_whi);
    cudaGetSymbolAddress((void**)&wlo, g_wlo);

    cudaFuncSetAttribute((const void*)fps_kernel, cudaFuncAttributeMaxDynamicSharedMemorySize, 65536);
    constexpr int HSM = 4 * 128 * 72 * 2;  // 73728 bytes
    cudaFuncSetAttribute((const void*)hm_gemm<64, 128, true, true, false>,
                         cudaFuncAttributeMaxDynamicSharedMemorySize, HSM);
    cudaFuncSetAttribute((const void*)hm_gemm<131, 128, false, false, true>,
                         cudaFuncAttributeMaxDynamicSharedMemorySize, HSM);
    cudaFuncSetAttribute((const void*)hm_gemm<128, 256, true, true, false>,
                         cudaFuncAttributeMaxDynamicSharedMemorySize, HSM);

    // ================= SA1 : N=4096 -> S=256, K=32 =================
    fps_kernel<<<16, 1024, 65536>>>(l0_xyz, 4096, 256, nxyz, o_l1xyz);
    ballquery_kernel<<<(16 * 256) / 8, 256>>>(l0_xyz, nxyz, 4096, 256, 32, 0.04f, gi);

    // fused gather + 6->64 GEMM + stats
    gather_gemm1<<<512, 256>>>(l0_xyz, l0_pts, gi, nxyz,
                               (const float*)d_in[2], (const float*)d_in[3], bufB);
    bn_finalize_kernel<<<1, 512>>>(64, 1.0 / 131072.0, (const float*)d_in[4], (const float*)d_in[5]);

    // 64 -> 128 (HMMA, pooled epilogue)
    prep_w<<<32, 256>>>((const float*)d_in[6], 64, 128, 64, whi, wlo);
    hm_gemm<64, 128, true, true, false><<<dim3(1024, 1), 256, HSM>>>(
        bufB, whi, wlo, (const float*)d_in[7], nullptr, nullptr, nullptr, nullptr);
    bn_finalize_kernel<<<1, 512>>>(128, 1.0 / 131072.0, (const float*)d_in[8], (const float*)d_in[9]);
    pool_bn_out<<<2048, 256>>>(256, 1, 128, o_l1pts, l1pt);

    // ================= SA2 : N=256 -> S=128, K=64 =================
    fps_kernel<<<16, 256, 4096>>>(o_l1xyz, 256, 128, nxyz, o_l2xyz);
    ballquery_kernel<<<(16 * 128) / 8, 256>>>(o_l1xyz, nxyz, 256, 128, 64, 0.0625f, gi);

    // 131 -> 128 (HMMA, fused gather)
    prep_w<<<96, 256>>>((const float*)d_in[10], 131, 128, 192, whi, wlo);
    hm_gemm<131, 128, false, false, true><<<dim3(1024, 1), 256, HSM>>>(
        l1pt, whi, wlo, (const float*)d_in[11], bufB, gi, o_l1xyz, nxyz);
    bn_finalize_kernel<<<1, 512>>>(128, 1.0 / 131072.0, (const float*)d_in[12], (const float*)d_in[13]);

    // 128 -> 256 (HMMA, pooled epilogue)
    prep_w<<<128, 256>>>((const float*)d_in[14], 128, 256, 128, whi, wlo);
    hm_gemm<128, 256, true, true, false><<<dim3(1024, 2), 256, HSM>>>(
        bufB, whi, wlo, (const float*)d_in[15], nullptr, nullptr, nullptr, nullptr);
    bn_finalize_kernel<<<1, 512>>>(256, 1.0 / 131072.0, (const float*)d_in[16], (const float*)d_in[17]);
    pool_bn_out<<<2048, 256>>>(128, 2, 256, o_l2pts, l2pt);

    // ================= SA3 : group_all, K=128 =================
    gather_sa3<<<256, 256>>>(o_l2xyz, l2pt, bufA);

    gemm_k<259, 256, 16, 4, 16, false><<<2048 / 16, 256, 19520>>>(
        bufA, (const float*)d_in[18], (const float*)d_in[19], bufB);
    bn_finalize_kernel<<<1, 512>>>(256, 1.0 / 2048.0, (const float*)d_in[20], (const float*)d_in[21]);

    gemm_k<256, 512, 16, 8, 16, true><<<2048 / 16, 256, 37952>>>(
        bufB, (const float*)d_in[22], (const float*)d_in[23], bufA);
    bn_finalize_kernel<<<1, 512>>>(512, 1.0 / 2048.0, (const float*)d_in[24], (const float*)d_in[25]);

    maxpool_bn_kernel<<<32, 256>>>(bufA, 1, 128, 512, o_x, nullptr);
    zero_kernel<<<1, 48>>>(o_l3xyz, 48);
}

// round 6
// speedup vs baseline: 2.1075x; 1.2941x over previous
#include <cuda_runtime.h>
#include <cuda_bf16.h>
#include <cstdint>
#include <cstddef>

// ---------------- problem constants ----------------
#define BB 16
#define N0 4096

// scratch (device globals; allocation-free per harness rules)
__device__ float  g_bufB[16777216];           // 64 MB (max: 131072x128)
__device__ float  g_bufA[8388608];            // 32 MB (sa3 scratch)
__device__ float  g_newxyz[BB * 256 * 3];
__device__ int    g_gi[131072];
__device__ float  g_l1pt[BB * 256 * 128];     // l1 points, (b,s,c), post-BN
__device__ float  g_l2pt[BB * 128 * 256];     // l2 points, (b,s,c), post-BN
__device__ double g_sum[512];
__device__ double g_sumsq[512];
__device__ float  g_scale[512];
__device__ float  g_shift[512];
__device__ __nv_bfloat16 g_whi[65536];
__device__ __nv_bfloat16 g_wlo[65536];
__device__ float  g_pmax[1048576];            // pooled-raw max per 32-row block
__device__ float  g_pmin[1048576];            // pooled-raw min per 32-row block

// ---------------- FPS: register dist + redux argmax, 2 bars/iter ----------------
// dist >= 0 always, so fp32 ordering == u32 bit-pattern ordering. Argmax with
// first-occurrence tie-break: stage 1 redux.max on value bits, stage 2 redux.min
// on index among lanes holding the max. Thread-local scan keeps first max.
template <int NPT>
__global__ void fps_fast(const float* __restrict__ xyz, int n, int npoint,
                         float* __restrict__ newxyz, float* __restrict__ outxyz) {
    extern __shared__ float sm[];
    float* sx = sm;
    float* sy = sm + n;
    float* sz = sm + 2 * n;
    uint32_t* pval = reinterpret_cast<uint32_t*>(sm + 3 * n);
    uint32_t* pidx = pval + 32;
    __shared__ int sfar;

    int b = blockIdx.x, tid = threadIdx.x, bt = blockDim.x;
    int wid = tid >> 5, lane = tid & 31;
    int nwarps = bt >> 5;
    const float* base = xyz + (size_t)b * 3 * n;
    for (int i = tid; i < n; i += bt) {
        sx[i] = base[i];
        sy[i] = base[n + i];
        sz[i] = base[2 * n + i];
    }
    __syncthreads();

    float px[NPT], py[NPT], pz[NPT], pd[NPT];
#pragma unroll
    for (int j = 0; j < NPT; j++) {
        int i = tid + j * bt;
        px[j] = sx[i]; py[j] = sy[i]; pz[j] = sz[i];
        pd[j] = 1e10f;
    }

    int far = 0;
    for (int t = 0; t < npoint; t++) {
        float cx = sx[far], cy = sy[far], cz = sz[far];
        if (tid == 0) {
            float* nw = &newxyz[(b * npoint + t) * 3];
            nw[0] = cx; nw[1] = cy; nw[2] = cz;
            outxyz[(size_t)b * 3 * npoint + t] = cx;
            outxyz[(size_t)b * 3 * npoint + npoint + t] = cy;
            outxyz[(size_t)b * 3 * npoint + 2 * npoint + t] = cz;
        }
        uint32_t bv; int bi;
#pragma unroll
        for (int j = 0; j < NPT; j++) {
            float dx = __fsub_rn(px[j], cx);
            float dy = __fsub_rn(py[j], cy);
            float dz = __fsub_rn(pz[j], cz);
            float d = __fadd_rn(__fadd_rn(__fmul_rn(dx, dx), __fmul_rn(dy, dy)), __fmul_rn(dz, dz));
            float dd = fminf(pd[j], d);
            pd[j] = dd;
            uint32_t bits = __float_as_uint(dd);
            if (j == 0) { bv = bits; bi = tid; }
            else if (bits > bv) { bv = bits; bi = tid + j * bt; }
        }
        // warp-level two-stage argmax
        uint32_t mval = __reduce_max_sync(0xffffffffu, bv);
        uint32_t cand = (bv == mval) ? (uint32_t)bi : 0xffffffffu;
        uint32_t midx = __reduce_min_sync(0xffffffffu, cand);
        if (lane == 0) { pval[wid] = mval; pidx[wid] = midx; }
        __syncthreads();
        if (wid == 0) {
            uint32_t v = (lane < nwarps) ? pval[lane] : 0u;
            uint32_t ii = (lane < nwarps) ? pidx[lane] : 0xffffffffu;
            uint32_t m = __reduce_max_sync(0xffffffffu, v);
            uint32_t c = (v == m) ? ii : 0xffffffffu;
            uint32_t mi = __reduce_min_sync(0xffffffffu, c);
            if (lane == 0) sfar = (int)mi;
        }
        __syncthreads();
        far = sfar;
        // race-free: sfar is re-written only after next iteration's first
        // __syncthreads, which every thread passes after this read.
    }
}

// ---------------- ball query: one warp per (b,s) ----------------
__global__ void ballquery_kernel(const float* __restrict__ xyz, const float* __restrict__ newxyz,
                                 int n, int S, int K, float r2, int* __restrict__ gi) {
    int gw = (blockIdx.x * blockDim.x + threadIdx.x) >> 5;
    int lane = threadIdx.x & 31;
    if (gw >= BB * S) return;
    int b = gw / S, s = gw % S;
    const float* nw = &newxyz[(b * S + s) * 3];
    float nx = nw[0], ny = nw[1], nz = nw[2];
    float nsq = __fadd_rn(__fadd_rn(__fmul_rn(nx, nx), __fmul_rn(ny, ny)), __fmul_rn(nz, nz));
    const float* px = xyz + (size_t)b * 3 * n;
    int* g = gi + (size_t)(b * S + s) * K;
    int cnt = 0, first = -1;
    for (int base = 0; base < n && cnt < K; base += 32) {
        int i = base + lane;
        float x = px[i], y = px[n + i], z = px[2 * n + i];
        float psq = __fadd_rn(__fadd_rn(__fmul_rn(x, x), __fmul_rn(y, y)), __fmul_rn(z, z));
        float dot = __fadd_rn(__fadd_rn(__fmul_rn(nx, x), __fmul_rn(ny, y)), __fmul_rn(nz, z));
        float sqr = __fsub_rn(__fadd_rn(nsq, psq), __fmul_rn(2.0f, dot));
        bool ok = !(sqr > r2);
        unsigned m = __ballot_sync(0xffffffffu, ok);
        if (first < 0 && m) first = base + __ffs(m) - 1;
        int pos = cnt + __popc(m & ((1u << lane) - 1u));
        if (ok && pos < K) g[pos] = i;
        cnt += __popc(m);
    }
    if (cnt > K) cnt = K;
    for (int p = cnt + lane; p < K; p += 32) g[p] = first;
}

// ---------------- fused gather + GEMM1 (6 -> 64) + stats ----------------
__global__ void __launch_bounds__(256)
gather_gemm1(const float* __restrict__ xyz, const float* __restrict__ pts,
             const int* __restrict__ gi, const float* __restrict__ newxyz,
             const float* __restrict__ W, const float* __restrict__ bias,
             float* __restrict__ out) {
    __shared__ float Ws[6 * 64];
    __shared__ float bs[64];
    __shared__ float ss[64], sq[64];
    int tid = threadIdx.x;
    for (int e = tid; e < 384; e += 256) Ws[e] = W[e];
    if (tid < 64) { bs[tid] = bias[tid]; ss[tid] = 0.f; sq[tid] = 0.f; }
    __syncthreads();

    int row = blockIdx.x * 256 + tid;
    int b = row >> 13, s = (row >> 5) & 255;
    int idx = gi[row];
    const float* px = xyz + (size_t)b * 3 * N0;
    const float* pp = pts + (size_t)b * 3 * N0;
    const float* nw = &newxyz[(b * 256 + s) * 3];
    float in[6];
    in[0] = __fsub_rn(px[idx], nw[0]);
    in[1] = __fsub_rn(px[N0 + idx], nw[1]);
    in[2] = __fsub_rn(px[2 * N0 + idx], nw[2]);
    in[3] = pp[idx];
    in[4] = pp[N0 + idx];
    in[5] = pp[2 * N0 + idx];

    const float4* W4 = reinterpret_cast<const float4*>(Ws);
    const float4* b4 = reinterpret_cast<const float4*>(bs);
    float4 v[16];
#pragma unroll
    for (int j = 0; j < 16; j++) v[j] = b4[j];
#pragma unroll
    for (int k = 0; k < 6; k++) {
        float a = in[k];
#pragma unroll
        for (int j = 0; j < 16; j++) {
            float4 w = W4[k * 16 + j];
            v[j].x += a * w.x; v[j].y += a * w.y;
            v[j].z += a * w.z; v[j].w += a * w.w;
        }
    }
    float4* o4 = reinterpret_cast<float4*>(out + (size_t)row * 64);
#pragma unroll
    for (int j = 0; j < 16; j++) o4[j] = v[j];

    int lane = tid & 31;
#pragma unroll
    for (int j = 0; j < 16; j++) {
        float c[4] = {v[j].x, v[j].y, v[j].z, v[j].w};
#pragma unroll
        for (int q = 0; q < 4; q++) {
            float sv = c[q], qv = c[q] * c[q];
#pragma unroll
            for (int o = 16; o; o >>= 1) {
                sv += __shfl_xor_sync(0xffffffffu, sv, o);
                qv += __shfl_xor_sync(0xffffffffu, qv, o);
            }
            if (lane == 0) {
                atomicAdd(&ss[j * 4 + q], sv);
                atomicAdd(&sq[j * 4 + q], qv);
            }
        }
    }
    __syncthreads();
    if (tid < 64) {
        atomicAdd(&g_sum[tid], (double)ss[tid]);
        atomicAdd(&g_sumsq[tid], (double)sq[tid]);
    }
}

// ---------------- W prep: fp32 [CIN][COUT] -> bf16 hi/lo transposed [COUT][KPAD] ----------------
__global__ void prep_w(const float* __restrict__ W, int CIN, int COUT, int KPAD,
                       __nv_bfloat16* __restrict__ hi, __nv_bfloat16* __restrict__ lo) {
    int i = blockIdx.x * blockDim.x + threadIdx.x;
    if (i >= COUT * KPAD) return;
    int n = i / KPAD, k = i - n * KPAD;
    float v = (k < CIN) ? W[(size_t)k * COUT + n] : 0.f;
    __nv_bfloat16 h = __float2bfloat16_rn(v);
    float r = v - __bfloat162float(h);
    hi[i] = h;
    lo[i] = __float2bfloat16_rn(r);
}

// ---------------- mma.sync helper ----------------
__device__ __forceinline__ void mma16816(float* c, const uint32_t* a, uint32_t b0, uint32_t b1) {
    asm volatile(
        "mma.sync.aligned.m16n8k16.row.col.f32.bf16.bf16.f32 "
        "{%0,%1,%2,%3}, {%4,%5,%6,%7}, {%8,%9}, {%0,%1,%2,%3};"
        : "+f"(c[0]), "+f"(c[1]), "+f"(c[2]), "+f"(c[3])
        : "r"(a[0]), "r"(a[1]), "r"(a[2]), "r"(a[3]), "r"(b0), "r"(b1));
}

// ---------------- HMMA bf16 split GEMM ----------------
template <int CIN, int COUT, bool IN_BN, bool POOL, bool GATHER2>
__global__ void __launch_bounds__(256)
hm_gemm(const float* __restrict__ A, const __nv_bfloat16* __restrict__ Whi,
        const __nv_bfloat16* __restrict__ Wlo, const float* __restrict__ bias,
        float* __restrict__ out, const int* __restrict__ gi,
        const float* __restrict__ gxyz, const float* __restrict__ gnew) {
    constexpr int KPAD = (CIN + 63) & ~63;
    constexpr int NCH = KPAD / 64;
    constexpr int LD = 72;
    extern __shared__ __nv_bfloat16 sh[];
    __nv_bfloat16* Ahi = sh;
    __nv_bfloat16* Alo = Ahi + 128 * LD;
    __nv_bfloat16* Bhi = Alo + 128 * LD;
    __nv_bfloat16* Blo = Bhi + 128 * LD;

    int tid = threadIdx.x;
    int lane = tid & 31, w = tid >> 5;
    int mw = w >> 1, nw = w & 1;
    int g = lane >> 2, tg = lane & 3;
    size_t row0 = (size_t)blockIdx.x * 128;
    int n0 = blockIdx.y * 128;

    float acc[2][8][4];
#pragma unroll
    for (int i = 0; i < 2; i++)
#pragma unroll
        for (int j = 0; j < 8; j++)
#pragma unroll
            for (int q = 0; q < 4; q++) acc[i][j][q] = 0.f;

    for (int ch = 0; ch < NCH; ch++) {
        __syncthreads();
        for (int e = tid; e < 128 * 32; e += 256) {
            int r = e >> 5, kp = e & 31;
            int gk = ch * 64 + kp * 2;
            float v0 = 0.f, v1 = 0.f;
            if (GATHER2) {
                size_t R = row0 + r;
                int bb_ = (int)(R >> 13);
                int idx = gi[R];
                size_t sidx = R >> 6;
                if (gk < CIN)
                    v0 = (gk < 3)
                        ? __fsub_rn(gxyz[bb_ * 768 + gk * 256 + idx], gnew[sidx * 3 + gk])
                        : A[((size_t)(bb_ * 256 + idx)) * 128 + (gk - 3)];
                if (gk + 1 < CIN)
                    v1 = (gk + 1 < 3)
                        ? __fsub_rn(gxyz[bb_ * 768 + (gk + 1) * 256 + idx], gnew[sidx * 3 + gk + 1])
                        : A[((size_t)(bb_ * 256 + idx)) * 128 + (gk - 2)];
            } else {
                if (gk < CIN)     v0 = A[(row0 + r) * CIN + gk];
                if (gk + 1 < CIN) v1 = A[(row0 + r) * CIN + gk + 1];
            }
            if (IN_BN) {
                if (gk < CIN)     v0 = fmaxf(v0 * g_scale[gk] + g_shift[gk], 0.f);
                if (gk + 1 < CIN) v1 = fmaxf(v1 * g_scale[gk + 1] + g_shift[gk + 1], 0.f);
            }
            __nv_bfloat16 h0 = __float2bfloat16_rn(v0);
            __nv_bfloat16 h1 = __float2bfloat16_rn(v1);
            __nv_bfloat162 hp; hp.x = h0; hp.y = h1;
            __nv_bfloat162 lp;
            lp.x = __float2bfloat16_rn(v0 - __bfloat162float(h0));
            lp.y = __float2bfloat16_rn(v1 - __bfloat162float(h1));
            *reinterpret_cast<__nv_bfloat162*>(&Ahi[r * LD + kp * 2]) = hp;
            *reinterpret_cast<__nv_bfloat162*>(&Alo[r * LD + kp * 2]) = lp;
        }
        for (int e = tid; e < 128 * 32; e += 256) {
            int n = e >> 5, kp = e & 31;
            size_t gidx = (size_t)(n0 + n) * KPAD + ch * 64 + kp * 2;
            *reinterpret_cast<__nv_bfloat162*>(&Bhi[n * LD + kp * 2]) =
                *reinterpret_cast<const __nv_bfloat162*>(Whi + gidx);
            *reinterpret_cast<__nv_bfloat162*>(&Blo[n * LD + kp * 2]) =
                *reinterpret_cast<const __nv_bfloat162*>(Wlo + gidx);
        }
        __syncthreads();

#pragma unroll
        for (int ks = 0; ks < 4; ks++) {
            int k0 = ks * 16;
            uint32_t ah[2][4], al[2][4];
#pragma unroll
            for (int mt = 0; mt < 2; mt++) {
                int rm = mw * 32 + mt * 16;
                ah[mt][0] = *reinterpret_cast<uint32_t*>(&Ahi[(rm + g) * LD + k0 + tg * 2]);
                ah[mt][1] = *reinterpret_cast<uint32_t*>(&Ahi[(rm + g + 8) * LD + k0 + tg * 2]);
                ah[mt][2] = *reinterpret_cast<uint32_t*>(&Ahi[(rm + g) * LD + k0 + tg * 2 + 8]);
                ah[mt][3] = *reinterpret_cast<uint32_t*>(&Ahi[(rm + g + 8) * LD + k0 + tg * 2 + 8]);
                al[mt][0] = *reinterpret_cast<uint32_t*>(&Alo[(rm + g) * LD + k0 + tg * 2]);
                al[mt][1] = *reinterpret_cast<uint32_t*>(&Alo[(rm + g + 8) * LD + k0 + tg * 2]);
                al[mt][2] = *reinterpret_cast<uint32_t*>(&Alo[(rm + g) * LD + k0 + tg * 2 + 8]);
                al[mt][3] = *reinterpret_cast<uint32_t*>(&Alo[(rm + g + 8) * LD + k0 + tg * 2 + 8]);
            }
#pragma unroll
            for (int nt = 0; nt < 8; nt++) {
                int cn = nw * 64 + nt * 8 + g;
                uint32_t bh0 = *reinterpret_cast<uint32_t*>(&Bhi[cn * LD + k0 + tg * 2]);
                uint32_t bh1 = *reinterpret_cast<uint32_t*>(&Bhi[cn * LD + k0 + tg * 2 + 8]);
                uint32_t bl0 = *reinterpret_cast<uint32_t*>(&Blo[cn * LD + k0 + tg * 2]);
                uint32_t bl1 = *reinterpret_cast<uint32_t*>(&Blo[cn * LD + k0 + tg * 2 + 8]);
#pragma unroll
                for (int mt = 0; mt < 2; mt++) {
                    mma16816(acc[mt][nt], ah[mt], bh0, bh1);
                    mma16816(acc[mt][nt], ah[mt], bl0, bl1);
                    mma16816(acc[mt][nt], al[mt], bh0, bh1);
                }
            }
        }
    }
    __syncthreads();

    float* ss = reinterpret_cast<float*>(sh);
    float* sq = ss + 128;
    for (int c = tid; c < 128; c += 256) { ss[c] = 0.f; sq[c] = 0.f; }
    __syncthreads();

    int rb32 = (int)(row0 >> 5) + mw;
#pragma unroll
    for (int nt = 0; nt < 8; nt++) {
        int lc = nw * 64 + nt * 8 + tg * 2;
        float b0 = bias[n0 + lc], b1 = bias[n0 + lc + 1];
        float s0 = 0.f, q0 = 0.f, s1 = 0.f, q1 = 0.f;
        float mx0 = -3.4e38f, mn0 = 3.4e38f, mx1 = -3.4e38f, mn1 = 3.4e38f;
#pragma unroll
        for (int mt = 0; mt < 2; mt++) {
            float v00 = acc[mt][nt][0] + b0, v01 = acc[mt][nt][1] + b1;
            float v10 = acc[mt][nt][2] + b0, v11 = acc[mt][nt][3] + b1;
            if (!POOL) {
                size_t r0 = row0 + mw * 32 + mt * 16 + g;
                *reinterpret_cast<float2*>(&out[r0 * COUT + n0 + lc]) = make_float2(v00, v01);
                *reinterpret_cast<float2*>(&out[(r0 + 8) * COUT + n0 + lc]) = make_float2(v10, v11);
            }
            s0 += v00 + v10; q0 += v00 * v00 + v10 * v10;
            s1 += v01 + v11; q1 += v01 * v01 + v11 * v11;
            mx0 = fmaxf(mx0, fmaxf(v00, v10)); mn0 = fminf(mn0, fminf(v00, v10));
            mx1 = fmaxf(mx1, fmaxf(v01, v11)); mn1 = fminf(mn1, fminf(v01, v11));
        }
#pragma unroll
        for (int o = 4; o < 32; o <<= 1) {
            s0 += __shfl_xor_sync(0xffffffffu, s0, o);
            q0 += __shfl_xor_sync(0xffffffffu, q0, o);
            s1 += __shfl_xor_sync(0xffffffffu, s1, o);
            q1 += __shfl_xor_sync(0xffffffffu, q1, o);
            if (POOL) {
                mx0 = fmaxf(mx0, __shfl_xor_sync(0xffffffffu, mx0, o));
                mn0 = fminf(mn0, __shfl_xor_sync(0xffffffffu, mn0, o));
                mx1 = fmaxf(mx1, __shfl_xor_sync(0xffffffffu, mx1, o));
                mn1 = fminf(mn1, __shfl_xor_sync(0xffffffffu, mn1, o));
            }
        }
        if (g == 0) {
            atomicAdd(&ss[lc], s0);
            atomicAdd(&sq[lc], q0);
            atomicAdd(&ss[lc + 1], s1);
            atomicAdd(&sq[lc + 1], q1);
            if (POOL) {
                size_t pb = (size_t)rb32 * COUT + n0 + lc;
                g_pmax[pb] = mx0; g_pmin[pb] = mn0;
                g_pmax[pb + 1] = mx1; g_pmin[pb + 1] = mn1;
            }
        }
    }
    __syncthreads();
    for (int c = tid; c < 128; c += 256) {
        atomicAdd(&g_sum[n0 + c], (double)ss[c]);
        atomicAdd(&g_sumsq[n0 + c], (double)sq[c]);
    }
}

// ---------------- pooled-raw -> BN + relu -> outputs ----------------
__global__ void pool_bn_out(int S, int KG, int C, float* __restrict__ out,
                            float* __restrict__ outT) {
    int total = BB * S * C;
    int stride = gridDim.x * blockDim.x;
    for (int i = blockIdx.x * blockDim.x + threadIdx.x; i < total; i += stride) {
        int c = i % C;
        int s = (i / C) % S;
        int b = i / (C * S);
        size_t base = ((size_t)(b * S + s) * KG) * C + c;
        float mx = g_pmax[base], mn = g_pmin[base];
        for (int q = 1; q < KG; q++) {
            mx = fmaxf(mx, g_pmax[base + (size_t)q * C]);
            mn = fminf(mn, g_pmin[base + (size_t)q * C]);
        }
        float sc = g_scale[c];
        float raw = (sc >= 0.f) ? mx : mn;
        float r = fmaxf(raw * sc + g_shift[c], 0.f);
        out[(size_t)b * C * S + (size_t)c * S + s] = r;
        if (outT) outT[(size_t)(b * S + s) * C + c] = r;
    }
}

// ---------------- SIMT GEMM (small shapes): fused BN-in + stats, opt. sa3 gather ----------------
template <int CIN, int COUT, int BM, int TN, int KC, bool IN_BN, bool GATHER3>
__global__ void __launch_bounds__(256)
gemm_k(const float* __restrict__ A, const float* __restrict__ W,
       const float* __restrict__ bias, float* __restrict__ out,
       const float* __restrict__ gxyz) {
    constexpr int COLT = COUT / TN;
    constexpr int ROWT = 256 / COLT;
    constexpr int TM = BM / ROWT;
    constexpr int LDA = KC + 1;
    extern __shared__ float sm[];
    float* As = sm;
    float* Ws = sm + BM * LDA;
    float* ss = Ws + KC * COUT;
    float* sq = ss + COUT;

    int tid = threadIdx.x;
    int ct = tid % COLT, rt = tid / COLT;
    size_t row0 = (size_t)blockIdx.x * BM;

    float acc[TM][TN];
#pragma unroll
    for (int i = 0; i < TM; i++)
#pragma unroll
        for (int j = 0; j < TN; j++) acc[i][j] = 0.f;

    for (int k0 = 0; k0 < CIN; k0 += KC) {
        int kc = (CIN - k0 < KC) ? (CIN - k0) : KC;
        __syncthreads();
        for (int e = tid; e < BM * kc; e += 256) {
            int r = e / kc, k = e - r * kc;
            size_t R = row0 + r;
            int c = k0 + k;
            float v;
            if (GATHER3) {
                // row R = b*128 + kk; feature c: <3 from l2xyz (B,3,128), else l2pt (B*128,256)
                int bb_ = (int)(R >> 7), kk = (int)(R & 127);
                v = (c < 3) ? gxyz[(size_t)bb_ * 384 + c * 128 + kk]
                            : A[R * 256 + (c - 3)];
            } else {
                v = A[R * CIN + c];
            }
            if (IN_BN) v = fmaxf(v * g_scale[c] + g_shift[c], 0.f);
            As[r * LDA + k] = v;
        }
        for (int e = tid; e < kc * COUT; e += 256)
            Ws[e] = W[(size_t)k0 * COUT + e];
        __syncthreads();
        for (int kk = 0; kk < kc; kk++) {
            float a[TM], ww[TN];
#pragma unroll
            for (int j = 0; j < TN; j++) ww[j] = Ws[kk * COUT + ct * TN + j];
#pragma unroll
            for (int i = 0; i < TM; i++) a[i] = As[(rt * TM + i) * LDA + kk];
#pragma unroll
            for (int i = 0; i < TM; i++)
#pragma unroll
                for (int j = 0; j < TN; j++) acc[i][j] += a[i] * ww[j];
        }
    }

    for (int c = tid; c < COUT; c += 256) { ss[c] = 0.f; sq[c] = 0.f; }
    __syncthreads();

    float bb[TN];
#pragma unroll
    for (int j = 0; j < TN; j++) bb[j] = bias[ct * TN + j];

    float sl[TN], ql[TN];
#pragma unroll
    for (int j = 0; j < TN; j++) { sl[j] = 0.f; ql[j] = 0.f; }
#pragma unroll
    for (int i = 0; i < TM; i++) {
        size_t r = row0 + rt * TM + i;
#pragma unroll
        for (int j = 0; j < TN; j++) {
            float v = acc[i][j] + bb[j];
            out[r * COUT + ct * TN + j] = v;
            sl[j] += v;
            ql[j] += v * v;
        }
    }
#pragma unroll
    for (int j = 0; j < TN; j++) {
        atomicAdd(&ss[ct * TN + j], sl[j]);
        atomicAdd(&sq[ct * TN + j], ql[j]);
    }
    __syncthreads();
    for (int c = tid; c < COUT; c += 256) {
        atomicAdd(&g_sum[c], (double)ss[c]);
        atomicAdd(&g_sumsq[c], (double)sq[c]);
    }
}

// ---------------- BN finalize (also re-zeros accumulators for next use) ----------------
__global__ void bn_finalize_kernel(int C, double invcnt, const float* __restrict__ gamma,
                                   const float* __restrict__ beta) {
    int c = threadIdx.x;
    if (c < C) {
        double m = g_sum[c] * invcnt;
        double var = g_sumsq[c] * invcnt - m * m;
        float s = gamma[c] * rsqrtf((float)var + 1e-5f);
        g_scale[c] = s;
        g_shift[c] = beta[c] - (float)m * s;
    }
    g_sum[c] = 0.0;
    g_sumsq[c] = 0.0;
}

// ---------------- maxpool over K with fused BN+relu (sa3) + l3xyz zeroing ----------------
__global__ void maxpool_bn_kernel(const float* __restrict__ x, int S, int K, int C,
                                  float* __restrict__ out, float* __restrict__ outT,
                                  float* __restrict__ zp, int zn) {
    if (zp && blockIdx.x == 0 && threadIdx.x < zn) zp[threadIdx.x] = 0.f;
    int total = BB * S * C;
    int stride = gridDim.x * blockDim.x;
    for (int i = blockIdx.x * blockDim.x + threadIdx.x; i < total; i += stride) {
        int c = i % C;
        int s = (i / C) % S;
        int b = i / (C * S);
        const float* p = x + ((size_t)(b * S + s) * K) * C + c;
        float mx = p[0], mn = p[0];
        for (int k = 1; k < K; k++) {
            float v = p[(size_t)k * C];
            mx = fmaxf(mx, v);
            mn = fminf(mn, v);
        }
        float sc = g_scale[c];
        float raw = (sc >= 0.f) ? mx : mn;
        float r = fmaxf(raw * sc + g_shift[c], 0.f);
        out[(size_t)b * C * S + (size_t)c * S + s] = r;
        if (outT) outT[(size_t)(b * S + s) * C + c] = r;
    }
}

// ---------------- orchestration ----------------
extern "C" void kernel_launch(void* const* d_in, const int* in_sizes, int n_in,
                              void* d_out, int out_size) {
    (void)in_sizes; (void)n_in; (void)out_size;
    const float* l0_xyz = (const float*)d_in[0];
    const float* l0_pts = (const float*)d_in[1];
    float* out = (float*)d_out;

    float* o_l1xyz = out;                 // 16*3*256   = 12288
    float* o_l1pts = out + 12288;         // 16*128*256 = 524288
    float* o_l2xyz = out + 536576;        // 16*3*128   = 6144
    float* o_l2pts = out + 542720;        // 16*256*128 = 524288
    float* o_l3xyz = out + 1067008;       // 16*3*1     = 48
    float* o_x     = out + 1067056;       // 16*512     = 8192

    float *bufA, *bufB, *nxyz, *l1pt, *l2pt;
    int *gi;
    __nv_bfloat16 *whi, *wlo;
    cudaGetSymbolAddress((void**)&bufA, g_bufA);
    cudaGetSymbolAddress((void**)&bufB, g_bufB);
    cudaGetSymbolAddress((void**)&nxyz, g_newxyz);
    cudaGetSymbolAddress((void**)&l1pt, g_l1pt);
    cudaGetSymbolAddress((void**)&l2pt, g_l2pt);
    cudaGetSymbolAddress((void**)&gi, g_gi);
    cudaGetSymbolAddress((void**)&whi, g_whi);
    cudaGetSymbolAddress((void**)&wlo, g_wlo);

    // fps smem: 3*n floats + 64 u32
    constexpr int FPS1_SM = 3 * 4096 * 4 + 256;   // 49408
    constexpr int FPS2_SM = 3 * 256 * 4 + 256;    // 3328
    cudaFuncSetAttribute((const void*)fps_fast<8>, cudaFuncAttributeMaxDynamicSharedMemorySize, FPS1_SM);
    constexpr int HSM = 4 * 128 * 72 * 2;  // 73728 bytes
    cudaFuncSetAttribute((const void*)hm_gemm<64, 128, true, true, false>,
                         cudaFuncAttributeMaxDynamicSharedMemorySize, HSM);
    cudaFuncSetAttribute((const void*)hm_gemm<131, 128, false, false, true>,
                         cudaFuncAttributeMaxDynamicSharedMemorySize, HSM);
    cudaFuncSetAttribute((const void*)hm_gemm<128, 256, true, true, false>,
                         cudaFuncAttributeMaxDynamicSharedMemorySize, HSM);

    // ================= SA1 : N=4096 -> S=256, K=32 =================
    fps_fast<8><<<16, 512, FPS1_SM>>>(l0_xyz, 4096, 256, nxyz, o_l1xyz);
    ballquery_kernel<<<(16 * 256) / 8, 256>>>(l0_xyz, nxyz, 4096, 256, 32, 0.04f, gi);

    gather_gemm1<<<512, 256>>>(l0_xyz, l0_pts, gi, nxyz,
                               (const float*)d_in[2], (const float*)d_in[3], bufB);
    bn_finalize_kernel<<<1, 512>>>(64, 1.0 / 131072.0, (const float*)d_in[4], (const float*)d_in[5]);

    prep_w<<<32, 256>>>((const float*)d_in[6], 64, 128, 64, whi, wlo);
    hm_gemm<64, 128, true, true, false><<<dim3(1024, 1), 256, HSM>>>(
        bufB, whi, wlo, (const float*)d_in[7], nullptr, nullptr, nullptr, nullptr);
    bn_finalize_kernel<<<1, 512>>>(128, 1.0 / 131072.0, (const float*)d_in[8], (const float*)d_in[9]);
    pool_bn_out<<<2048, 256>>>(256, 1, 128, o_l1pts, l1pt);

    // ================= SA2 : N=256 -> S=128, K=64 =================
    fps_fast<1><<<16, 256, FPS2_SM>>>(o_l1xyz, 256, 128, nxyz, o_l2xyz);
    ballquery_kernel<<<(16 * 128) / 8, 256>>>(o_l1xyz, nxyz, 256, 128, 64, 0.0625f, gi);

    prep_w<<<96, 256>>>((const float*)d_in[10], 131, 128, 192, whi, wlo);
    hm_gemm<131, 128, false, false, true><<<dim3(1024, 1), 256, HSM>>>(
        l1pt, whi, wlo, (const float*)d_in[11], bufB, gi, o_l1xyz, nxyz);
    bn_finalize_kernel<<<1, 512>>>(128, 1.0 / 131072.0, (const float*)d_in[12], (const float*)d_in[13]);

    prep_w<<<128, 256>>>((const float*)d_in[14], 128, 256, 128, whi, wlo);
    hm_gemm<128, 256, true, true, false><<<dim3(1024, 2), 256, HSM>>>(
        bufB, whi, wlo, (const float*)d_in[15], nullptr, nullptr, nullptr, nullptr);
    bn_finalize_kernel<<<1, 512>>>(256, 1.0 / 131072.0, (const float*)d_in[16], (const float*)d_in[17]);
    pool_bn_out<<<2048, 256>>>(128, 2, 256, o_l2pts, l2pt);

    // ================= SA3 : group_all, K=128 (gather fused into GEMM) =================
    gemm_k<259, 256, 16, 4, 16, false, true><<<2048 / 16, 256, 19520>>>(
        l2pt, (const float*)d_in[18], (const float*)d_in[19], bufB, o_l2xyz);
    bn_finalize_kernel<<<1, 512>>>(256, 1.0 / 2048.0, (const float*)d_in[20], (const float*)d_in[21]);

    gemm_k<256, 512, 16, 8, 16, true, false><<<2048 / 16, 256, 37952>>>(
        bufB, (const float*)d_in[22], (const float*)d_in[23], bufA, nullptr);
    bn_finalize_kernel<<<1, 512>>>(512, 1.0 / 2048.0, (const float*)d_in[24], (const float*)d_in[25]);

    maxpool_bn_kernel<<<32, 256>>>(bufA, 1, 128, 512, o_x, nullptr, o_l3xyz, 48);
}

// round 7
// speedup vs baseline: 2.3061x; 1.0942x over previous
#include <cuda_runtime.h>
#include <cuda_bf16.h>
#include <cstdint>
#include <cstddef>

// ---------------- problem constants ----------------
#define BB 16
#define N0 4096

// scratch (device globals; allocation-free per harness rules)
__device__ float  g_bufB[16777216];           // 64 MB (max: 131072x128)
__device__ float  g_bufA[8388608];            // 32 MB (sa3 scratch)
__device__ float  g_newxyz[BB * 256 * 3];
__device__ int    g_gi[131072];
__device__ __nv_bfloat16 g_l1hi[786432];      // l1 feats hi, (b*256+s)*192 + (c+3); pads stay 0
__device__ __nv_bfloat16 g_l1lo[786432];      // l1 feats lo
__device__ float  g_l2pt[BB * 128 * 256];     // l2 points, (b,s,c), post-BN
__device__ double g_sum[512];
__device__ double g_sumsq[512];
__device__ float  g_scale[512];
__device__ float  g_shift[512];
__device__ __nv_bfloat16 g_whi[65536];
__device__ __nv_bfloat16 g_wlo[65536];
__device__ float  g_pmax[1048576];            // pooled-raw max per 32-row block
__device__ float  g_pmin[1048576];            // pooled-raw min per 32-row block

// ---------------- bf16 pack helpers ----------------
__device__ __forceinline__ uint32_t pack_bf16x2(float lo, float hi) {
    uint32_t r;
    asm("cvt.rn.bf16x2.f32 %0, %1, %2;" : "=r"(r) : "f"(hi), "f"(lo));
    return r;
}
__device__ __forceinline__ float bf_lo(uint32_t p) { return __uint_as_float(p << 16); }
__device__ __forceinline__ float bf_hi(uint32_t p) { return __uint_as_float(p & 0xffff0000u); }

// ---------------- FPS: register dist + redux argmax ----------------
template <int NPT>
__global__ void fps_fast(const float* __restrict__ xyz, int n, int npoint,
                         float* __restrict__ newxyz, float* __restrict__ outxyz) {
    extern __shared__ float sm[];
    float* sx = sm;
    float* sy = sm + n;
    float* sz = sm + 2 * n;
    uint32_t* pval = reinterpret_cast<uint32_t*>(sm + 3 * n);
    uint32_t* pidx = pval + 32;
    __shared__ int sfar;

    int b = blockIdx.x, tid = threadIdx.x, bt = blockDim.x;
    int wid = tid >> 5, lane = tid & 31;
    int nwarps = bt >> 5;
    const float* base = xyz + (size_t)b * 3 * n;
    for (int i = tid; i < n; i += bt) {
        sx[i] = base[i];
        sy[i] = base[n + i];
        sz[i] = base[2 * n + i];
    }
    __syncthreads();

    float px[NPT], py[NPT], pz[NPT], pd[NPT];
#pragma unroll
    for (int j = 0; j < NPT; j++) {
        int i = tid + j * bt;
        px[j] = sx[i]; py[j] = sy[i]; pz[j] = sz[i];
        pd[j] = 1e10f;
    }

    int far = 0;
    for (int t = 0; t < npoint; t++) {
        float cx = sx[far], cy = sy[far], cz = sz[far];
        if (tid == 0) {
            float* nw = &newxyz[(b * npoint + t) * 3];
            nw[0] = cx; nw[1] = cy; nw[2] = cz;
            outxyz[(size_t)b * 3 * npoint + t] = cx;
            outxyz[(size_t)b * 3 * npoint + npoint + t] = cy;
            outxyz[(size_t)b * 3 * npoint + 2 * npoint + t] = cz;
        }
        uint32_t bv; int bi;
#pragma unroll
        for (int j = 0; j < NPT; j++) {
            float dx = __fsub_rn(px[j], cx);
            float dy = __fsub_rn(py[j], cy);
            float dz = __fsub_rn(pz[j], cz);
            float d = __fadd_rn(__fadd_rn(__fmul_rn(dx, dx), __fmul_rn(dy, dy)), __fmul_rn(dz, dz));
            float dd = fminf(pd[j], d);
            pd[j] = dd;
            uint32_t bits = __float_as_uint(dd);
            if (j == 0) { bv = bits; bi = tid; }
            else if (bits > bv) { bv = bits; bi = tid + j * bt; }
        }
        uint32_t mval = __reduce_max_sync(0xffffffffu, bv);
        uint32_t cand = (bv == mval) ? (uint32_t)bi : 0xffffffffu;
        uint32_t midx = __reduce_min_sync(0xffffffffu, cand);
        if (lane == 0) { pval[wid] = mval; pidx[wid] = midx; }
        __syncthreads();
        if (wid == 0) {
            uint32_t v = (lane < nwarps) ? pval[lane] : 0u;
            uint32_t ii = (lane < nwarps) ? pidx[lane] : 0xffffffffu;
            uint32_t m = __reduce_max_sync(0xffffffffu, v);
            uint32_t c = (v == m) ? ii : 0xffffffffu;
            uint32_t mi = __reduce_min_sync(0xffffffffu, c);
            if (lane == 0) sfar = (int)mi;
        }
        __syncthreads();
        far = sfar;
    }
}

// ---------------- ball query: one warp per (b,s) ----------------
__global__ void ballquery_kernel(const float* __restrict__ xyz, const float* __restrict__ newxyz,
                                 int n, int S, int K, float r2, int* __restrict__ gi) {
    int gw = (blockIdx.x * blockDim.x + threadIdx.x) >> 5;
    int lane = threadIdx.x & 31;
    if (gw >= BB * S) return;
    int b = gw / S, s = gw % S;
    const float* nw = &newxyz[(b * S + s) * 3];
    float nx = nw[0], ny = nw[1], nz = nw[2];
    float nsq = __fadd_rn(__fadd_rn(__fmul_rn(nx, nx), __fmul_rn(ny, ny)), __fmul_rn(nz, nz));
    const float* px = xyz + (size_t)b * 3 * n;
    int* g = gi + (size_t)(b * S + s) * K;
    int cnt = 0, first = -1;
    for (int base = 0; base < n && cnt < K; base += 32) {
        int i = base + lane;
        float x = px[i], y = px[n + i], z = px[2 * n + i];
        float psq = __fadd_rn(__fadd_rn(__fmul_rn(x, x), __fmul_rn(y, y)), __fmul_rn(z, z));
        float dot = __fadd_rn(__fadd_rn(__fmul_rn(nx, x), __fmul_rn(ny, y)), __fmul_rn(nz, z));
        float sqr = __fsub_rn(__fadd_rn(nsq, psq), __fmul_rn(2.0f, dot));
        bool ok = !(sqr > r2);
        unsigned m = __ballot_sync(0xffffffffu, ok);
        if (first < 0 && m) first = base + __ffs(m) - 1;
        int pos = cnt + __popc(m & ((1u << lane) - 1u));
        if (ok && pos < K) g[pos] = i;
        cnt += __popc(m);
    }
    if (cnt > K) cnt = K;
    for (int p = cnt + lane; p < K; p += 32) g[p] = first;
}

// ---------------- fused gather + GEMM1 (6 -> 64) + stats ----------------
__global__ void __launch_bounds__(256)
gather_gemm1(const float* __restrict__ xyz, const float* __restrict__ pts,
             const int* __restrict__ gi, const float* __restrict__ newxyz,
             const float* __restrict__ W, const float* __restrict__ bias,
             float* __restrict__ out) {
    __shared__ float Ws[6 * 64];
    __shared__ float bs[64];
    __shared__ float ss[64], sq[64];
    int tid = threadIdx.x;
    for (int e = tid; e < 384; e += 256) Ws[e] = W[e];
    if (tid < 64) { bs[tid] = bias[tid]; ss[tid] = 0.f; sq[tid] = 0.f; }
    __syncthreads();

    int row = blockIdx.x * 256 + tid;
    int b = row >> 13, s = (row >> 5) & 255;
    int idx = gi[row];
    const float* px = xyz + (size_t)b * 3 * N0;
    const float* pp = pts + (size_t)b * 3 * N0;
    const float* nw = &newxyz[(b * 256 + s) * 3];
    float in[6];
    in[0] = __fsub_rn(px[idx], nw[0]);
    in[1] = __fsub_rn(px[N0 + idx], nw[1]);
    in[2] = __fsub_rn(px[2 * N0 + idx], nw[2]);
    in[3] = pp[idx];
    in[4] = pp[N0 + idx];
    in[5] = pp[2 * N0 + idx];

    const float4* W4 = reinterpret_cast<const float4*>(Ws);
    const float4* b4 = reinterpret_cast<const float4*>(bs);
    float4 v[16];
#pragma unroll
    for (int j = 0; j < 16; j++) v[j] = b4[j];
#pragma unroll
    for (int k = 0; k < 6; k++) {
        float a = in[k];
#pragma unroll
        for (int j = 0; j < 16; j++) {
            float4 w = W4[k * 16 + j];
            v[j].x += a * w.x; v[j].y += a * w.y;
            v[j].z += a * w.z; v[j].w += a * w.w;
        }
    }
    float4* o4 = reinterpret_cast<float4*>(out + (size_t)row * 64);
#pragma unroll
    for (int j = 0; j < 16; j++) o4[j] = v[j];

    int lane = tid & 31;
#pragma unroll
    for (int j = 0; j < 16; j++) {
        float c[4] = {v[j].x, v[j].y, v[j].z, v[j].w};
#pragma unroll
        for (int q = 0; q < 4; q++) {
            float sv = c[q], qv = c[q] * c[q];
#pragma unroll
            for (int o = 16; o; o >>= 1) {
                sv += __shfl_xor_sync(0xffffffffu, sv, o);
                qv += __shfl_xor_sync(0xffffffffu, qv, o);
            }
            if (lane == 0) {
                atomicAdd(&ss[j * 4 + q], sv);
                atomicAdd(&sq[j * 4 + q], qv);
            }
        }
    }
    __syncthreads();
    if (tid < 64) {
        atomicAdd(&g_sum[tid], (double)ss[tid]);
        atomicAdd(&g_sumsq[tid], (double)sq[tid]);
    }
}

// ---------------- W prep: fp32 [CIN][COUT] -> bf16 hi/lo transposed [COUT][KPAD] ----------------
__global__ void prep_w(const float* __restrict__ W, int CIN, int COUT, int KPAD,
                       __nv_bfloat16* __restrict__ hi, __nv_bfloat16* __restrict__ lo) {
    int i = blockIdx.x * blockDim.x + threadIdx.x;
    if (i >= COUT * KPAD) return;
    int n = i / KPAD, k = i - n * KPAD;
    float v = (k < CIN) ? W[(size_t)k * COUT + n] : 0.f;
    __nv_bfloat16 h = __float2bfloat16_rn(v);
    float r = v - __bfloat162float(h);
    hi[i] = h;
    lo[i] = __float2bfloat16_rn(r);
}

// ---------------- mma.sync helper ----------------
__device__ __forceinline__ void mma16816(float* c, const uint32_t* a, uint32_t b0, uint32_t b1) {
    asm volatile(
        "mma.sync.aligned.m16n8k16.row.col.f32.bf16.bf16.f32 "
        "{%0,%1,%2,%3}, {%4,%5,%6,%7}, {%8,%9}, {%0,%1,%2,%3};"
        : "+f"(c[0]), "+f"(c[1]), "+f"(c[2]), "+f"(c[3])
        : "r"(a[0]), "r"(a[1]), "r"(a[2]), "r"(a[3]), "r"(b0), "r"(b1));
}

// ---------------- HMMA bf16 split GEMM ----------------
// Block tile: 128 rows x COUT (=NT*16) cols, K chunk 64, 8 warps 4(m) x 2(n):
// warp owns 32 rows x NT*8 cols. Split: hi*hi + hi*lo + lo*hi, fp32 accum.
template <int CIN, int COUT, int NT, bool IN_BN, bool POOL, bool GATHER2>
__global__ void __launch_bounds__(256)
hm_gemm(const float* __restrict__ A, const __nv_bfloat16* __restrict__ Whi,
        const __nv_bfloat16* __restrict__ Wlo, const float* __restrict__ bias,
        float* __restrict__ out, const int* __restrict__ gi,
        const float* __restrict__ gxyz, const float* __restrict__ gnew) {
    constexpr int KPAD = (CIN + 63) & ~63;
    constexpr int NCH = KPAD / 64;
    constexpr int LD = 72;
    static_assert(COUT == NT * 16, "tile covers full COUT");
    extern __shared__ __nv_bfloat16 sh[];
    __nv_bfloat16* Ahi = sh;
    __nv_bfloat16* Alo = Ahi + 128 * LD;
    __nv_bfloat16* Bhi = Alo + 128 * LD;
    __nv_bfloat16* Blo = Bhi + COUT * LD;

    int tid = threadIdx.x;
    int lane = tid & 31, w = tid >> 5;
    int mw = w >> 1, nw = w & 1;
    int g = lane >> 2, tg = lane & 3;
    size_t row0 = (size_t)blockIdx.x * 128;

    float acc[2][NT][4];
#pragma unroll
    for (int i = 0; i < 2; i++)
#pragma unroll
        for (int j = 0; j < NT; j++)
#pragma unroll
            for (int q = 0; q < 4; q++) acc[i][j][q] = 0.f;

    int kp = tid & 15;  // loop bounds are multiples of 256 -> kp constant per thread
    for (int ch = 0; ch < NCH; ch++) {
        int gk0 = ch * 64 + kp * 4;
        __syncthreads();
        // ---- A fill: 4 elements per thread-iteration ----
        float4 s4, t4;
        if (IN_BN) {
            s4 = *reinterpret_cast<const float4*>(&g_scale[gk0]);
            t4 = *reinterpret_cast<const float4*>(&g_shift[gk0]);
        }
        for (int e = tid; e < 128 * 16; e += 256) {
            int r = e >> 4;
            if (GATHER2) {
                size_t R = row0 + r;
                int bb_ = (int)(R >> 13);
                int idx = gi[R];
                size_t rowoff = ((size_t)(bb_ * 256 + idx)) * 192;
                if (gk0 >= 4) {
                    uint2 hv = *reinterpret_cast<const uint2*>(g_l1hi + rowoff + gk0);
                    uint2 lv = *reinterpret_cast<const uint2*>(g_l1lo + rowoff + gk0);
                    *reinterpret_cast<uint2*>(&Ahi[r * LD + kp * 4]) = hv;
                    *reinterpret_cast<uint2*>(&Alo[r * LD + kp * 4]) = lv;
                } else {
                    // gk0 == 0: channels 0..2 = xyz - center, channel 3 = feature 0
                    size_t sidx = R >> 6;
#pragma unroll
                    for (int c = 0; c < 3; c++) {
                        float v = __fsub_rn(gxyz[(size_t)bb_ * 768 + c * 256 + idx],
                                            gnew[sidx * 3 + c]);
                        __nv_bfloat16 h = __float2bfloat16_rn(v);
                        Ahi[r * LD + c] = h;
                        Alo[r * LD + c] = __float2bfloat16_rn(v - __bfloat162float(h));
                    }
                    Ahi[r * LD + 3] = g_l1hi[rowoff + 3];
                    Alo[r * LD + 3] = g_l1lo[rowoff + 3];
                }
            } else {
                float4 v = *reinterpret_cast<const float4*>(&A[(row0 + r) * CIN + gk0]);
                if (IN_BN) {
                    v.x = fmaxf(v.x * s4.x + t4.x, 0.f);
                    v.y = fmaxf(v.y * s4.y + t4.y, 0.f);
                    v.z = fmaxf(v.z * s4.z + t4.z, 0.f);
                    v.w = fmaxf(v.w * s4.w + t4.w, 0.f);
                }
                uint32_t h01 = pack_bf16x2(v.x, v.y);
                uint32_t h23 = pack_bf16x2(v.z, v.w);
                float r0 = v.x - bf_lo(h01), r1 = v.y - bf_hi(h01);
                float r2 = v.z - bf_lo(h23), r3 = v.w - bf_hi(h23);
                uint32_t l01 = pack_bf16x2(r0, r1);
                uint32_t l23 = pack_bf16x2(r2, r3);
                *reinterpret_cast<uint2*>(&Ahi[r * LD + kp * 4]) = make_uint2(h01, h23);
                *reinterpret_cast<uint2*>(&Alo[r * LD + kp * 4]) = make_uint2(l01, l23);
            }
        }
        // ---- B fill: pre-split transposed W, uint2 copies ----
        for (int e = tid; e < COUT * 16; e += 256) {
            int n = e >> 4;
            size_t gidx = (size_t)n * KPAD + gk0;
            *reinterpret_cast<uint2*>(&Bhi[n * LD + kp * 4]) =
                *reinterpret_cast<const uint2*>(Whi + gidx);
            *reinterpret_cast<uint2*>(&Blo[n * LD + kp * 4]) =
                *reinterpret_cast<const uint2*>(Wlo + gidx);
        }
        __syncthreads();

#pragma unroll
        for (int ks = 0; ks < 4; ks++) {
            int k0 = ks * 16;
            uint32_t ah[2][4], al[2][4];
#pragma unroll
            for (int mt = 0; mt < 2; mt++) {
                int rm = mw * 32 + mt * 16;
                ah[mt][0] = *reinterpret_cast<uint32_t*>(&Ahi[(rm + g) * LD + k0 + tg * 2]);
                ah[mt][1] = *reinterpret_cast<uint32_t*>(&Ahi[(rm + g + 8) * LD + k0 + tg * 2]);
                ah[mt][2] = *reinterpret_cast<uint32_t*>(&Ahi[(rm + g) * LD + k0 + tg * 2 + 8]);
                ah[mt][3] = *reinterpret_cast<uint32_t*>(&Ahi[(rm + g + 8) * LD + k0 + tg * 2 + 8]);
                al[mt][0] = *reinterpret_cast<uint32_t*>(&Alo[(rm + g) * LD + k0 + tg * 2]);
                al[mt][1] = *reinterpret_cast<uint32_t*>(&Alo[(rm + g + 8) * LD + k0 + tg * 2]);
                al[mt][2] = *reinterpret_cast<uint32_t*>(&Alo[(rm + g) * LD + k0 + tg * 2 + 8]);
                al[mt][3] = *reinterpret_cast<uint32_t*>(&Alo[(rm + g + 8) * LD + k0 + tg * 2 + 8]);
            }
#pragma unroll
            for (int nt = 0; nt < NT; nt++) {
                int cn = nw * (NT * 8) + nt * 8 + g;
                uint32_t bh0 = *reinterpret_cast<uint32_t*>(&Bhi[cn * LD + k0 + tg * 2]);
                uint32_t bh1 = *reinterpret_cast<uint32_t*>(&Bhi[cn * LD + k0 + tg * 2 + 8]);
                uint32_t bl0 = *reinterpret_cast<uint32_t*>(&Blo[cn * LD + k0 + tg * 2]);
                uint32_t bl1 = *reinterpret_cast<uint32_t*>(&Blo[cn * LD + k0 + tg * 2 + 8]);
#pragma unroll
                for (int mt = 0; mt < 2; mt++) {
                    mma16816(acc[mt][nt], ah[mt], bh0, bh1);
                    mma16816(acc[mt][nt], ah[mt], bl0, bl1);
                    mma16816(acc[mt][nt], al[mt], bh0, bh1);
                }
            }
        }
    }
    __syncthreads();

    float* ss = reinterpret_cast<float*>(sh);
    float* sq = ss + COUT;
    for (int c = tid; c < COUT; c += 256) { ss[c] = 0.f; sq[c] = 0.f; }
    __syncthreads();

    int rb32 = (int)(row0 >> 5) + mw;
#pragma unroll
    for (int nt = 0; nt < NT; nt++) {
        int lc = nw * (NT * 8) + nt * 8 + tg * 2;
        float b0 = bias[lc], b1 = bias[lc + 1];
        float s0 = 0.f, q0 = 0.f, s1 = 0.f, q1 = 0.f;
        float mx0 = -3.4e38f, mn0 = 3.4e38f, mx1 = -3.4e38f, mn1 = 3.4e38f;
#pragma unroll
        for (int mt = 0; mt < 2; mt++) {
            float v00 = acc[mt][nt][0] + b0, v01 = acc[mt][nt][1] + b1;
            float v10 = acc[mt][nt][2] + b0, v11 = acc[mt][nt][3] + b1;
            if (!POOL) {
                size_t r0 = row0 + mw * 32 + mt * 16 + g;
                *reinterpret_cast<float2*>(&out[r0 * COUT + lc]) = make_float2(v00, v01);
                *reinterpret_cast<float2*>(&out[(r0 + 8) * COUT + lc]) = make_float2(v10, v11);
            }
            s0 += v00 + v10; q0 += v00 * v00 + v10 * v10;
            s1 += v01 + v11; q1 += v01 * v01 + v11 * v11;
            mx0 = fmaxf(mx0, fmaxf(v00, v10)); mn0 = fminf(mn0, fminf(v00, v10));
            mx1 = fmaxf(mx1, fmaxf(v01, v11)); mn1 = fminf(mn1, fminf(v01, v11));
        }
#pragma unroll
        for (int o = 4; o < 32; o <<= 1) {
            s0 += __shfl_xor_sync(0xffffffffu, s0, o);
            q0 += __shfl_xor_sync(0xffffffffu, q0, o);
            s1 += __shfl_xor_sync(0xffffffffu, s1, o);
            q1 += __shfl_xor_sync(0xffffffffu, q1, o);
            if (POOL) {
                mx0 = fmaxf(mx0, __shfl_xor_sync(0xffffffffu, mx0, o));
                mn0 = fminf(mn0, __shfl_xor_sync(0xffffffffu, mn0, o));
                mx1 = fmaxf(mx1, __shfl_xor_sync(0xffffffffu, mx1, o));
                mn1 = fminf(mn1, __shfl_xor_sync(0xffffffffu, mn1, o));
            }
        }
        if (g == 0) {
            atomicAdd(&ss[lc], s0);
            atomicAdd(&sq[lc], q0);
            atomicAdd(&ss[lc + 1], s1);
            atomicAdd(&sq[lc + 1], q1);
            if (POOL) {
                size_t pb = (size_t)rb32 * COUT + lc;
                g_pmax[pb] = mx0; g_pmin[pb] = mn0;
                g_pmax[pb + 1] = mx1; g_pmin[pb + 1] = mn1;
            }
        }
    }
    __syncthreads();
    for (int c = tid; c < COUT; c += 256) {
        atomicAdd(&g_sum[c], (double)ss[c]);
        atomicAdd(&g_sumsq[c], (double)sq[c]);
    }
}

// ---------------- pooled-raw -> BN + relu -> outputs (fp32 and/or bf16 hi/lo) ----------------
__global__ void pool_bn_out(int S, int KG, int C, float* __restrict__ out,
                            float* __restrict__ outT,
                            __nv_bfloat16* __restrict__ ohi, __nv_bfloat16* __restrict__ olo) {
    int total = BB * S * C;
    int stride = gridDim.x * blockDim.x;
    for (int i = blockIdx.x * blockDim.x + threadIdx.x; i < total; i += stride) {
        int c = i % C;
        int s = (i / C) % S;
        int b = i / (C * S);
        size_t base = ((size_t)(b * S + s) * KG) * C + c;
        float mx = g_pmax[base], mn = g_pmin[base];
        for (int q = 1; q < KG; q++) {
            mx = fmaxf(mx, g_pmax[base + (size_t)q * C]);
            mn = fminf(mn, g_pmin[base + (size_t)q * C]);
        }
        float sc = g_scale[c];
        float raw = (sc >= 0.f) ? mx : mn;
        float r = fmaxf(raw * sc + g_shift[c], 0.f);
        out[(size_t)b * C * S + (size_t)c * S + s] = r;
        if (outT) outT[(size_t)(b * S + s) * C + c] = r;
        if (ohi) {
            __nv_bfloat16 h = __float2bfloat16_rn(r);
            size_t o = (size_t)(b * S + s) * 192 + c + 3;
            ohi[o] = h;
            olo[o] = __float2bfloat16_rn(r - __bfloat162float(h));
        }
    }
}

// ---------------- SIMT GEMM (small shapes): fused BN-in + stats, opt. sa3 gather ----------------
template <int CIN, int COUT, int BM, int TN, int KC, bool IN_BN, bool GATHER3>
__global__ void __launch_bounds__(256)
gemm_k(const float* __restrict__ A, const float* __restrict__ W,
       const float* __restrict__ bias, float* __restrict__ out,
       const float* __restrict__ gxyz) {
    constexpr int COLT = COUT / TN;
    constexpr int ROWT = 256 / COLT;
    constexpr int TM = BM / ROWT;
    constexpr int LDA = KC + 1;
    extern __shared__ float sm[];
    float* As = sm;
    float* Ws = sm + BM * LDA;
    float* ss = Ws + KC * COUT;
    float* sq = ss + COUT;

    int tid = threadIdx.x;
    int ct = tid % COLT, rt = tid / COLT;
    size_t row0 = (size_t)blockIdx.x * BM;

    float acc[TM][TN];
#pragma unroll
    for (int i = 0; i < TM; i++)
#pragma unroll
        for (int j = 0; j < TN; j++) acc[i][j] = 0.f;

    for (int k0 = 0; k0 < CIN; k0 += KC) {
        int kc = (CIN - k0 < KC) ? (CIN - k0) : KC;
        __syncthreads();
        for (int e = tid; e < BM * kc; e += 256) {
            int r = e / kc, k = e - r * kc;
            size_t R = row0 + r;
            int c = k0 + k;
            float v;
            if (GATHER3) {
                int bb_ = (int)(R >> 7), kk = (int)(R & 127);
                v = (c < 3) ? gxyz[(size_t)bb_ * 384 + c * 128 + kk]
                            : A[R * 256 + (c - 3)];
            } else {
                v = A[R * CIN + c];
            }
            if (IN_BN) v = fmaxf(v * g_scale[c] + g_shift[c], 0.f);
            As[r * LDA + k] = v;
        }
        for (int e = tid; e < kc * COUT; e += 256)
            Ws[e] = W[(size_t)k0 * COUT + e];
        __syncthreads();
        for (int kk = 0; kk < kc; kk++) {
            float a[TM], ww[TN];
#pragma unroll
            for (int j = 0; j < TN; j++) ww[j] = Ws[kk * COUT + ct * TN + j];
#pragma unroll
            for (int i = 0; i < TM; i++) a[i] = As[(rt * TM + i) * LDA + kk];
#pragma unroll
            for (int i = 0; i < TM; i++)
#pragma unroll
                for (int j = 0; j < TN; j++) acc[i][j] += a[i] * ww[j];
        }
    }

    for (int c = tid; c < COUT; c += 256) { ss[c] = 0.f; sq[c] = 0.f; }
    __syncthreads();

    float bb[TN];
#pragma unroll
    for (int j = 0; j < TN; j++) bb[j] = bias[ct * TN + j];

    float sl[TN], ql[TN];
#pragma unroll
    for (int j = 0; j < TN; j++) { sl[j] = 0.f; ql[j] = 0.f; }
#pragma unroll
    for (int i = 0; i < TM; i++) {
        size_t r = row0 + rt * TM + i;
#pragma unroll
        for (int j = 0; j < TN; j++) {
            float v = acc[i][j] + bb[j];
            out[r * COUT + ct * TN + j] = v;
            sl[j] += v;
            ql[j] += v * v;
        }
    }
#pragma unroll
    for (int j = 0; j < TN; j++) {
        atomicAdd(&ss[ct * TN + j], sl[j]);
        atomicAdd(&sq[ct * TN + j], ql[j]);
    }
    __syncthreads();
    for (int c = tid; c < COUT; c += 256) {
        atomicAdd(&g_sum[c], (double)ss[c]);
        atomicAdd(&g_sumsq[c], (double)sq[c]);
    }
}

// ---------------- BN finalize (also re-zeros accumulators for next use) ----------------
__global__ void bn_finalize_kernel(int C, double invcnt, const float* __restrict__ gamma,
                                   const float* __restrict__ beta) {
    int c = threadIdx.x;
    if (c < C) {
        double m = g_sum[c] * invcnt;
        double var = g_sumsq[c] * invcnt - m * m;
        float s = gamma[c] * rsqrtf((float)var + 1e-5f);
        g_scale[c] = s;
        g_shift[c] = beta[c] - (float)m * s;
    }
    g_sum[c] = 0.0;
    g_sumsq[c] = 0.0;
}

// ---------------- maxpool over K with fused BN+relu (sa3) + l3xyz zeroing ----------------
__global__ void maxpool_bn_kernel(const float* __restrict__ x, int S, int K, int C,
                                  float* __restrict__ out, float* __restrict__ outT,
                                  float* __restrict__ zp, int zn) {
    if (zp && blockIdx.x == 0 && threadIdx.x < zn) zp[threadIdx.x] = 0.f;
    int total = BB * S * C;
    int stride = gridDim.x * blockDim.x;
    for (int i = blockIdx.x * blockDim.x + threadIdx.x; i < total; i += stride) {
        int c = i % C;
        int s = (i / C) % S;
        int b = i / (C * S);
        const float* p = x + ((size_t)(b * S + s) * K) * C + c;
        float mx = p[0], mn = p[0];
        for (int k = 1; k < K; k++) {
            float v = p[(size_t)k * C];
            mx = fmaxf(mx, v);
            mn = fminf(mn, v);
        }
        float sc = g_scale[c];
        float raw = (sc >= 0.f) ? mx : mn;
        float r = fmaxf(raw * sc + g_shift[c], 0.f);
        out[(size_t)b * C * S + (size_t)c * S + s] = r;
        if (outT) outT[(size_t)(b * S + s) * C + c] = r;
    }
}

// ---------------- orchestration ----------------
extern "C" void kernel_launch(void* const* d_in, const int* in_sizes, int n_in,
                              void* d_out, int out_size) {
    (void)in_sizes; (void)n_in; (void)out_size;
    const float* l0_xyz = (const float*)d_in[0];
    const float* l0_pts = (const float*)d_in[1];
    float* out = (float*)d_out;

    float* o_l1xyz = out;                 // 16*3*256   = 12288
    float* o_l1pts = out + 12288;         // 16*128*256 = 524288
    float* o_l2xyz = out + 536576;        // 16*3*128   = 6144
    float* o_l2pts = out + 542720;        // 16*256*128 = 524288
    float* o_l3xyz = out + 1067008;       // 16*3*1     = 48
    float* o_x     = out + 1067056;       // 16*512     = 8192

    float *bufA, *bufB, *nxyz, *l2pt;
    int *gi;
    __nv_bfloat16 *whi, *wlo, *l1hi, *l1lo;
    cudaGetSymbolAddress((void**)&bufA, g_bufA);
    cudaGetSymbolAddress((void**)&bufB, g_bufB);
    cudaGetSymbolAddress((void**)&nxyz, g_newxyz);
    cudaGetSymbolAddress((void**)&l2pt, g_l2pt);
    cudaGetSymbolAddress((void**)&gi, g_gi);
    cudaGetSymbolAddress((void**)&whi, g_whi);
    cudaGetSymbolAddress((void**)&wlo, g_wlo);
    cudaGetSymbolAddress((void**)&l1hi, g_l1hi);
    cudaGetSymbolAddress((void**)&l1lo, g_l1lo);

    constexpr int FPS1_SM = 3 * 4096 * 4 + 256;
    constexpr int FPS2_SM = 3 * 256 * 4 + 256;
    cudaFuncSetAttribute((const void*)fps_fast<8>, cudaFuncAttributeMaxDynamicSharedMemorySize, FPS1_SM);
    constexpr int HSM8  = (2 * 128 * 72 + 2 * 128 * 72) * 2;   // 73728
    constexpr int HSM16 = (2 * 128 * 72 + 2 * 256 * 72) * 2;   // 110592
    cudaFuncSetAttribute((const void*)hm_gemm<64, 128, 8, true, true, false>,
                         cudaFuncAttributeMaxDynamicSharedMemorySize, HSM8);
    cudaFuncSetAttribute((const void*)hm_gemm<131, 128, 8, false, false, true>,
                         cudaFuncAttributeMaxDynamicSharedMemorySize, HSM8);
    cudaFuncSetAttribute((const void*)hm_gemm<128, 256, 16, true, true, false>,
                         cudaFuncAttributeMaxDynamicSharedMemorySize, HSM16);

    // ================= SA1 : N=4096 -> S=256, K=32 =================
    fps_fast<8><<<16, 512, FPS1_SM>>>(l0_xyz, 4096, 256, nxyz, o_l1xyz);
    ballquery_kernel<<<(16 * 256) / 8, 256>>>(l0_xyz, nxyz, 4096, 256, 32, 0.04f, gi);

    gather_gemm1<<<512, 256>>>(l0_xyz, l0_pts, gi, nxyz,
                               (const float*)d_in[2], (const float*)d_in[3], bufB);
    bn_finalize_kernel<<<1, 512>>>(64, 1.0 / 131072.0, (const float*)d_in[4], (const float*)d_in[5]);

    prep_w<<<32, 256>>>((const float*)d_in[6], 64, 128, 64, whi, wlo);
    hm_gemm<64, 128, 8, true, true, false><<<1024, 256, HSM8>>>(
        bufB, whi, wlo, (const float*)d_in[7], nullptr, nullptr, nullptr, nullptr);
    bn_finalize_kernel<<<1, 512>>>(128, 1.0 / 131072.0, (const float*)d_in[8], (const float*)d_in[9]);
    pool_bn_out<<<2048, 256>>>(256, 1, 128, o_l1pts, nullptr, l1hi, l1lo);

    // ================= SA2 : N=256 -> S=128, K=64 =================
    fps_fast<1><<<16, 256, FPS2_SM>>>(o_l1xyz, 256, 128, nxyz, o_l2xyz);
    ballquery_kernel<<<(16 * 128) / 8, 256>>>(o_l1xyz, nxyz, 256, 128, 64, 0.0625f, gi);

    prep_w<<<96, 256>>>((const float*)d_in[10], 131, 128, 192, whi, wlo);
    hm_gemm<131, 128, 8, false, false, true><<<1024, 256, HSM8>>>(
        nullptr, whi, wlo, (const float*)d_in[11], bufB, gi, o_l1xyz, nxyz);
    bn_finalize_kernel<<<1, 512>>>(128, 1.0 / 131072.0, (const float*)d_in[12], (const float*)d_in[13]);

    prep_w<<<128, 256>>>((const float*)d_in[14], 128, 256, 128, whi, wlo);
    hm_gemm<128, 256, 16, true, true, false><<<1024, 256, HSM16>>>(
        bufB, whi, wlo, (const float*)d_in[15], nullptr, nullptr, nullptr, nullptr);
    bn_finalize_kernel<<<1, 512>>>(256, 1.0 / 131072.0, (const float*)d_in[16], (const float*)d_in[17]);
    pool_bn_out<<<2048, 256>>>(128, 2, 256, o_l2pts, l2pt, nullptr, nullptr);

    // ================= SA3 : group_all, K=128 (gather fused into GEMM) =================
    gemm_k<259, 256, 16, 4, 16, false, true><<<2048 / 16, 256, 19520>>>(
        l2pt, (const float*)d_in[18], (const float*)d_in[19], bufB, o_l2xyz);
    bn_finalize_kernel<<<1, 512>>>(256, 1.0 / 2048.0, (const float*)d_in[20], (const float*)d_in[21]);

    gemm_k<256, 512, 16, 8, 16, true, false><<<2048 / 16, 256, 37952>>>(
        bufB, (const float*)d_in[22], (const float*)d_in[23], bufA, nullptr);
    bn_finalize_kernel<<<1, 512>>>(512, 1.0 / 2048.0, (const float*)d_in[24], (const float*)d_in[25]);

    maxpool_bn_kernel<<<32, 256>>>(bufA, 1, 128, 512, o_x, nullptr, o_l3xyz, 48);
}

// round 8
// speedup vs baseline: 2.6712x; 1.1583x over previous
#include <cuda_runtime.h>
#include <cuda_bf16.h>
#include <cstdint>
#include <cstddef>

// ---------------- problem constants ----------------
#define BB 16
#define N0 4096

// scratch (device globals; allocation-free per harness rules)
__device__ float  g_bufB[16777216];           // 64 MB (max: 131072x128)
__device__ float  g_newxyz[BB * 256 * 3];
__device__ int    g_gi[131072];
__device__ __nv_bfloat16 g_l1hi[786432];      // l1 feats hi, (b*256+s)*192 + (c+3); pads stay 0
__device__ __nv_bfloat16 g_l1lo[786432];
__device__ __nv_bfloat16 g_l2hi[655360];      // l2 row*(320): [0..2]=xyz, [3..258]=feats, pads 0
__device__ __nv_bfloat16 g_l2lo[655360];
__device__ double g_sum[512];
__device__ double g_sumsq[512];
__device__ float  g_scale[512];
__device__ float  g_shift[512];
__device__ __nv_bfloat16 g_whi[278528];       // all 5 layers, pre-split transposed
__device__ __nv_bfloat16 g_wlo[278528];
__device__ float  g_pmax[1048576];            // pooled-raw max per 32-row block
__device__ float  g_pmin[1048576];

// weight segment offsets in g_whi/g_wlo
#define WOFF_L1B 0        // 64->128,  KPAD 64,  128*64   = 8192
#define WOFF_L2A 8192     // 131->128, KPAD 192, 128*192  = 24576
#define WOFF_L2B 32768    // 128->256, KPAD 128, 256*128  = 32768
#define WOFF_L3A 65536    // 259->256, KPAD 320, 256*320  = 81920
#define WOFF_L3B 147456   // 256->512, KPAD 256, 512*256  = 131072

// ---------------- bf16 pack helpers ----------------
__device__ __forceinline__ uint32_t pack_bf16x2(float lo, float hi) {
    uint32_t r;
    asm("cvt.rn.bf16x2.f32 %0, %1, %2;" : "=r"(r) : "f"(hi), "f"(lo));
    return r;
}
__device__ __forceinline__ float bf_lo(uint32_t p) { return __uint_as_float(p << 16); }
__device__ __forceinline__ float bf_hi(uint32_t p) { return __uint_as_float(p & 0xffff0000u); }

// ---------------- FPS: register dist + redux argmax ----------------
template <int NPT>
__global__ void fps_fast(const float* __restrict__ xyz, int n, int npoint,
                         float* __restrict__ newxyz, float* __restrict__ outxyz) {
    extern __shared__ float sm[];
    float* sx = sm;
    float* sy = sm + n;
    float* sz = sm + 2 * n;
    uint32_t* pval = reinterpret_cast<uint32_t*>(sm + 3 * n);
    uint32_t* pidx = pval + 32;
    __shared__ int sfar;

    int b = blockIdx.x, tid = threadIdx.x, bt = blockDim.x;
    int wid = tid >> 5, lane = tid & 31;
    int nwarps = bt >> 5;
    const float* base = xyz + (size_t)b * 3 * n;
    for (int i = tid; i < n; i += bt) {
        sx[i] = base[i];
        sy[i] = base[n + i];
        sz[i] = base[2 * n + i];
    }
    __syncthreads();

    float px[NPT], py[NPT], pz[NPT], pd[NPT];
#pragma unroll
    for (int j = 0; j < NPT; j++) {
        int i = tid + j * bt;
        px[j] = sx[i]; py[j] = sy[i]; pz[j] = sz[i];
        pd[j] = 1e10f;
    }

    int far = 0;
    for (int t = 0; t < npoint; t++) {
        float cx = sx[far], cy = sy[far], cz = sz[far];
        if (tid == 0) {
            float* nw = &newxyz[(b * npoint + t) * 3];
            nw[0] = cx; nw[1] = cy; nw[2] = cz;
            outxyz[(size_t)b * 3 * npoint + t] = cx;
            outxyz[(size_t)b * 3 * npoint + npoint + t] = cy;
            outxyz[(size_t)b * 3 * npoint + 2 * npoint + t] = cz;
        }
        uint32_t bv; int bi;
#pragma unroll
        for (int j = 0; j < NPT; j++) {
            float dx = __fsub_rn(px[j], cx);
            float dy = __fsub_rn(py[j], cy);
            float dz = __fsub_rn(pz[j], cz);
            float d = __fadd_rn(__fadd_rn(__fmul_rn(dx, dx), __fmul_rn(dy, dy)), __fmul_rn(dz, dz));
            float dd = fminf(pd[j], d);
            pd[j] = dd;
            uint32_t bits = __float_as_uint(dd);
            if (j == 0) { bv = bits; bi = tid; }
            else if (bits > bv) { bv = bits; bi = tid + j * bt; }
        }
        uint32_t mval = __reduce_max_sync(0xffffffffu, bv);
        uint32_t cand = (bv == mval) ? (uint32_t)bi : 0xffffffffu;
        uint32_t midx = __reduce_min_sync(0xffffffffu, cand);
        if (lane == 0) { pval[wid] = mval; pidx[wid] = midx; }
        __syncthreads();
        if (wid == 0) {
            uint32_t v = (lane < nwarps) ? pval[lane] : 0u;
            uint32_t ii = (lane < nwarps) ? pidx[lane] : 0xffffffffu;
            uint32_t m = __reduce_max_sync(0xffffffffu, v);
            uint32_t c = (v == m) ? ii : 0xffffffffu;
            uint32_t mi = __reduce_min_sync(0xffffffffu, c);
            if (lane == 0) sfar = (int)mi;
        }
        __syncthreads();
        far = sfar;
    }
}

// ---------------- ball query: one warp per (b,s); optional l2-xyz bf16 split ----------------
__global__ void ballquery_kernel(const float* __restrict__ xyz, const float* __restrict__ newxyz,
                                 int n, int S, int K, float r2, int* __restrict__ gi,
                                 const float* __restrict__ sxyz,
                                 __nv_bfloat16* __restrict__ shi, __nv_bfloat16* __restrict__ slo) {
    int gt = blockIdx.x * blockDim.x + threadIdx.x;
    if (shi && gt < BB * 128 * 3) {
        // sxyz layout (B,3,128): element gt = b*384 + c*128 + kk
        int b = gt / 384, rr = gt % 384;
        int c = rr >> 7, kk = rr & 127;
        float v = sxyz[gt];
        __nv_bfloat16 h = __float2bfloat16_rn(v);
        size_t o = (size_t)(b * 128 + kk) * 320 + c;
        shi[o] = h;
        slo[o] = __float2bfloat16_rn(v - __bfloat162float(h));
    }
    int gw = gt >> 5;
    int lane = gt & 31;
    if (gw >= BB * S) return;
    int b = gw / S, s = gw % S;
    const float* nw = &newxyz[(b * S + s) * 3];
    float nx = nw[0], ny = nw[1], nz = nw[2];
    float nsq = __fadd_rn(__fadd_rn(__fmul_rn(nx, nx), __fmul_rn(ny, ny)), __fmul_rn(nz, nz));
    const float* px = xyz + (size_t)b * 3 * n;
    int* g = gi + (size_t)(b * S + s) * K;
    int cnt = 0, first = -1;
    for (int base = 0; base < n && cnt < K; base += 32) {
        int i = base + lane;
        float x = px[i], y = px[n + i], z = px[2 * n + i];
        float psq = __fadd_rn(__fadd_rn(__fmul_rn(x, x), __fmul_rn(y, y)), __fmul_rn(z, z));
        float dot = __fadd_rn(__fadd_rn(__fmul_rn(nx, x), __fmul_rn(ny, y)), __fmul_rn(nz, z));
        float sqr = __fsub_rn(__fadd_rn(nsq, psq), __fmul_rn(2.0f, dot));
        bool ok = !(sqr > r2);
        unsigned m = __ballot_sync(0xffffffffu, ok);
        if (first < 0 && m) first = base + __ffs(m) - 1;
        int pos = cnt + __popc(m & ((1u << lane) - 1u));
        if (ok && pos < K) g[pos] = i;
        cnt += __popc(m);
    }
    if (cnt > K) cnt = K;
    for (int p = cnt + lane; p < K; p += 32) g[p] = first;
}

// ---------------- fused gather + GEMM1 (6 -> 64) + stats ----------------
__global__ void __launch_bounds__(256)
gather_gemm1(const float* __restrict__ xyz, const float* __restrict__ pts,
             const int* __restrict__ gi, const float* __restrict__ newxyz,
             const float* __restrict__ W, const float* __restrict__ bias,
             float* __restrict__ out) {
    __shared__ float Ws[6 * 64];
    __shared__ float bs[64];
    __shared__ float ss[64], sq[64];
    int tid = threadIdx.x;
    for (int e = tid; e < 384; e += 256) Ws[e] = W[e];
    if (tid < 64) { bs[tid] = bias[tid]; ss[tid] = 0.f; sq[tid] = 0.f; }
    __syncthreads();

    int row = blockIdx.x * 256 + tid;
    int b = row >> 13, s = (row >> 5) & 255;
    int idx = gi[row];
    const float* px = xyz + (size_t)b * 3 * N0;
    const float* pp = pts + (size_t)b * 3 * N0;
    const float* nw = &newxyz[(b * 256 + s) * 3];
    float in[6];
    in[0] = __fsub_rn(px[idx], nw[0]);
    in[1] = __fsub_rn(px[N0 + idx], nw[1]);
    in[2] = __fsub_rn(px[2 * N0 + idx], nw[2]);
    in[3] = pp[idx];
    in[4] = pp[N0 + idx];
    in[5] = pp[2 * N0 + idx];

    const float4* W4 = reinterpret_cast<const float4*>(Ws);
    const float4* b4 = reinterpret_cast<const float4*>(bs);
    float4 v[16];
#pragma unroll
    for (int j = 0; j < 16; j++) v[j] = b4[j];
#pragma unroll
    for (int k = 0; k < 6; k++) {
        float a = in[k];
#pragma unroll
        for (int j = 0; j < 16; j++) {
            float4 w = W4[k * 16 + j];
            v[j].x += a * w.x; v[j].y += a * w.y;
            v[j].z += a * w.z; v[j].w += a * w.w;
        }
    }
    float4* o4 = reinterpret_cast<float4*>(out + (size_t)row * 64);
#pragma unroll
    for (int j = 0; j < 16; j++) o4[j] = v[j];

    int lane = tid & 31;
#pragma unroll
    for (int j = 0; j < 16; j++) {
        float c[4] = {v[j].x, v[j].y, v[j].z, v[j].w};
#pragma unroll
        for (int q = 0; q < 4; q++) {
            float sv = c[q], qv = c[q] * c[q];
#pragma unroll
            for (int o = 16; o; o >>= 1) {
                sv += __shfl_xor_sync(0xffffffffu, sv, o);
                qv += __shfl_xor_sync(0xffffffffu, qv, o);
            }
            if (lane == 0) {
                atomicAdd(&ss[j * 4 + q], sv);
                atomicAdd(&sq[j * 4 + q], qv);
            }
        }
    }
    __syncthreads();
    if (tid < 64) {
        atomicAdd(&g_sum[tid], (double)ss[tid]);
        atomicAdd(&g_sumsq[tid], (double)sq[tid]);
    }
}

// ---------------- prep all 5 weight matrices (split + transpose + pad) ----------------
__global__ void prep_all(const float* __restrict__ w1, const float* __restrict__ w2,
                         const float* __restrict__ w3, const float* __restrict__ w4,
                         const float* __restrict__ w5) {
    int i = blockIdx.x * blockDim.x + threadIdx.x;
    const float* W;
    int CIN, COUT, KPAD, j;
    if (i < 8192)        { W = w1; CIN = 64;  COUT = 128; KPAD = 64;  j = i; }
    else if (i < 32768)  { W = w2; CIN = 131; COUT = 128; KPAD = 192; j = i - 8192; }
    else if (i < 65536)  { W = w3; CIN = 128; COUT = 256; KPAD = 128; j = i - 32768; }
    else if (i < 147456) { W = w4; CIN = 259; COUT = 256; KPAD = 320; j = i - 65536; }
    else if (i < 278528) { W = w5; CIN = 256; COUT = 512; KPAD = 256; j = i - 147456; }
    else return;
    int n = j / KPAD, k = j - n * KPAD;
    float v = (k < CIN) ? W[(size_t)k * COUT + n] : 0.f;
    __nv_bfloat16 h = __float2bfloat16_rn(v);
    g_whi[i] = h;
    g_wlo[i] = __float2bfloat16_rn(v - __bfloat162float(h));
}

// ---------------- mma.sync helper ----------------
__device__ __forceinline__ void mma16816(float* c, const uint32_t* a, uint32_t b0, uint32_t b1) {
    asm volatile(
        "mma.sync.aligned.m16n8k16.row.col.f32.bf16.bf16.f32 "
        "{%0,%1,%2,%3}, {%4,%5,%6,%7}, {%8,%9}, {%0,%1,%2,%3};"
        : "+f"(c[0]), "+f"(c[1]), "+f"(c[2]), "+f"(c[3])
        : "r"(a[0]), "r"(a[1]), "r"(a[2]), "r"(a[3]), "r"(b0), "r"(b1));
}

// ---------------- HMMA bf16 split GEMM ----------------
// Block: 128 rows x COLS cols (n0 = blockIdx.y*COLS), K chunk 64.
// 16 warps as 4(m) x 4(n): warp owns 32 rows x NT*8 cols, NT = COLS/32.
// GATHER: 0 = plain fp32 A; 2 = SA2 gather (l1 hi/lo + inline xyz-center);
//         3 = SA3 pre-split rows (g_l2hi/lo, stride 320).
template <int CIN, int COUT, int COLS, int GATHER, bool IN_BN, bool POOL>
__global__ void __launch_bounds__(512)
hm_gemm(const float* __restrict__ A, const __nv_bfloat16* __restrict__ Whi,
        const __nv_bfloat16* __restrict__ Wlo, const float* __restrict__ bias,
        float* __restrict__ out, const int* __restrict__ gi,
        const float* __restrict__ gxyz, const float* __restrict__ gnew) {
    constexpr int KPAD = (CIN + 63) & ~63;
    constexpr int NCH = KPAD / 64;
    constexpr int LD = 72;
    constexpr int NT = COLS / 32;
    extern __shared__ __nv_bfloat16 sh[];
    __nv_bfloat16* Ahi = sh;
    __nv_bfloat16* Alo = Ahi + 128 * LD;
    __nv_bfloat16* Bhi = Alo + 128 * LD;
    __nv_bfloat16* Blo = Bhi + COLS * LD;

    int tid = threadIdx.x;
    int lane = tid & 31, w = tid >> 5;
    int mw = w >> 2, nw = w & 3;
    int g = lane >> 2, tg = lane & 3;
    size_t row0 = (size_t)blockIdx.x * 128;
    int n0 = blockIdx.y * COLS;

    float acc[2][NT][4];
#pragma unroll
    for (int i = 0; i < 2; i++)
#pragma unroll
        for (int j = 0; j < NT; j++)
#pragma unroll
            for (int q = 0; q < 4; q++) acc[i][j][q] = 0.f;

    int kp = tid & 15;  // constant per thread: strides are multiples of 16
    for (int ch = 0; ch < NCH; ch++) {
        int gk0 = ch * 64 + kp * 4;
        __syncthreads();
        // ---- A fill ----
        float4 s4, t4;
        if (IN_BN) {
            s4 = *reinterpret_cast<const float4*>(&g_scale[gk0]);
            t4 = *reinterpret_cast<const float4*>(&g_shift[gk0]);
        }
        for (int e = tid; e < 128 * 16; e += 512) {
            int r = e >> 4;
            if (GATHER == 2) {
                size_t R = row0 + r;
                int bb_ = (int)(R >> 13);
                int idx = gi[R];
                size_t rowoff = ((size_t)(bb_ * 256 + idx)) * 192;
                if (gk0 >= 4) {
                    *reinterpret_cast<uint2*>(&Ahi[r * LD + kp * 4]) =
                        *reinterpret_cast<const uint2*>(g_l1hi + rowoff + gk0);
                    *reinterpret_cast<uint2*>(&Alo[r * LD + kp * 4]) =
                        *reinterpret_cast<const uint2*>(g_l1lo + rowoff + gk0);
                } else {
                    size_t sidx = R >> 6;
#pragma unroll
                    for (int c = 0; c < 3; c++) {
                        float v = __fsub_rn(gxyz[(size_t)bb_ * 768 + c * 256 + idx],
                                            gnew[sidx * 3 + c]);
                        __nv_bfloat16 h = __float2bfloat16_rn(v);
                        Ahi[r * LD + c] = h;
                        Alo[r * LD + c] = __float2bfloat16_rn(v - __bfloat162float(h));
                    }
                    Ahi[r * LD + 3] = g_l1hi[rowoff + 3];
                    Alo[r * LD + 3] = g_l1lo[rowoff + 3];
                }
            } else if (GATHER == 3) {
                size_t rowoff = (row0 + r) * 320;
                *reinterpret_cast<uint2*>(&Ahi[r * LD + kp * 4]) =
                    *reinterpret_cast<const uint2*>(g_l2hi + rowoff + gk0);
                *reinterpret_cast<uint2*>(&Alo[r * LD + kp * 4]) =
                    *reinterpret_cast<const uint2*>(g_l2lo + rowoff + gk0);
            } else {
                float4 v = *reinterpret_cast<const float4*>(&A[(row0 + r) * CIN + gk0]);
                if (IN_BN) {
                    v.x = fmaxf(v.x * s4.x + t4.x, 0.f);
                    v.y = fmaxf(v.y * s4.y + t4.y, 0.f);
                    v.z = fmaxf(v.z * s4.z + t4.z, 0.f);
                    v.w = fmaxf(v.w * s4.w + t4.w, 0.f);
                }
                uint32_t h01 = pack_bf16x2(v.x, v.y);
                uint32_t h23 = pack_bf16x2(v.z, v.w);
                float r0 = v.x - bf_lo(h01), r1 = v.y - bf_hi(h01);
                float r2 = v.z - bf_lo(h23), r3 = v.w - bf_hi(h23);
                uint32_t l01 = pack_bf16x2(r0, r1);
                uint32_t l23 = pack_bf16x2(r2, r3);
                *reinterpret_cast<uint2*>(&Ahi[r * LD + kp * 4]) = make_uint2(h01, h23);
                *reinterpret_cast<uint2*>(&Alo[r * LD + kp * 4]) = make_uint2(l01, l23);
            }
        }
        // ---- B fill ----
        for (int e = tid; e < COLS * 16; e += 512) {
            int n = e >> 4;
            size_t gidx = (size_t)(n0 + n) * KPAD + gk0;
            *reinterpret_cast<uint2*>(&Bhi[n * LD + kp * 4]) =
                *reinterpret_cast<const uint2*>(Whi + gidx);
            *reinterpret_cast<uint2*>(&Blo[n * LD + kp * 4]) =
                *reinterpret_cast<const uint2*>(Wlo + gidx);
        }
        __syncthreads();

#pragma unroll
        for (int ks = 0; ks < 4; ks++) {
            int k0 = ks * 16;
            uint32_t ah[2][4], al[2][4];
#pragma unroll
            for (int mt = 0; mt < 2; mt++) {
                int rm = mw * 32 + mt * 16;
                ah[mt][0] = *reinterpret_cast<uint32_t*>(&Ahi[(rm + g) * LD + k0 + tg * 2]);
                ah[mt][1] = *reinterpret_cast<uint32_t*>(&Ahi[(rm + g + 8) * LD + k0 + tg * 2]);
                ah[mt][2] = *reinterpret_cast<uint32_t*>(&Ahi[(rm + g) * LD + k0 + tg * 2 + 8]);
                ah[mt][3] = *reinterpret_cast<uint32_t*>(&Ahi[(rm + g + 8) * LD + k0 + tg * 2 + 8]);
                al[mt][0] = *reinterpret_cast<uint32_t*>(&Alo[(rm + g) * LD + k0 + tg * 2]);
                al[mt][1] = *reinterpret_cast<uint32_t*>(&Alo[(rm + g + 8) * LD + k0 + tg * 2]);
                al[mt][2] = *reinterpret_cast<uint32_t*>(&Alo[(rm + g) * LD + k0 + tg * 2 + 8]);
                al[mt][3] = *reinterpret_cast<uint32_t*>(&Alo[(rm + g + 8) * LD + k0 + tg * 2 + 8]);
            }
#pragma unroll
            for (int nt = 0; nt < NT; nt++) {
                int cn = nw * (NT * 8) + nt * 8 + g;
                uint32_t bh0 = *reinterpret_cast<uint32_t*>(&Bhi[cn * LD + k0 + tg * 2]);
                uint32_t bh1 = *reinterpret_cast<uint32_t*>(&Bhi[cn * LD + k0 + tg * 2 + 8]);
                uint32_t bl0 = *reinterpret_cast<uint32_t*>(&Blo[cn * LD + k0 + tg * 2]);
                uint32_t bl1 = *reinterpret_cast<uint32_t*>(&Blo[cn * LD + k0 + tg * 2 + 8]);
#pragma unroll
                for (int mt = 0; mt < 2; mt++) {
                    mma16816(acc[mt][nt], ah[mt], bh0, bh1);
                    mma16816(acc[mt][nt], ah[mt], bl0, bl1);
                    mma16816(acc[mt][nt], al[mt], bh0, bh1);
                }
            }
        }
    }
    __syncthreads();

    // ---- epilogue: bias + (write | pool) + per-channel stats ----
    float* ss = reinterpret_cast<float*>(sh);
    float* sq = ss + COLS;
    for (int c = tid; c < COLS; c += 512) { ss[c] = 0.f; sq[c] = 0.f; }
    __syncthreads();

    int rb32 = (int)(row0 >> 5) + mw;
#pragma unroll
    for (int nt = 0; nt < NT; nt++) {
        int lc = nw * (NT * 8) + nt * 8 + tg * 2;
        float b0 = bias[n0 + lc], b1 = bias[n0 + lc + 1];
        float s0 = 0.f, q0 = 0.f, s1 = 0.f, q1 = 0.f;
        float mx0 = -3.4e38f, mn0 = 3.4e38f, mx1 = -3.4e38f, mn1 = 3.4e38f;
#pragma unroll
        for (int mt = 0; mt < 2; mt++) {
            float v00 = acc[mt][nt][0] + b0, v01 = acc[mt][nt][1] + b1;
            float v10 = acc[mt][nt][2] + b0, v11 = acc[mt][nt][3] + b1;
            if (!POOL) {
                size_t r0 = row0 + mw * 32 + mt * 16 + g;
                *reinterpret_cast<float2*>(&out[r0 * COUT + n0 + lc]) = make_float2(v00, v01);
                *reinterpret_cast<float2*>(&out[(r0 + 8) * COUT + n0 + lc]) = make_float2(v10, v11);
            }
            s0 += v00 + v10; q0 += v00 * v00 + v10 * v10;
            s1 += v01 + v11; q1 += v01 * v01 + v11 * v11;
            mx0 = fmaxf(mx0, fmaxf(v00, v10)); mn0 = fminf(mn0, fminf(v00, v10));
            mx1 = fmaxf(mx1, fmaxf(v01, v11)); mn1 = fminf(mn1, fminf(v01, v11));
        }
#pragma unroll
        for (int o = 4; o < 32; o <<= 1) {
            s0 += __shfl_xor_sync(0xffffffffu, s0, o);
            q0 += __shfl_xor_sync(0xffffffffu, q0, o);
            s1 += __shfl_xor_sync(0xffffffffu, s1, o);
            q1 += __shfl_xor_sync(0xffffffffu, q1, o);
            if (POOL) {
                mx0 = fmaxf(mx0, __shfl_xor_sync(0xffffffffu, mx0, o));
                mn0 = fminf(mn0, __shfl_xor_sync(0xffffffffu, mn0, o));
                mx1 = fmaxf(mx1, __shfl_xor_sync(0xffffffffu, mx1, o));
                mn1 = fminf(mn1, __shfl_xor_sync(0xffffffffu, mn1, o));
            }
        }
        if (g == 0) {
            atomicAdd(&ss[lc], s0);
            atomicAdd(&sq[lc], q0);
            atomicAdd(&ss[lc + 1], s1);
            atomicAdd(&sq[lc + 1], q1);
            if (POOL) {
                size_t pb = (size_t)rb32 * COUT + n0 + lc;
                g_pmax[pb] = mx0; g_pmin[pb] = mn0;
                g_pmax[pb + 1] = mx1; g_pmin[pb + 1] = mn1;
            }
        }
    }
    __syncthreads();
    for (int c = tid; c < COLS; c += 512) {
        atomicAdd(&g_sum[n0 + c], (double)ss[c]);
        atomicAdd(&g_sumsq[n0 + c], (double)sq[c]);
    }
}

// ---------------- pooled-raw -> BN + relu -> outputs ----------------
__global__ void pool_bn_out(int S, int KG, int C, float* __restrict__ out,
                            __nv_bfloat16* __restrict__ ohi, __nv_bfloat16* __restrict__ olo,
                            int ostride, float* __restrict__ zp, int zn) {
    if (zp && blockIdx.x == 0 && threadIdx.x < zn) zp[threadIdx.x] = 0.f;
    int total = BB * S * C;
    int stride = gridDim.x * blockDim.x;
    for (int i = blockIdx.x * blockDim.x + threadIdx.x; i < total; i += stride) {
        int c = i % C;
        int s = (i / C) % S;
        int b = i / (C * S);
        size_t base = ((size_t)(b * S + s) * KG) * C + c;
        float mx = g_pmax[base], mn = g_pmin[base];
        for (int q = 1; q < KG; q++) {
            mx = fmaxf(mx, g_pmax[base + (size_t)q * C]);
            mn = fminf(mn, g_pmin[base + (size_t)q * C]);
        }
        float sc = g_scale[c];
        float raw = (sc >= 0.f) ? mx : mn;
        float r = fmaxf(raw * sc + g_shift[c], 0.f);
        out[(size_t)b * C * S + (size_t)c * S + s] = r;
        if (ohi) {
            __nv_bfloat16 h = __float2bfloat16_rn(r);
            size_t o = (size_t)(b * S + s) * ostride + c + 3;
            ohi[o] = h;
            olo[o] = __float2bfloat16_rn(r - __bfloat162float(h));
        }
    }
}

// ---------------- BN finalize (also re-zeros accumulators for next use) ----------------
__global__ void bn_finalize_kernel(int C, double invcnt, const float* __restrict__ gamma,
                                   const float* __restrict__ beta) {
    int c = threadIdx.x;
    if (c < C) {
        double m = g_sum[c] * invcnt;
        double var = g_sumsq[c] * invcnt - m * m;
        float s = gamma[c] * rsqrtf((float)var + 1e-5f);
        g_scale[c] = s;
        g_shift[c] = beta[c] - (float)m * s;
    }
    g_sum[c] = 0.0;
    g_sumsq[c] = 0.0;
}

// ---------------- orchestration ----------------
extern "C" void kernel_launch(void* const* d_in, const int* in_sizes, int n_in,
                              void* d_out, int out_size) {
    (void)in_sizes; (void)n_in; (void)out_size;
    const float* l0_xyz = (const float*)d_in[0];
    const float* l0_pts = (const float*)d_in[1];
    float* out = (float*)d_out;

    float* o_l1xyz = out;                 // 16*3*256   = 12288
    float* o_l1pts = out + 12288;         // 16*128*256 = 524288
    float* o_l2xyz = out + 536576;        // 16*3*128   = 6144
    float* o_l2pts = out + 542720;        // 16*256*128 = 524288
    float* o_l3xyz = out + 1067008;       // 16*3*1     = 48
    float* o_x     = out + 1067056;       // 16*512     = 8192

    float *bufB, *nxyz;
    int *gi;
    __nv_bfloat16 *whi, *wlo, *l1hi, *l1lo, *l2hi, *l2lo;
    cudaGetSymbolAddress((void**)&bufB, g_bufB);
    cudaGetSymbolAddress((void**)&nxyz, g_newxyz);
    cudaGetSymbolAddress((void**)&gi, g_gi);
    cudaGetSymbolAddress((void**)&whi, g_whi);
    cudaGetSymbolAddress((void**)&wlo, g_wlo);
    cudaGetSymbolAddress((void**)&l1hi, g_l1hi);
    cudaGetSymbolAddress((void**)&l1lo, g_l1lo);
    cudaGetSymbolAddress((void**)&l2hi, g_l2hi);
    cudaGetSymbolAddress((void**)&l2lo, g_l2lo);

    constexpr int FPS1_SM = 3 * 4096 * 4 + 256;
    constexpr int FPS2_SM = 3 * 256 * 4 + 256;
    cudaFuncSetAttribute((const void*)fps_fast<8>, cudaFuncAttributeMaxDynamicSharedMemorySize, FPS1_SM);
    constexpr int HSM128 = (2 * 128 * 72 + 2 * 128 * 72) * 2;   // 73728
    constexpr int HSM256 = (2 * 128 * 72 + 2 * 256 * 72) * 2;   // 110592
    cudaFuncSetAttribute((const void*)hm_gemm<64, 128, 128, 0, true, true>,
                         cudaFuncAttributeMaxDynamicSharedMemorySize, HSM128);
    cudaFuncSetAttribute((const void*)hm_gemm<131, 128, 128, 2, false, false>,
                         cudaFuncAttributeMaxDynamicSharedMemorySize, HSM128);
    cudaFuncSetAttribute((const void*)hm_gemm<128, 256, 256, 0, true, true>,
                         cudaFuncAttributeMaxDynamicSharedMemorySize, HSM256);
    cudaFuncSetAttribute((const void*)hm_gemm<259, 256, 256, 3, false, false>,
                         cudaFuncAttributeMaxDynamicSharedMemorySize, HSM256);
    cudaFuncSetAttribute((const void*)hm_gemm<256, 512, 256, 0, true, true>,
                         cudaFuncAttributeMaxDynamicSharedMemorySize, HSM256);

    // ---- all weight prep up front (1 launch) ----
    prep_all<<<1088, 256>>>((const float*)d_in[6], (const float*)d_in[10],
                            (const float*)d_in[14], (const float*)d_in[18],
                            (const float*)d_in[22]);

    // ================= SA1 : N=4096 -> S=256, K=32 =================
    fps_fast<8><<<16, 512, FPS1_SM>>>(l0_xyz, 4096, 256, nxyz, o_l1xyz);
    ballquery_kernel<<<(16 * 256) / 8, 256>>>(l0_xyz, nxyz, 4096, 256, 32, 0.04f, gi,
                                              nullptr, nullptr, nullptr);
    gather_gemm1<<<512, 256>>>(l0_xyz, l0_pts, gi, nxyz,
                               (const float*)d_in[2], (const float*)d_in[3], bufB);
    bn_finalize_kernel<<<1, 512>>>(64, 1.0 / 131072.0, (const float*)d_in[4], (const float*)d_in[5]);

    hm_gemm<64, 128, 128, 0, true, true><<<1024, 512, HSM128>>>(
        bufB, whi + WOFF_L1B, wlo + WOFF_L1B, (const float*)d_in[7],
        nullptr, nullptr, nullptr, nullptr);
    bn_finalize_kernel<<<1, 512>>>(128, 1.0 / 131072.0, (const float*)d_in[8], (const float*)d_in[9]);
    pool_bn_out<<<2048, 256>>>(256, 1, 128, o_l1pts, l1hi, l1lo, 192, nullptr, 0);

    // ================= SA2 : N=256 -> S=128, K=64 =================
    fps_fast<1><<<16, 256, FPS2_SM>>>(o_l1xyz, 256, 128, nxyz, o_l2xyz);
    ballquery_kernel<<<(16 * 128) / 8, 256>>>(o_l1xyz, nxyz, 256, 128, 64, 0.0625f, gi,
                                              o_l2xyz, l2hi, l2lo);

    hm_gemm<131, 128, 128, 2, false, false><<<1024, 512, HSM128>>>(
        nullptr, whi + WOFF_L2A, wlo + WOFF_L2A, (const float*)d_in[11],
        bufB, gi, o_l1xyz, nxyz);
    bn_finalize_kernel<<<1, 512>>>(128, 1.0 / 131072.0, (const float*)d_in[12], (const float*)d_in[13]);

    hm_gemm<128, 256, 256, 0, true, true><<<1024, 512, HSM256>>>(
        bufB, whi + WOFF_L2B, wlo + WOFF_L2B, (const float*)d_in[15],
        nullptr, nullptr, nullptr, nullptr);
    bn_finalize_kernel<<<1, 512>>>(256, 1.0 / 131072.0, (const float*)d_in[16], (const float*)d_in[17]);
    pool_bn_out<<<2048, 256>>>(128, 2, 256, o_l2pts, l2hi, l2lo, 320, nullptr, 0);

    // ================= SA3 : group_all, rows = 16*128 = 2048 =================
    hm_gemm<259, 256, 256, 3, false, false><<<16, 512, HSM256>>>(
        nullptr, whi + WOFF_L3A, wlo + WOFF_L3A, (const float*)d_in[19],
        bufB, nullptr, nullptr, nullptr);
    bn_finalize_kernel<<<1, 512>>>(256, 1.0 / 2048.0, (const float*)d_in[20], (const float*)d_in[21]);

    hm_gemm<256, 512, 256, 0, true, true><<<dim3(16, 2), 512, HSM256>>>(
        bufB, whi + WOFF_L3B, wlo + WOFF_L3B, (const float*)d_in[23],
        nullptr, nullptr, nullptr, nullptr);
    bn_finalize_kernel<<<1, 512>>>(512, 1.0 / 2048.0, (const float*)d_in[24], (const float*)d_in[25]);

    pool_bn_out<<<64, 256>>>(1, 4, 512, o_x, nullptr, nullptr, 0, o_l3xyz, 48);
}

// round 9
// speedup vs baseline: 2.8216x; 1.0563x over previous
#include <cuda_runtime.h>
#include <cuda_bf16.h>
#include <cstdint>
#include <cstddef>

// ---------------- problem constants ----------------
#define BB 16
#define N0 4096

// scratch (device globals; allocation-free per harness rules)
__device__ float  g_bufB[16777216];           // 64 MB (max: 131072x128)
__device__ float  g_newxyz[BB * 256 * 3];
__device__ int    g_gi[131072];
__device__ __nv_bfloat16 g_l1hi[786432];      // l1 feats hi, (b*256+s)*192 + (c+3); pads stay 0
__device__ __nv_bfloat16 g_l1lo[786432];
__device__ __nv_bfloat16 g_l2hi[655360];      // l2 row*(320): [0..2]=xyz, [3..258]=feats, pads 0
__device__ __nv_bfloat16 g_l2lo[655360];
__device__ double g_sum[512];
__device__ double g_sumsq[512];
__device__ double g_m6[32];                   // layer-1 input moments: S[6], M-upper[21]
__device__ float  g_scale[512];
__device__ float  g_shift[512];
__device__ __nv_bfloat16 g_whi[278528];       // all 5 layers, pre-split transposed
__device__ __nv_bfloat16 g_wlo[278528];
__device__ float  g_pmax[1048576];            // pooled-raw max per 32-row block
__device__ float  g_pmin[1048576];

// weight segment offsets in g_whi/g_wlo
#define WOFF_L1B 0        // 64->128,  KPAD 64
#define WOFF_L2A 8192     // 131->128, KPAD 192
#define WOFF_L2B 32768    // 128->256, KPAD 128
#define WOFF_L3A 65536    // 259->256, KPAD 320
#define WOFF_L3B 147456   // 256->512, KPAD 256

// ---------------- bf16 pack helpers ----------------
__device__ __forceinline__ uint32_t pack_bf16x2(float lo, float hi) {
    uint32_t r;
    asm("cvt.rn.bf16x2.f32 %0, %1, %2;" : "=r"(r) : "f"(hi), "f"(lo));
    return r;
}
__device__ __forceinline__ float bf_lo(uint32_t p) { return __uint_as_float(p << 16); }
__device__ __forceinline__ float bf_hi(uint32_t p) { return __uint_as_float(p & 0xffff0000u); }

// ---------------- FPS: register dist + redux argmax ----------------
template <int NPT>
__global__ void fps_fast(const float* __restrict__ xyz, int n, int npoint,
                         float* __restrict__ newxyz, float* __restrict__ outxyz) {
    extern __shared__ float sm[];
    float* sx = sm;
    float* sy = sm + n;
    float* sz = sm + 2 * n;
    uint32_t* pval = reinterpret_cast<uint32_t*>(sm + 3 * n);
    uint32_t* pidx = pval + 32;
    __shared__ int sfar;

    int b = blockIdx.x, tid = threadIdx.x, bt = blockDim.x;
    int wid = tid >> 5, lane = tid & 31;
    int nwarps = bt >> 5;
    const float* base = xyz + (size_t)b * 3 * n;
    for (int i = tid; i < n; i += bt) {
        sx[i] = base[i];
        sy[i] = base[n + i];
        sz[i] = base[2 * n + i];
    }
    __syncthreads();

    float px[NPT], py[NPT], pz[NPT], pd[NPT];
#pragma unroll
    for (int j = 0; j < NPT; j++) {
        int i = tid + j * bt;
        px[j] = sx[i]; py[j] = sy[i]; pz[j] = sz[i];
        pd[j] = 1e10f;
    }

    int far = 0;
    for (int t = 0; t < npoint; t++) {
        float cx = sx[far], cy = sy[far], cz = sz[far];
        if (tid == 0) {
            float* nw = &newxyz[(b * npoint + t) * 3];
            nw[0] = cx; nw[1] = cy; nw[2] = cz;
            outxyz[(size_t)b * 3 * npoint + t] = cx;
            outxyz[(size_t)b * 3 * npoint + npoint + t] = cy;
            outxyz[(size_t)b * 3 * npoint + 2 * npoint + t] = cz;
        }
        uint32_t bv; int bi;
#pragma unroll
        for (int j = 0; j < NPT; j++) {
            float dx = __fsub_rn(px[j], cx);
            float dy = __fsub_rn(py[j], cy);
            float dz = __fsub_rn(pz[j], cz);
            float d = __fadd_rn(__fadd_rn(__fmul_rn(dx, dx), __fmul_rn(dy, dy)), __fmul_rn(dz, dz));
            float dd = fminf(pd[j], d);
            pd[j] = dd;
            uint32_t bits = __float_as_uint(dd);
            if (j == 0) { bv = bits; bi = tid; }
            else if (bits > bv) { bv = bits; bi = tid + j * bt; }
        }
        uint32_t mval = __reduce_max_sync(0xffffffffu, bv);
        uint32_t cand = (bv == mval) ? (uint32_t)bi : 0xffffffffu;
        uint32_t midx = __reduce_min_sync(0xffffffffu, cand);
        if (lane == 0) { pval[wid] = mval; pidx[wid] = midx; }
        __syncthreads();
        if (wid == 0) {
            uint32_t v = (lane < nwarps) ? pval[lane] : 0u;
            uint32_t ii = (lane < nwarps) ? pidx[lane] : 0xffffffffu;
            uint32_t m = __reduce_max_sync(0xffffffffu, v);
            uint32_t c = (v == m) ? ii : 0xffffffffu;
            uint32_t mi = __reduce_min_sync(0xffffffffu, c);
            if (lane == 0) sfar = (int)mi;
        }
        __syncthreads();
        far = sfar;
    }
}

// ---------------- ball query: one warp per (b,s); optional l2-xyz bf16 split ----------------
__global__ void ballquery_kernel(const float* __restrict__ xyz, const float* __restrict__ newxyz,
                                 int n, int S, int K, float r2, int* __restrict__ gi,
                                 const float* __restrict__ sxyz,
                                 __nv_bfloat16* __restrict__ shi, __nv_bfloat16* __restrict__ slo) {
    int gt = blockIdx.x * blockDim.x + threadIdx.x;
    if (shi && gt < BB * 128 * 3) {
        int b = gt / 384, rr = gt % 384;
        int c = rr >> 7, kk = rr & 127;
        float v = sxyz[gt];
        __nv_bfloat16 h = __float2bfloat16_rn(v);
        size_t o = (size_t)(b * 128 + kk) * 320 + c;
        shi[o] = h;
        slo[o] = __float2bfloat16_rn(v - __bfloat162float(h));
    }
    int gw = gt >> 5;
    int lane = gt & 31;
    if (gw >= BB * S) return;
    int b = gw / S, s = gw % S;
    const float* nw = &newxyz[(b * S + s) * 3];
    float nx = nw[0], ny = nw[1], nz = nw[2];
    float nsq = __fadd_rn(__fadd_rn(__fmul_rn(nx, nx), __fmul_rn(ny, ny)), __fmul_rn(nz, nz));
    const float* px = xyz + (size_t)b * 3 * n;
    int* g = gi + (size_t)(b * S + s) * K;
    int cnt = 0, first = -1;
    for (int base = 0; base < n && cnt < K; base += 32) {
        int i = base + lane;
        float x = px[i], y = px[n + i], z = px[2 * n + i];
        float psq = __fadd_rn(__fadd_rn(__fmul_rn(x, x), __fmul_rn(y, y)), __fmul_rn(z, z));
        float dot = __fadd_rn(__fadd_rn(__fmul_rn(nx, x), __fmul_rn(ny, y)), __fmul_rn(nz, z));
        float sqr = __fsub_rn(__fadd_rn(nsq, psq), __fmul_rn(2.0f, dot));
        bool ok = !(sqr > r2);
        unsigned m = __ballot_sync(0xffffffffu, ok);
        if (first < 0 && m) first = base + __ffs(m) - 1;
        int pos = cnt + __popc(m & ((1u << lane) - 1u));
        if (ok && pos < K) g[pos] = i;
        cnt += __popc(m);
    }
    if (cnt > K) cnt = K;
    for (int p = cnt + lane; p < K; p += 32) g[p] = first;
}

// ---------------- layer-1 input moments: S[6] + upper M[21] ----------------
__global__ void __launch_bounds__(256)
gather_stats1(const float* __restrict__ xyz, const float* __restrict__ pts,
              const int* __restrict__ gi, const float* __restrict__ newxyz) {
    __shared__ float sm27[27];
    int tid = threadIdx.x;
    int lane = tid & 31;
    if (tid < 27) sm27[tid] = 0.f;
    __syncthreads();

    float acc[27];
#pragma unroll
    for (int i = 0; i < 27; i++) acc[i] = 0.f;

    for (int it = 0; it < 4; it++) {
        int row = blockIdx.x * 1024 + it * 256 + tid;
        int b = row >> 13, s = (row >> 5) & 255;
        int idx = gi[row];
        const float* px = xyz + (size_t)b * 3 * N0;
        const float* pp = pts + (size_t)b * 3 * N0;
        const float* nw = &newxyz[(b * 256 + s) * 3];
        float in[6];
        in[0] = __fsub_rn(px[idx], nw[0]);
        in[1] = __fsub_rn(px[N0 + idx], nw[1]);
        in[2] = __fsub_rn(px[2 * N0 + idx], nw[2]);
        in[3] = pp[idx];
        in[4] = pp[N0 + idx];
        in[5] = pp[2 * N0 + idx];
        int c = 0;
#pragma unroll
        for (int k = 0; k < 6; k++) acc[c++] += in[k];
#pragma unroll
        for (int k = 0; k < 6; k++)
#pragma unroll
            for (int l = k; l < 6; l++) acc[c++] += in[k] * in[l];
    }
#pragma unroll
    for (int i = 0; i < 27; i++) {
        float v = acc[i];
#pragma unroll
        for (int o = 16; o; o >>= 1) v += __shfl_xor_sync(0xffffffffu, v, o);
        if (lane == 0) atomicAdd(&sm27[i], v);
    }
    __syncthreads();
    if (tid < 27) atomicAdd(&g_m6[tid], (double)sm27[tid]);
}

// ---------------- layer-1 BN finalize from moments (double), then reset ----------------
__global__ void bn_finalize6(const float* __restrict__ W, const float* __restrict__ bias,
                             const float* __restrict__ gamma, const float* __restrict__ beta) {
    __shared__ double S[6], M[6][6];
    int tid = threadIdx.x;  // 64 threads
    if (tid < 6) S[tid] = g_m6[tid];
    if (tid == 0) {
        int c = 6;
        for (int k = 0; k < 6; k++)
            for (int l = k; l < 6; l++) { M[k][l] = g_m6[c]; M[l][k] = g_m6[c]; c++; }
    }
    __syncthreads();
    double w[6];
#pragma unroll
    for (int k = 0; k < 6; k++) w[k] = (double)W[k * 64 + tid];
    double bc = (double)bias[tid];
    double sw = 0.0;
#pragma unroll
    for (int k = 0; k < 6; k++) sw += S[k] * w[k];
    const double N = 131072.0;
    double mean = (sw + N * bc) / N;
    double q = 0.0;
#pragma unroll
    for (int k = 0; k < 6; k++)
#pragma unroll
        for (int l = 0; l < 6; l++) q += M[k][l] * w[k] * w[l];
    double ex2 = (q + 2.0 * bc * sw + N * bc * bc) / N;
    double var = ex2 - mean * mean;
    float sc = gamma[tid] * rsqrtf((float)var + 1e-5f);
    g_scale[tid] = sc;
    g_shift[tid] = beta[tid] - (float)mean * sc;
    __syncthreads();
    if (tid < 27) g_m6[tid] = 0.0;  // reset for next graph replay
}

// ---------------- prep all 5 weight matrices (split + transpose + pad) ----------------
__global__ void prep_all(const float* __restrict__ w1, const float* __restrict__ w2,
                         const float* __restrict__ w3, const float* __restrict__ w4,
                         const float* __restrict__ w5) {
    int i = blockIdx.x * blockDim.x + threadIdx.x;
    const float* W;
    int CIN, COUT, KPAD, j;
    if (i < 8192)        { W = w1; CIN = 64;  COUT = 128; KPAD = 64;  j = i; }
    else if (i < 32768)  { W = w2; CIN = 131; COUT = 128; KPAD = 192; j = i - 8192; }
    else if (i < 65536)  { W = w3; CIN = 128; COUT = 256; KPAD = 128; j = i - 32768; }
    else if (i < 147456) { W = w4; CIN = 259; COUT = 256; KPAD = 320; j = i - 65536; }
    else if (i < 278528) { W = w5; CIN = 256; COUT = 512; KPAD = 256; j = i - 147456; }
    else return;
    int n = j / KPAD, k = j - n * KPAD;
    float v = (k < CIN) ? W[(size_t)k * COUT + n] : 0.f;
    __nv_bfloat16 h = __float2bfloat16_rn(v);
    g_whi[i] = h;
    g_wlo[i] = __float2bfloat16_rn(v - __bfloat162float(h));
}

// ---------------- mma.sync helper ----------------
__device__ __forceinline__ void mma16816(float* c, const uint32_t* a, uint32_t b0, uint32_t b1) {
    asm volatile(
        "mma.sync.aligned.m16n8k16.row.col.f32.bf16.bf16.f32 "
        "{%0,%1,%2,%3}, {%4,%5,%6,%7}, {%8,%9}, {%0,%1,%2,%3};"
        : "+f"(c[0]), "+f"(c[1]), "+f"(c[2]), "+f"(c[3])
        : "r"(a[0]), "r"(a[1]), "r"(a[2]), "r"(a[3]), "r"(b0), "r"(b1));
}

// ---------------- HMMA bf16 split GEMM ----------------
// Block: 128 rows x COLS cols (n0 = blockIdx.y*COLS), K chunk 64.
// 16 warps as 4(m) x 4(n): warp owns 32 rows x NT*8 cols, NT = COLS/32.
// GATHER: 0 = plain fp32 A; 1 = fused gather + 6->64 layer-1 (A = W1 fp32,
//         gpts/gb1 used, BN+relu applied on computed layer-1 outputs);
//         2 = SA2 gather (l1 hi/lo + inline xyz-center);
//         3 = SA3 pre-split rows (g_l2hi/lo, stride 320).
template <int CIN, int COUT, int COLS, int GATHER, bool IN_BN, bool POOL>
__global__ void __launch_bounds__(512)
hm_gemm(const float* __restrict__ A, const __nv_bfloat16* __restrict__ Whi,
        const __nv_bfloat16* __restrict__ Wlo, const float* __restrict__ bias,
        float* __restrict__ out, const int* __restrict__ gi,
        const float* __restrict__ gxyz, const float* __restrict__ gnew,
        const float* __restrict__ gpts, const float* __restrict__ gb1) {
    constexpr int KPAD = (CIN + 63) & ~63;
    constexpr int NCH = KPAD / 64;
    constexpr int LD = 72;
    constexpr int NT = COLS / 32;
    extern __shared__ __nv_bfloat16 sh[];
    __nv_bfloat16* Ahi = sh;
    __nv_bfloat16* Alo = Ahi + 128 * LD;
    __nv_bfloat16* Bhi = Alo + 128 * LD;
    __nv_bfloat16* Blo = Bhi + COLS * LD;
    // GATHER1 extras (beyond the B tiles)
    float* in6 = reinterpret_cast<float*>(Blo + COLS * LD);  // 128*8 floats
    float* W1s = in6 + 128 * 8;                              // 384
    float* b1s = W1s + 384;                                  // 64

    int tid = threadIdx.x;
    int lane = tid & 31, w = tid >> 5;
    int mw = w >> 2, nw = w & 3;
    int g = lane >> 2, tg = lane & 3;
    size_t row0 = (size_t)blockIdx.x * 128;
    int n0 = blockIdx.y * COLS;

    float acc[2][NT][4];
#pragma unroll
    for (int i = 0; i < 2; i++)
#pragma unroll
        for (int j = 0; j < NT; j++)
#pragma unroll
            for (int q = 0; q < 4; q++) acc[i][j][q] = 0.f;

    if (GATHER == 1) {
        for (int e = tid; e < 384; e += 512) W1s[e] = A[e];
        if (tid < 64) b1s[tid] = gb1[tid];
    }

    int kp = tid & 15;  // constant per thread: strides are multiples of 16
    for (int ch = 0; ch < NCH; ch++) {
        int gk0 = ch * 64 + kp * 4;
        __syncthreads();
        float4 s4, t4;
        if (IN_BN) {
            s4 = *reinterpret_cast<const float4*>(&g_scale[gk0]);
            t4 = *reinterpret_cast<const float4*>(&g_shift[gk0]);
        }
        // ---- GATHER1 stage 1: rows' 6 inputs into smem ----
        if (GATHER == 1) {
            for (int r = tid; r < 128; r += 512) {
                size_t R = row0 + r;
                int bb_ = (int)(R >> 13), s = (int)((R >> 5) & 255);
                int idx = gi[R];
                const float* px = gxyz + (size_t)bb_ * 3 * N0;
                const float* pp = gpts + (size_t)bb_ * 3 * N0;
                const float* nwp = gnew + (size_t)(bb_ * 256 + s) * 3;
                in6[r * 8 + 0] = __fsub_rn(px[idx], nwp[0]);
                in6[r * 8 + 1] = __fsub_rn(px[N0 + idx], nwp[1]);
                in6[r * 8 + 2] = __fsub_rn(px[2 * N0 + idx], nwp[2]);
                in6[r * 8 + 3] = pp[idx];
                in6[r * 8 + 4] = pp[N0 + idx];
                in6[r * 8 + 5] = pp[2 * N0 + idx];
            }
        }
        // ---- B fill ----
        for (int e = tid; e < COLS * 16; e += 512) {
            int n = e >> 4;
            size_t gidx = (size_t)(n0 + n) * KPAD + gk0;
            *reinterpret_cast<uint2*>(&Bhi[n * LD + kp * 4]) =
                *reinterpret_cast<const uint2*>(Whi + gidx);
            *reinterpret_cast<uint2*>(&Blo[n * LD + kp * 4]) =
                *reinterpret_cast<const uint2*>(Wlo + gidx);
        }
        // ---- A fill ----
        if (GATHER == 1) {
            __syncthreads();  // in6 + W1s visible
            for (int e = tid; e < 128 * 16; e += 512) {
                int r = e >> 4;
                int c0 = kp * 4;
                float i0 = in6[r * 8 + 0], i1 = in6[r * 8 + 1], i2 = in6[r * 8 + 2];
                float i3 = in6[r * 8 + 3], i4 = in6[r * 8 + 4], i5 = in6[r * 8 + 5];
                float v[4];
#pragma unroll
                for (int q = 0; q < 4; q++) {
                    float a = b1s[c0 + q];
                    a += i0 * W1s[0 * 64 + c0 + q];
                    a += i1 * W1s[1 * 64 + c0 + q];
                    a += i2 * W1s[2 * 64 + c0 + q];
                    a += i3 * W1s[3 * 64 + c0 + q];
                    a += i4 * W1s[4 * 64 + c0 + q];
                    a += i5 * W1s[5 * 64 + c0 + q];
                    v[q] = a;
                }
                v[0] = fmaxf(v[0] * s4.x + t4.x, 0.f);
                v[1] = fmaxf(v[1] * s4.y + t4.y, 0.f);
                v[2] = fmaxf(v[2] * s4.z + t4.z, 0.f);
                v[3] = fmaxf(v[3] * s4.w + t4.w, 0.f);
                uint32_t h01 = pack_bf16x2(v[0], v[1]);
                uint32_t h23 = pack_bf16x2(v[2], v[3]);
                uint32_t l01 = pack_bf16x2(v[0] - bf_lo(h01), v[1] - bf_hi(h01));
                uint32_t l23 = pack_bf16x2(v[2] - bf_lo(h23), v[3] - bf_hi(h23));
                *reinterpret_cast<uint2*>(&Ahi[r * LD + kp * 4]) = make_uint2(h01, h23);
                *reinterpret_cast<uint2*>(&Alo[r * LD + kp * 4]) = make_uint2(l01, l23);
            }
        } else {
            for (int e = tid; e < 128 * 16; e += 512) {
                int r = e >> 4;
                if (GATHER == 2) {
                    size_t R = row0 + r;
                    int bb_ = (int)(R >> 13);
                    int idx = gi[R];
                    size_t rowoff = ((size_t)(bb_ * 256 + idx)) * 192;
                    if (gk0 >= 4) {
                        *reinterpret_cast<uint2*>(&Ahi[r * LD + kp * 4]) =
                            *reinterpret_cast<const uint2*>(g_l1hi + rowoff + gk0);
                        *reinterpret_cast<uint2*>(&Alo[r * LD + kp * 4]) =
                            *reinterpret_cast<const uint2*>(g_l1lo + rowoff + gk0);
                    } else {
                        size_t sidx = R >> 6;
#pragma unroll
                        for (int c = 0; c < 3; c++) {
                            float v = __fsub_rn(gxyz[(size_t)bb_ * 768 + c * 256 + idx],
                                                gnew[sidx * 3 + c]);
                            __nv_bfloat16 h = __float2bfloat16_rn(v);
                            Ahi[r * LD + c] = h;
                            Alo[r * LD + c] = __float2bfloat16_rn(v - __bfloat162float(h));
                        }
                        Ahi[r * LD + 3] = g_l1hi[rowoff + 3];
                        Alo[r * LD + 3] = g_l1lo[rowoff + 3];
                    }
                } else if (GATHER == 3) {
                    size_t rowoff = (row0 + r) * 320;
                    *reinterpret_cast<uint2*>(&Ahi[r * LD + kp * 4]) =
                        *reinterpret_cast<const uint2*>(g_l2hi + rowoff + gk0);
                    *reinterpret_cast<uint2*>(&Alo[r * LD + kp * 4]) =
                        *reinterpret_cast<const uint2*>(g_l2lo + rowoff + gk0);
                } else {
                    float4 v = *reinterpret_cast<const float4*>(&A[(row0 + r) * CIN + gk0]);
                    if (IN_BN) {
                        v.x = fmaxf(v.x * s4.x + t4.x, 0.f);
                        v.y = fmaxf(v.y * s4.y + t4.y, 0.f);
                        v.z = fmaxf(v.z * s4.z + t4.z, 0.f);
                        v.w = fmaxf(v.w * s4.w + t4.w, 0.f);
                    }
                    uint32_t h01 = pack_bf16x2(v.x, v.y);
                    uint32_t h23 = pack_bf16x2(v.z, v.w);
                    float r0 = v.x - bf_lo(h01), r1 = v.y - bf_hi(h01);
                    float r2 = v.z - bf_lo(h23), r3 = v.w - bf_hi(h23);
                    uint32_t l01 = pack_bf16x2(r0, r1);
                    uint32_t l23 = pack_bf16x2(r2, r3);
                    *reinterpret_cast<uint2*>(&Ahi[r * LD + kp * 4]) = make_uint2(h01, h23);
                    *reinterpret_cast<uint2*>(&Alo[r * LD + kp * 4]) = make_uint2(l01, l23);
                }
            }
        }
        __syncthreads();

#pragma unroll
        for (int ks = 0; ks < 4; ks++) {
            int k0 = ks * 16;
            uint32_t ah[2][4], al[2][4];
#pragma unroll
            for (int mt = 0; mt < 2; mt++) {
                int rm = mw * 32 + mt * 16;
                ah[mt][0] = *reinterpret_cast<uint32_t*>(&Ahi[(rm + g) * LD + k0 + tg * 2]);
                ah[mt][1] = *reinterpret_cast<uint32_t*>(&Ahi[(rm + g + 8) * LD + k0 + tg * 2]);
                ah[mt][2] = *reinterpret_cast<uint32_t*>(&Ahi[(rm + g) * LD + k0 + tg * 2 + 8]);
                ah[mt][3] = *reinterpret_cast<uint32_t*>(&Ahi[(rm + g + 8) * LD + k0 + tg * 2 + 8]);
                al[mt][0] = *reinterpret_cast<uint32_t*>(&Alo[(rm + g) * LD + k0 + tg * 2]);
                al[mt][1] = *reinterpret_cast<uint32_t*>(&Alo[(rm + g + 8) * LD + k0 + tg * 2]);
                al[mt][2] = *reinterpret_cast<uint32_t*>(&Alo[(rm + g) * LD + k0 + tg * 2 + 8]);
                al[mt][3] = *reinterpret_cast<uint32_t*>(&Alo[(rm + g + 8) * LD + k0 + tg * 2 + 8]);
            }
#pragma unroll
            for (int nt = 0; nt < NT; nt++) {
                int cn = nw * (NT * 8) + nt * 8 + g;
                uint32_t bh0 = *reinterpret_cast<uint32_t*>(&Bhi[cn * LD + k0 + tg * 2]);
                uint32_t bh1 = *reinterpret_cast<uint32_t*>(&Bhi[cn * LD + k0 + tg * 2 + 8]);
                uint32_t bl0 = *reinterpret_cast<uint32_t*>(&Blo[cn * LD + k0 + tg * 2]);
                uint32_t bl1 = *reinterpret_cast<uint32_t*>(&Blo[cn * LD + k0 + tg * 2 + 8]);
#pragma unroll
                for (int mt = 0; mt < 2; mt++) {
                    mma16816(acc[mt][nt], ah[mt], bh0, bh1);
                    mma16816(acc[mt][nt], ah[mt], bl0, bl1);
                    mma16816(acc[mt][nt], al[mt], bh0, bh1);
                }
            }
        }
    }
    __syncthreads();

    // ---- epilogue: bias + (write | pool) + per-channel stats ----
    float* ss = reinterpret_cast<float*>(sh);
    float* sq = ss + COLS;
    for (int c = tid; c < COLS; c += 512) { ss[c] = 0.f; sq[c] = 0.f; }
    __syncthreads();

    int rb32 = (int)(row0 >> 5) + mw;
#pragma unroll
    for (int nt = 0; nt < NT; nt++) {
        int lc = nw * (NT * 8) + nt * 8 + tg * 2;
        float b0 = bias[n0 + lc], b1 = bias[n0 + lc + 1];
        float s0 = 0.f, q0 = 0.f, s1 = 0.f, q1 = 0.f;
        float mx0 = -3.4e38f, mn0 = 3.4e38f, mx1 = -3.4e38f, mn1 = 3.4e38f;
#pragma unroll
        for (int mt = 0; mt < 2; mt++) {
            float v00 = acc[mt][nt][0] + b0, v01 = acc[mt][nt][1] + b1;
            float v10 = acc[mt][nt][2] + b0, v11 = acc[mt][nt][3] + b1;
            if (!POOL) {
                size_t r0 = row0 + mw * 32 + mt * 16 + g;
                *reinterpret_cast<float2*>(&out[r0 * COUT + n0 + lc]) = make_float2(v00, v01);
                *reinterpret_cast<float2*>(&out[(r0 + 8) * COUT + n0 + lc]) = make_float2(v10, v11);
            }
            s0 += v00 + v10; q0 += v00 * v00 + v10 * v10;
            s1 += v01 + v11; q1 += v01 * v01 + v11 * v11;
            mx0 = fmaxf(mx0, fmaxf(v00, v10)); mn0 = fminf(mn0, fminf(v00, v10));
            mx1 = fmaxf(mx1, fmaxf(v01, v11)); mn1 = fminf(mn1, fminf(v01, v11));
        }
#pragma unroll
        for (int o = 4; o < 32; o <<= 1) {
            s0 += __shfl_xor_sync(0xffffffffu, s0, o);
            q0 += __shfl_xor_sync(0xffffffffu, q0, o);
            s1 += __shfl_xor_sync(0xffffffffu, s1, o);
            q1 += __shfl_xor_sync(0xffffffffu, q1, o);
            if (POOL) {
                mx0 = fmaxf(mx0, __shfl_xor_sync(0xffffffffu, mx0, o));
                mn0 = fminf(mn0, __shfl_xor_sync(0xffffffffu, mn0, o));
                mx1 = fmaxf(mx1, __shfl_xor_sync(0xffffffffu, mx1, o));
                mn1 = fminf(mn1, __shfl_xor_sync(0xffffffffu, mn1, o));
            }
        }
        if (g == 0) {
            atomicAdd(&ss[lc], s0);
            atomicAdd(&sq[lc], q0);
            atomicAdd(&ss[lc + 1], s1);
            atomicAdd(&sq[lc + 1], q1);
            if (POOL) {
                size_t pb = (size_t)rb32 * COUT + n0 + lc;
                g_pmax[pb] = mx0; g_pmin[pb] = mn0;
                g_pmax[pb + 1] = mx1; g_pmin[pb + 1] = mn1;
            }
        }
    }
    __syncthreads();
    for (int c = tid; c < COLS; c += 512) {
        atomicAdd(&g_sum[n0 + c], (double)ss[c]);
        atomicAdd(&g_sumsq[n0 + c], (double)sq[c]);
    }
}

// ---------------- pooled-raw -> BN + relu -> outputs ----------------
__global__ void pool_bn_out(int S, int KG, int C, float* __restrict__ out,
                            __nv_bfloat16* __restrict__ ohi, __nv_bfloat16* __restrict__ olo,
                            int ostride, float* __restrict__ zp, int zn) {
    if (zp && blockIdx.x == 0 && threadIdx.x < zn) zp[threadIdx.x] = 0.f;
    int total = BB * S * C;
    int stride = gridDim.x * blockDim.x;
    for (int i = blockIdx.x * blockDim.x + threadIdx.x; i < total; i += stride) {
        int c = i % C;
        int s = (i / C) % S;
        int b = i / (C * S);
        size_t base = ((size_t)(b * S + s) * KG) * C + c;
        float mx = g_pmax[base], mn = g_pmin[base];
        for (int q = 1; q < KG; q++) {
            mx = fmaxf(mx, g_pmax[base + (size_t)q * C]);
            mn = fminf(mn, g_pmin[base + (size_t)q * C]);
        }
        float sc = g_scale[c];
        float raw = (sc >= 0.f) ? mx : mn;
        float r = fmaxf(raw * sc + g_shift[c], 0.f);
        out[(size_t)b * C * S + (size_t)c * S + s] = r;
        if (ohi) {
            __nv_bfloat16 h = __float2bfloat16_rn(r);
            size_t o = (size_t)(b * S + s) * ostride + c + 3;
            ohi[o] = h;
            olo[o] = __float2bfloat16_rn(r - __bfloat162float(h));
        }
    }
}

// ---------------- BN finalize (also re-zeros accumulators for next use) ----------------
__global__ void bn_finalize_kernel(int C, double invcnt, const float* __restrict__ gamma,
                                   const float* __restrict__ beta) {
    int c = threadIdx.x;
    if (c < C) {
        double m = g_sum[c] * invcnt;
        double var = g_sumsq[c] * invcnt - m * m;
        float s = gamma[c] * rsqrtf((float)var + 1e-5f);
        g_scale[c] = s;
        g_shift[c] = beta[c] - (float)m * s;
    }
    g_sum[c] = 0.0;
    g_sumsq[c] = 0.0;
}

// ---------------- orchestration ----------------
extern "C" void kernel_launch(void* const* d_in, const int* in_sizes, int n_in,
                              void* d_out, int out_size) {
    (void)in_sizes; (void)n_in; (void)out_size;
    const float* l0_xyz = (const float*)d_in[0];
    const float* l0_pts = (const float*)d_in[1];
    float* out = (float*)d_out;

    float* o_l1xyz = out;                 // 16*3*256   = 12288
    float* o_l1pts = out + 12288;         // 16*128*256 = 524288
    float* o_l2xyz = out + 536576;        // 16*3*128   = 6144
    float* o_l2pts = out + 542720;        // 16*256*128 = 524288
    float* o_l3xyz = out + 1067008;       // 16*3*1     = 48
    float* o_x     = out + 1067056;       // 16*512     = 8192

    float *bufB, *nxyz;
    int *gi;
    __nv_bfloat16 *whi, *wlo, *l1hi, *l1lo, *l2hi, *l2lo;
    cudaGetSymbolAddress((void**)&bufB, g_bufB);
    cudaGetSymbolAddress((void**)&nxyz, g_newxyz);
    cudaGetSymbolAddress((void**)&gi, g_gi);
    cudaGetSymbolAddress((void**)&whi, g_whi);
    cudaGetSymbolAddress((void**)&wlo, g_wlo);
    cudaGetSymbolAddress((void**)&l1hi, g_l1hi);
    cudaGetSymbolAddress((void**)&l1lo, g_l1lo);
    cudaGetSymbolAddress((void**)&l2hi, g_l2hi);
    cudaGetSymbolAddress((void**)&l2lo, g_l2lo);

    constexpr int FPS1_SM = 3 * 4096 * 4 + 256;
    constexpr int FPS2_SM = 3 * 256 * 4 + 256;
    cudaFuncSetAttribute((const void*)fps_fast<8>, cudaFuncAttributeMaxDynamicSharedMemorySize, FPS1_SM);
    constexpr int HSM128 = (2 * 128 * 72 + 2 * 128 * 72) * 2;            // 73728
    constexpr int HSM256 = (2 * 128 * 72 + 2 * 256 * 72) * 2;            // 110592
    constexpr int HSM1G  = HSM128 + (128 * 8 + 384 + 64) * 4;            // 79616
    cudaFuncSetAttribute((const void*)hm_gemm<64, 128, 128, 1, true, true>,
                         cudaFuncAttributeMaxDynamicSharedMemorySize, HSM1G);
    cudaFuncSetAttribute((const void*)hm_gemm<131, 128, 128, 2, false, false>,
                         cudaFuncAttributeMaxDynamicSharedMemorySize, HSM128);
    cudaFuncSetAttribute((const void*)hm_gemm<128, 256, 256, 0, true, true>,
                         cudaFuncAttributeMaxDynamicSharedMemorySize, HSM256);
    cudaFuncSetAttribute((const void*)hm_gemm<259, 256, 256, 3, false, false>,
                         cudaFuncAttributeMaxDynamicSharedMemorySize, HSM256);
    cudaFuncSetAttribute((const void*)hm_gemm<256, 512, 256, 0, true, true>,
                         cudaFuncAttributeMaxDynamicSharedMemorySize, HSM256);

    // ---- all weight prep up front (1 launch) ----
    prep_all<<<1088, 256>>>((const float*)d_in[6], (const float*)d_in[10],
                            (const float*)d_in[14], (const float*)d_in[18],
                            (const float*)d_in[22]);

    // ================= SA1 : N=4096 -> S=256, K=32 =================
    fps_fast<8><<<16, 512, FPS1_SM>>>(l0_xyz, 4096, 256, nxyz, o_l1xyz);
    ballquery_kernel<<<(16 * 256) / 8, 256>>>(l0_xyz, nxyz, 4096, 256, 32, 0.04f, gi,
                                              nullptr, nullptr, nullptr);
    // layer-1 BN stats from input moments (no 6->64 materialization)
    gather_stats1<<<128, 256>>>(l0_xyz, l0_pts, gi, nxyz);
    bn_finalize6<<<1, 64>>>((const float*)d_in[2], (const float*)d_in[3],
                            (const float*)d_in[4], (const float*)d_in[5]);

    // fused gather + 6->64 + BN + 64->128 (HMMA) + pooled epilogue
    hm_gemm<64, 128, 128, 1, true, true><<<1024, 512, HSM1G>>>(
        (const float*)d_in[2], whi + WOFF_L1B, wlo + WOFF_L1B, (const float*)d_in[7],
        nullptr, gi, l0_xyz, nxyz, l0_pts, (const float*)d_in[3]);
    bn_finalize_kernel<<<1, 512>>>(128, 1.0 / 131072.0, (const float*)d_in[8], (const float*)d_in[9]);
    pool_bn_out<<<2048, 256>>>(256, 1, 128, o_l1pts, l1hi, l1lo, 192, nullptr, 0);

    // ================= SA2 : N=256 -> S=128, K=64 =================
    fps_fast<1><<<16, 256, FPS2_SM>>>(o_l1xyz, 256, 128, nxyz, o_l2xyz);
    ballquery_kernel<<<(16 * 128) / 8, 256>>>(o_l1xyz, nxyz, 256, 128, 64, 0.0625f, gi,
                                              o_l2xyz, l2hi, l2lo);

    hm_gemm<131, 128, 128, 2, false, false><<<1024, 512, HSM128>>>(
        nullptr, whi + WOFF_L2A, wlo + WOFF_L2A, (const float*)d_in[11],
        bufB, gi, o_l1xyz, nxyz, nullptr, nullptr);
    bn_finalize_kernel<<<1, 512>>>(128, 1.0 / 131072.0, (const float*)d_in[12], (const float*)d_in[13]);

    hm_gemm<128, 256, 256, 0, true, true><<<1024, 512, HSM256>>>(
        bufB, whi + WOFF_L2B, wlo + WOFF_L2B, (const float*)d_in[15],
        nullptr, nullptr, nullptr, nullptr, nullptr, nullptr);
    bn_finalize_kernel<<<1, 512>>>(256, 1.0 / 131072.0, (const float*)d_in[16], (const float*)d_in[17]);
    pool_bn_out<<<2048, 256>>>(128, 2, 256, o_l2pts, l2hi, l2lo, 320, nullptr, 0);

    // ================= SA3 : group_all, rows = 16*128 = 2048 =================
    hm_gemm<259, 256, 256, 3, false, false><<<16, 512, HSM256>>>(
        nullptr, whi + WOFF_L3A, wlo + WOFF_L3A, (const float*)d_in[19],
        bufB, nullptr, nullptr, nullptr, nullptr, nullptr);
    bn_finalize_kernel<<<1, 512>>>(256, 1.0 / 2048.0, (const float*)d_in[20], (const float*)d_in[21]);

    hm_gemm<256, 512, 256, 0, true, true><<<dim3(16, 2), 512, HSM256>>>(
        bufB, whi + WOFF_L3B, wlo + WOFF_L3B, (const float*)d_in[23],
        nullptr, nullptr, nullptr, nullptr, nullptr, nullptr);
    bn_finalize_kernel<<<1, 512>>>(512, 1.0 / 2048.0, (const float*)d_in[24], (const float*)d_in[25]);

    pool_bn_out<<<64, 256>>>(1, 4, 512, o_x, nullptr, nullptr, 0, o_l3xyz, 48);
}